// round 10
// baseline (speedup 1.0000x reference)
#include <cuda_runtime.h>
#include <cuda_bf16.h>
#include <mma.h>
#include <math.h>
#include <stdint.h>

using namespace nvcuda;

// Problem constants
#define T_  16
#define DB_ 512
#define H_  512
#define U_  1024
#define MC_ 8
#define MT_ 4
#define L_  64
#define K_  64
#define Hh_ 256
#define G3_ (3*Hh_)     // 768
#define TU_ (T_*U_)     // 16384
#define TDB_ (T_*DB_)   // 8192
#define OUTC_ (U_+K_)   // 1088

// ---------------- scratch (device globals; no allocs allowed) ----------------
__device__ float d_Pf[TDB_*G3_];      // feat @ Wih_f^T   (8192 x 768)
__device__ float d_Pb[TDB_*G3_];      // feat @ Wih_b^T
__device__ float d_g_f2[TU_*G3_];     // col-mean of Pf  (gi for f2)
__device__ float d_g_b2[TU_*G3_];     // tab-mean of Pb  (gi for b2)
__device__ float d_f1[TU_*Hh_];
__device__ float d_b1[TU_*Hh_];
__device__ float d_gh_f[TU_*G3_];     // f1@Whh_f^T (raw, bhh added in gru_second)
__device__ float d_gh_b[TU_*G3_];
__device__ float d_db[TU_*H_];        // db_emb
__device__ float d_logits[T_*U_];
__device__ float d_wsm[T_*U_];
__device__ float d_attnp[T_*8*H_];    // attention partials (8 U-chunks)
__device__ float d_attnv[T_*H_];
__device__ float d_ffin[T_*L_*H_];
__device__ float d_ff[T_*L_*H_];
__device__ float d_probs[T_*L_*OUTC_];

// split-bf16 operand buffers ([hi|lo|hi] A-side, [hi|hi|lo] B-side)
__device__ __nv_bfloat16 d_featS[TDB_*3*H_];   // 8192 x 1536
__device__ __nv_bfloat16 d_WihfS[G3_*3*H_];
__device__ __nv_bfloat16 d_WihbS[G3_*3*H_];
__device__ __nv_bfloat16 d_WhhfS[G3_*3*Hh_];
__device__ __nv_bfloat16 d_WhhbS[G3_*3*Hh_];
__device__ __nv_bfloat16 d_f1S[TU_*3*Hh_];
__device__ __nv_bfloat16 d_b1S[TU_*3*Hh_];

// ================= cp.async helpers =================
__device__ __forceinline__ void cp_async16(void* smem_ptr, const void* gptr) {
    uint32_t s = (uint32_t)__cvta_generic_to_shared(smem_ptr);
    asm volatile("cp.async.cg.shared.global [%0], [%1], 16;" :: "r"(s), "l"(gptr));
}
__device__ __forceinline__ void cp_commit() { asm volatile("cp.async.commit_group;" ::: "memory"); }
__device__ __forceinline__ void cp_wait1()  { asm volatile("cp.async.wait_group 1;" ::: "memory"); }
__device__ __forceinline__ void cp_wait0()  { asm volatile("cp.async.wait_group 0;" ::: "memory"); }

// ================= WMMA bf16 GEMM, 2-stage cp.async pipeline =================
// C(MxN) = A(M x K3) @ B(N x K3)^T ; bf16 operands, fp32 accumulate.
// BM=128, BN=128, BK=32; 256 threads = 8 warps (2x4), warp tile 64x32.
#define WBK 32
#define WPAD 40   // smem leading dim (elements): 80B rows (16B-aligned, %8==0)

__global__ __launch_bounds__(256)
void gemm_wmma(const __nv_bfloat16* __restrict__ A, const __nv_bfloat16* __restrict__ B,
               float* __restrict__ C, int M, int N, int K3, int ldc)
{
    __shared__ __nv_bfloat16 As[2][128 * WPAD];
    __shared__ __nv_bfloat16 Bs[2][128 * WPAD];

    int tid  = threadIdx.x;
    int warp = tid >> 5;
    int wm = warp >> 2;          // 0..1 : 64-row slab
    int wn = warp & 3;           // 0..3 : 32-col slab
    int bm = blockIdx.y * 128;
    int bn = blockIdx.x * 128;

    wmma::fragment<wmma::accumulator, 16, 16, 16, float> acc[4][2];
    #pragma unroll
    for (int i = 0; i < 4; i++)
        #pragma unroll
        for (int j = 0; j < 2; j++) wmma::fill_fragment(acc[i][j], 0.0f);

    const int nch = K3 / WBK;

    // stage loader: 128 rows x 32 cols per operand, 16B per cp.async
    auto load_stage = [&](int s, int k0) {
        #pragma unroll
        for (int i = tid; i < 512; i += 256) {
            int r = i >> 2, c = i & 3;
            cp_async16(&As[s][r * WPAD + c * 8], A + (size_t)(bm + r) * K3 + k0 + c * 8);
        }
        #pragma unroll
        for (int i = tid; i < 512; i += 256) {
            int r = i >> 2, c = i & 3;
            cp_async16(&Bs[s][r * WPAD + c * 8], B + (size_t)(bn + r) * K3 + k0 + c * 8);
        }
        cp_commit();
    };

    load_stage(0, 0);

    for (int c = 0; c < nch; c++) {
        if (c + 1 < nch) { load_stage((c + 1) & 1, (c + 1) * WBK); cp_wait1(); }
        else             { cp_wait0(); }
        __syncthreads();

        int s = c & 1;
        #pragma unroll
        for (int kk = 0; kk < WBK; kk += 16) {
            wmma::fragment<wmma::matrix_a, 16, 16, 16, __nv_bfloat16, wmma::row_major> fa[4];
            wmma::fragment<wmma::matrix_b, 16, 16, 16, __nv_bfloat16, wmma::col_major> fb[2];
            #pragma unroll
            for (int i = 0; i < 4; i++)
                wmma::load_matrix_sync(fa[i], &As[s][(wm * 64 + i * 16) * WPAD + kk], WPAD);
            #pragma unroll
            for (int j = 0; j < 2; j++)
                wmma::load_matrix_sync(fb[j], &Bs[s][(wn * 32 + j * 16) * WPAD + kk], WPAD);
            #pragma unroll
            for (int i = 0; i < 4; i++)
                #pragma unroll
                for (int j = 0; j < 2; j++)
                    wmma::mma_sync(acc[i][j], fa[i], fb[j], acc[i][j]);
        }
        __syncthreads();
    }

    #pragma unroll
    for (int i = 0; i < 4; i++)
        #pragma unroll
        for (int j = 0; j < 2; j++) {
            int m0 = bm + wm * 64 + i * 16;
            int n0 = bn + wn * 32 + j * 16;
            wmma::store_matrix_sync(C + (size_t)m0 * ldc + n0, acc[i][j], ldc, wmma::mem_row_major);
        }
}

// ================= split-bf16 conversion =================
// orderB=0: [hi|lo|hi] (A-side) ; orderB=1: [hi|hi|lo] (B-side)
__global__ void split_bf16_kernel(const float* __restrict__ X, __nv_bfloat16* __restrict__ Y,
                                  int n, int Kd, int orderB)
{
    int idx = blockIdx.x * blockDim.x + threadIdx.x;
    if (idx >= n) return;
    float x = X[idx];
    __nv_bfloat16 h = __float2bfloat16(x);
    __nv_bfloat16 l = __float2bfloat16(x - __bfloat162float(h));
    int r = idx / Kd, k = idx - r * Kd;
    size_t bse = (size_t)r * 3 * Kd;
    if (orderB) { Y[bse + k] = h; Y[bse + Kd + k] = h; Y[bse + 2*Kd + k] = l; }
    else        { Y[bse + k] = h; Y[bse + Kd + k] = l; Y[bse + 2*Kd + k] = h; }
}

// ---------------- scalar-FFMA SGEMM (small tail GEMMs) ----------------
template<int BM, int BN, int BK, int TM, int TN>
__global__ void sgemm_nt(const float* __restrict__ A, const float* __restrict__ B,
                         const float* __restrict__ bias, float* __restrict__ C,
                         int M, int N, int K, int lda, int ldb, int ldc,
                         long long sA, long long sB, long long sC, int act)
{
    constexpr int THREADS = (BM/TM) * (BN/TN);
    __shared__ float As[BK][BM];
    __shared__ float Bs[BK][BN];

    A += (size_t)blockIdx.z * sA;
    B += (size_t)blockIdx.z * sB;
    C += (size_t)blockIdx.z * sC;

    int bm = blockIdx.y * BM;
    int bn = blockIdx.x * BN;
    int tid = threadIdx.x;
    int tx = tid % (BN/TN);
    int ty = tid / (BN/TN);

    float acc[TM][TN];
    #pragma unroll
    for (int i = 0; i < TM; i++)
        #pragma unroll
        for (int j = 0; j < TN; j++) acc[i][j] = 0.f;

    for (int k0 = 0; k0 < K; k0 += BK) {
        #pragma unroll
        for (int i = tid; i < BM*BK/4; i += THREADS) {
            int r = i / (BK/4), c4 = i % (BK/4);
            float4 v = *(const float4*)&A[(size_t)(bm+r)*lda + k0 + c4*4];
            As[c4*4+0][r] = v.x; As[c4*4+1][r] = v.y;
            As[c4*4+2][r] = v.z; As[c4*4+3][r] = v.w;
        }
        #pragma unroll
        for (int i = tid; i < BN*BK/4; i += THREADS) {
            int r = i / (BK/4), c4 = i % (BK/4);
            float4 v = *(const float4*)&B[(size_t)(bn+r)*ldb + k0 + c4*4];
            Bs[c4*4+0][r] = v.x; Bs[c4*4+1][r] = v.y;
            Bs[c4*4+2][r] = v.z; Bs[c4*4+3][r] = v.w;
        }
        __syncthreads();
        #pragma unroll
        for (int kk = 0; kk < BK; kk++) {
            float a[TM], b[TN];
            #pragma unroll
            for (int i = 0; i < TM; i++) a[i] = As[kk][ty*TM + i];
            #pragma unroll
            for (int j = 0; j < TN; j++) b[j] = Bs[kk][tx*TN + j];
            #pragma unroll
            for (int i = 0; i < TM; i++)
                #pragma unroll
                for (int j = 0; j < TN; j++) acc[i][j] += a[i]*b[j];
        }
        __syncthreads();
    }

    #pragma unroll
    for (int i = 0; i < TM; i++) {
        int m = bm + ty*TM + i;
        #pragma unroll
        for (int j = 0; j < TN; j++) {
            int n = bn + tx*TN + j;
            float v = acc[i][j];
            if (bias) v += bias[n];
            if (act == 1) v = tanhf(v);
            C[(size_t)m*ldc + n] = v;
        }
    }
}

// ---------------- GRU math ----------------
__device__ __forceinline__ float sigm(float x) { return 1.f / (1.f + expf(-x)); }

// ============ FUSED: masked-mean gather (projected space) + GRU step 1 ============
// Block = (u, t), 256 threads; thread j owns gate triple (j, j+256, j+512).
// Accumulates 4 means in registers, writes only g_f2/g_b2 (for step 2) and
// f1/b1 (+ split-bf16) — eliminates the g_f1/g_b1 round-trip entirely.
__global__ __launch_bounds__(256)
void gather_gru1_kernel(const int* __restrict__ col_idx, const int* __restrict__ col_mask,
                        const int* __restrict__ tab_idx, const int* __restrict__ tab_mask,
                        const float* __restrict__ bih_f, const float* __restrict__ bhh_f,
                        const float* __restrict__ bih_b, const float* __restrict__ bhh_b)
{
    int u = blockIdx.x, t = blockIdx.y;
    int j = threadIdx.x;
    const float* Pf = d_Pf + (size_t)t * DB_ * G3_;
    const float* Pb = d_Pb + (size_t)t * DB_ * G3_;

    // tab means: gf1 (Pf) , gb2 (Pb)
    float tf_r=0.f, tf_z=0.f, tf_n=0.f, tb_r=0.f, tb_z=0.f, tb_n=0.f, cnt_t=0.f;
    #pragma unroll
    for (int m = 0; m < MT_; m++) {
        if (tab_mask[u*MT_+m]) {
            int id = tab_idx[u*MT_+m];
            const float* pf = Pf + (size_t)id * G3_;
            const float* pb = Pb + (size_t)id * G3_;
            tf_r += pf[j]; tf_z += pf[Hh_+j]; tf_n += pf[2*Hh_+j];
            tb_r += pb[j]; tb_z += pb[Hh_+j]; tb_n += pb[2*Hh_+j];
            cnt_t += 1.f;
        }
    }
    // col means: gf2 (Pf) , gb1 (Pb)
    float cf_r=0.f, cf_z=0.f, cf_n=0.f, cb_r=0.f, cb_z=0.f, cb_n=0.f, cnt_c=0.f;
    #pragma unroll
    for (int m = 0; m < MC_; m++) {
        if (col_mask[u*MC_+m]) {
            int id = col_idx[u*MC_+m];
            const float* pf = Pf + (size_t)id * G3_;
            const float* pb = Pb + (size_t)id * G3_;
            cf_r += pf[j]; cf_z += pf[Hh_+j]; cf_n += pf[2*Hh_+j];
            cb_r += pb[j]; cb_z += pb[Hh_+j]; cb_n += pb[2*Hh_+j];
            cnt_c += 1.f;
        }
    }
    float it = 1.f / fmaxf(cnt_t, 1.f);
    float ic = 1.f / fmaxf(cnt_c, 1.f);
    size_t row = (size_t)t * U_ + u;

    // store gi's needed by GRU step 2
    d_g_f2[row*G3_ + j]        = cf_r * ic;
    d_g_f2[row*G3_ + Hh_ + j]  = cf_z * ic;
    d_g_f2[row*G3_ + 2*Hh_ + j]= cf_n * ic;
    d_g_b2[row*G3_ + j]        = tb_r * it;
    d_g_b2[row*G3_ + Hh_ + j]  = tb_z * it;
    d_g_b2[row*G3_ + 2*Hh_ + j]= tb_n * it;

    // f1 = GRUCell_f(x1 = tab-mean, h = 0)
    {
        float r = sigm(tf_r*it + bih_f[j]       + bhh_f[j]);
        float z = sigm(tf_z*it + bih_f[Hh_+j]   + bhh_f[Hh_+j]);
        float n = tanhf(tf_n*it + bih_f[2*Hh_+j] + r * bhh_f[2*Hh_+j]);
        float v = (1.f - z) * n;
        d_f1[row*Hh_ + j] = v;
        __nv_bfloat16 h = __float2bfloat16(v);
        __nv_bfloat16 l = __float2bfloat16(v - __bfloat162float(h));
        d_f1S[row*G3_ + j] = h; d_f1S[row*G3_ + Hh_ + j] = l; d_f1S[row*G3_ + 2*Hh_ + j] = h;
    }
    // b1 = GRUCell_b(x2 = col-mean, h = 0)
    {
        float r = sigm(cb_r*ic + bih_b[j]       + bhh_b[j]);
        float z = sigm(cb_z*ic + bih_b[Hh_+j]   + bhh_b[Hh_+j]);
        float n = tanhf(cb_n*ic + bih_b[2*Hh_+j] + r * bhh_b[2*Hh_+j]);
        float v = (1.f - z) * n;
        d_b1[row*Hh_ + j] = v;
        __nv_bfloat16 h = __float2bfloat16(v);
        __nv_bfloat16 l = __float2bfloat16(v - __bfloat162float(h));
        d_b1S[row*G3_ + j] = h; d_b1S[row*G3_ + Hh_ + j] = l; d_b1S[row*G3_ + 2*Hh_ + j] = h;
    }
}

// second steps: gh buffers are RAW h@Whh^T -> add bhh here; gi needs +bih.
__global__ void gru_second_kernel(const float* __restrict__ bih_f, const float* __restrict__ bhh_f,
                                  const float* __restrict__ bih_b, const float* __restrict__ bhh_b)
{
    int idx = blockIdx.x * blockDim.x + threadIdx.x;   // TU_*Hh_
    int row = idx >> 8, j = idx & 255;
    {
        const float* gi = d_g_f2 + (size_t)row * G3_;
        const float* gh = d_gh_f + (size_t)row * G3_;
        float h  = d_f1[idx];
        float r = sigm(gi[j]       + bih_f[j]       + gh[j]       + bhh_f[j]);
        float z = sigm(gi[Hh_+j]   + bih_f[Hh_+j]   + gh[Hh_+j]   + bhh_f[Hh_+j]);
        float n = tanhf(gi[2*Hh_+j] + bih_f[2*Hh_+j] + r * (gh[2*Hh_+j] + bhh_f[2*Hh_+j]));
        float f2 = (1.f - z) * n + z * h;
        d_db[(size_t)row*H_ + j] = 0.5f * (h + f2);
    }
    {
        const float* gi = d_g_b2 + (size_t)row * G3_;
        const float* gh = d_gh_b + (size_t)row * G3_;
        float h  = d_b1[idx];
        float r = sigm(gi[j]       + bih_b[j]       + gh[j]       + bhh_b[j]);
        float z = sigm(gi[Hh_+j]   + bih_b[Hh_+j]   + gh[Hh_+j]   + bhh_b[Hh_+j]);
        float n = tanhf(gi[2*Hh_+j] + bih_b[2*Hh_+j] + r * (gh[2*Hh_+j] + bhh_b[2*Hh_+j]));
        float b2 = (1.f - z) * n + z * h;
        d_db[(size_t)row*H_ + Hh_ + j] = 0.5f * (h + b2);
    }
}

// ---------------- attention ----------------
__global__ void logits_kernel(const float* __restrict__ key, const int* __restrict__ attn_mask)
{
    int t = blockIdx.y;
    int warp = threadIdx.x >> 5, lane = threadIdx.x & 31;
    int u = blockIdx.x * 8 + warp;
    const float* kv = key + (size_t)t * H_;
    const float* d  = d_db + ((size_t)t*U_ + u) * H_;
    float acc = 0.f;
    for (int h = lane; h < H_; h += 32) acc += kv[h] * d[h];
    #pragma unroll
    for (int s = 16; s > 0; s >>= 1) acc += __shfl_xor_sync(0xFFFFFFFFu, acc, s);
    if (lane == 0)
        d_logits[t*U_ + u] = attn_mask[t*U_ + u] ? acc : -1e9f;
}

__global__ void softmax_kernel()
{
    int t = blockIdx.x;
    __shared__ float red[256];
    int tid = threadIdx.x;
    float mx = -INFINITY;
    for (int u = tid; u < U_; u += 256) mx = fmaxf(mx, d_logits[t*U_+u]);
    red[tid] = mx; __syncthreads();
    for (int s = 128; s > 0; s >>= 1) { if (tid < s) red[tid] = fmaxf(red[tid], red[tid+s]); __syncthreads(); }
    mx = red[0]; __syncthreads();
    float sum = 0.f;
    for (int u = tid; u < U_; u += 256) sum += expf(d_logits[t*U_+u] - mx);
    red[tid] = sum; __syncthreads();
    for (int s = 128; s > 0; s >>= 1) { if (tid < s) red[tid] += red[tid+s]; __syncthreads(); }
    sum = red[0];
    float inv = 1.f / sum;
    for (int u = tid; u < U_; u += 256) d_wsm[t*U_+u] = expf(d_logits[t*U_+u] - mx) * inv;
}

// attention value: split U into 8 chunks of 128 for parallelism (128 blocks)
__global__ void attn_part_kernel()
{
    int chunk = blockIdx.x, t = blockIdx.y;
    int h = threadIdx.x;                 // 512 threads
    __shared__ float ws[128];
    if (h < 128) ws[h] = d_wsm[t*U_ + chunk*128 + h];
    __syncthreads();
    float acc = 0.f;
    const float* d = d_db + ((size_t)t*U_ + chunk*128) * H_ + h;
    #pragma unroll 4
    for (int u = 0; u < 128; u++) acc += ws[u] * d[(size_t)u*H_];
    d_attnp[((size_t)t*8 + chunk)*H_ + h] = acc;
}

__global__ void attn_reduce_kernel()
{
    int t = blockIdx.x;
    int h = threadIdx.x;                 // 512
    float acc = 0.f;
    #pragma unroll
    for (int c = 0; c < 8; c++) acc += d_attnp[((size_t)t*8 + c)*H_ + h];
    d_attnv[t*H_ + h] = acc;
}

__global__ void add_attn_kernel(const float* __restrict__ final_feature)
{
    int idx = blockIdx.x * blockDim.x + threadIdx.x;   // T_*L_*H_
    int h = idx & (H_-1);
    int t = idx >> 15;
    d_ffin[idx] = final_feature[idx] + d_attnv[t*H_ + h];
}

// ---------------- final log-softmax ----------------
__global__ void logsoftmax_kernel(float* __restrict__ out)
{
    int r = blockIdx.x;
    int tid = threadIdx.x;
    __shared__ float red[256];
    const float* x = d_probs + (size_t)r * OUTC_;
    float mx = -INFINITY;
    for (int c = tid; c < OUTC_; c += 256) mx = fmaxf(mx, x[c]);
    red[tid] = mx; __syncthreads();
    for (int s = 128; s > 0; s >>= 1) { if (tid < s) red[tid] = fmaxf(red[tid], red[tid+s]); __syncthreads(); }
    mx = red[0]; __syncthreads();
    float sum = 0.f;
    for (int c = tid; c < OUTC_; c += 256) sum += expf(x[c] - mx);
    red[tid] = sum; __syncthreads();
    for (int s = 128; s > 0; s >>= 1) { if (tid < s) red[tid] += red[tid+s]; __syncthreads(); }
    float lse = mx + logf(red[0]);
    for (int c = tid; c < OUTC_; c += 256) out[(size_t)r*OUTC_ + c] = x[c] - lse;
}

// ---------------- host launcher ----------------
#define SYM(p, t, s) do { void* _t; cudaGetSymbolAddress(&_t, s); (p) = (t*)_t; } while (0)

extern "C" void kernel_launch(void* const* d_in, const int* in_sizes, int n_in,
                              void* d_out, int out_size)
{
    const float* feat          = (const float*)d_in[0];
    const float* key           = (const float*)d_in[1];
    const float* final_feature = (const float*)d_in[2];
    const float* Wih_f         = (const float*)d_in[3];
    const float* Whh_f         = (const float*)d_in[4];
    const float* bih_f         = (const float*)d_in[5];
    const float* bhh_f         = (const float*)d_in[6];
    const float* Wih_b         = (const float*)d_in[7];
    const float* Whh_b         = (const float*)d_in[8];
    const float* bih_b         = (const float*)d_in[9];
    const float* bhh_b         = (const float*)d_in[10];
    const float* Wb            = (const float*)d_in[11];
    const float* bb            = (const float*)d_in[12];
    const float* Kemb          = (const float*)d_in[13];
    const int*   col_idx       = (const int*)d_in[14];
    const int*   col_mask      = (const int*)d_in[15];
    const int*   tab_idx       = (const int*)d_in[16];
    const int*   tab_mask      = (const int*)d_in[17];
    const int*   attn_mask     = (const int*)d_in[18];
    float* out = (float*)d_out;

    float *Pf, *Pb, *gh_f, *gh_b, *db, *ffin, *ff, *probs;
    __nv_bfloat16 *featS, *WihfS, *WihbS, *WhhfS, *WhhbS, *f1S, *b1S;
    SYM(Pf, float, d_Pf);   SYM(Pb, float, d_Pb);
    SYM(gh_f, float, d_gh_f); SYM(gh_b, float, d_gh_b);
    SYM(db, float, d_db);   SYM(ffin, float, d_ffin); SYM(ff, float, d_ff); SYM(probs, float, d_probs);
    SYM(featS, __nv_bfloat16, d_featS);
    SYM(WihfS, __nv_bfloat16, d_WihfS); SYM(WihbS, __nv_bfloat16, d_WihbS);
    SYM(WhhfS, __nv_bfloat16, d_WhhfS); SYM(WhhbS, __nv_bfloat16, d_WhhbS);
    SYM(f1S, __nv_bfloat16, d_f1S);     SYM(b1S, __nv_bfloat16, d_b1S);

    // 0) split-bf16 conversions
    split_bf16_kernel<<<(TDB_*H_+255)/256, 256>>>(feat,  featS, TDB_*H_, H_, 0);
    split_bf16_kernel<<<(G3_*H_+255)/256, 256>>>(Wih_f, WihfS, G3_*H_, H_, 1);
    split_bf16_kernel<<<(G3_*H_+255)/256, 256>>>(Wih_b, WihbS, G3_*H_, H_, 1);
    split_bf16_kernel<<<(G3_*Hh_+255)/256, 256>>>(Whh_f, WhhfS, G3_*Hh_, Hh_, 1);
    split_bf16_kernel<<<(G3_*Hh_+255)/256, 256>>>(Whh_b, WhhbS, G3_*Hh_, Hh_, 1);

    // 1) projection GEMMs (HMMA, pipelined): P = feat @ Wih^T  (8192 x 768, K'=1536)
    {
        dim3 grid(G3_/128, TDB_/128);
        gemm_wmma<<<grid, 256>>>(featS, WihfS, Pf, TDB_, G3_, 3*H_, G3_);
        gemm_wmma<<<grid, 256>>>(featS, WihbS, Pb, TDB_, G3_, 3*H_, G3_);
    }

    // 2+3) fused masked-mean gather + GRU step 1
    gather_gru1_kernel<<<dim3(U_, T_), 256>>>(col_idx, col_mask, tab_idx, tab_mask,
                                              bih_f, bhh_f, bih_b, bhh_b);

    // 4) hidden-projection GEMMs (HMMA): (16384 x 768, K'=768) — raw, bhh added later
    {
        dim3 grid(G3_/128, TU_/128);
        gemm_wmma<<<grid, 256>>>(f1S, WhhfS, gh_f, TU_, G3_, 3*Hh_, G3_);
        gemm_wmma<<<grid, 256>>>(b1S, WhhbS, gh_b, TU_, G3_, 3*Hh_, G3_);
    }

    // 5) second GRU steps + db_emb
    gru_second_kernel<<<TU_*Hh_/256, 256>>>(bih_f, bhh_f, bih_b, bhh_b);

    // 6) attention
    logits_kernel<<<dim3(U_/8, T_), 256>>>(key, attn_mask);
    softmax_kernel<<<T_, 256>>>();
    attn_part_kernel<<<dim3(8, T_), 512>>>();
    attn_reduce_kernel<<<T_, 512>>>();

    // 7) feature + attn, then ff = tanh(ffin @ Wb^T + bb)
    add_attn_kernel<<<T_*L_*H_/256, 256>>>(final_feature);
    {
        dim3 grid(H_/128, T_*L_/128, 1);
        sgemm_nt<128,128,16,8,8><<<grid, 256>>>(ffin, Wb, bb, ff, T_*L_, H_, H_, H_, H_, H_, 0,0,0, 1);
    }

    // 8) db_prob: per-t (64 x 1024) = ff[t] (64x512) @ db_emb[t] (1024x512)^T
    {
        dim3 grid(U_/128, L_/64, T_);
        sgemm_nt<64,128,16,4,8><<<grid, 256>>>(ff, db, nullptr, probs,
            L_, U_, H_, H_, H_, OUTC_,
            (long long)L_*H_, (long long)U_*H_, (long long)L_*OUTC_, 0);
    }
    // 9) kw_prob: (1024 x 64) = ff @ Kemb^T, at column offset U_
    {
        dim3 grid(K_/64, T_*L_/64, 1);
        sgemm_nt<64,64,16,4,4><<<grid, 256>>>(ff, Kemb, nullptr, probs + U_,
            T_*L_, K_, H_, H_, H_, OUTC_, 0,0,0, 0);
    }

    // 10) log-softmax over last dim (1088) -> output
    logsoftmax_kernel<<<T_*L_, 256>>>(out);
}

// round 11
// speedup vs baseline: 1.2299x; 1.2299x over previous
#include <cuda_runtime.h>
#include <cuda_bf16.h>
#include <mma.h>
#include <math.h>
#include <stdint.h>

using namespace nvcuda;

// Problem constants
#define T_  16
#define DB_ 512
#define H_  512
#define U_  1024
#define MC_ 8
#define MT_ 4
#define L_  64
#define K_  64
#define Hh_ 256
#define G3_ (3*Hh_)     // 768
#define TU_ (T_*U_)     // 16384
#define TDB_ (T_*DB_)   // 8192
#define OUTC_ (U_+K_)   // 1088

// ---------------- scratch (device globals; no allocs allowed) ----------------
__device__ float d_Pf[TDB_*G3_];      // feat @ Wih_f^T   (8192 x 768)
__device__ float d_Pb[TDB_*G3_];      // feat @ Wih_b^T
__device__ float d_g_f1[TU_*G3_];
__device__ float d_g_b2[TU_*G3_];
__device__ float d_g_f2[TU_*G3_];
__device__ float d_g_b1[TU_*G3_];
__device__ float d_f1[TU_*Hh_];
__device__ float d_b1[TU_*Hh_];
__device__ float d_gh_f[TU_*G3_];     // f1@Whh_f^T (raw, bhh added in gru_second)
__device__ float d_gh_b[TU_*G3_];
__device__ float d_db[TU_*H_];        // db_emb
__device__ float d_logits[T_*U_];
__device__ float d_wsm[T_*U_];
__device__ float d_attnp[T_*8*H_];    // attention partials (8 U-chunks)
__device__ float d_attnv[T_*H_];
__device__ float d_ffin[T_*L_*H_];
__device__ float d_ff[T_*L_*H_];
__device__ float d_probs[T_*L_*OUTC_];

// split-bf16 operand buffers ([hi|lo|hi] A-side, [hi|hi|lo] B-side)
__device__ __nv_bfloat16 d_featS[TDB_*3*H_];   // 8192 x 1536
__device__ __nv_bfloat16 d_WihfS[G3_*3*H_];
__device__ __nv_bfloat16 d_WihbS[G3_*3*H_];
__device__ __nv_bfloat16 d_WhhfS[G3_*3*Hh_];
__device__ __nv_bfloat16 d_WhhbS[G3_*3*Hh_];
__device__ __nv_bfloat16 d_f1S[TU_*3*Hh_];
__device__ __nv_bfloat16 d_b1S[TU_*3*Hh_];

// ================= WMMA bf16 GEMM (R7 version — known 969us config) =================
// C(MxN) = A(M x K3) @ B(N x K3)^T ; bf16 operands, fp32 accumulate.
// Tile: BM=128, BN=128, BK=32; 256 threads = 8 warps (2x4), warp tile 64x32.
#define WBK 32
#define WPAD 48   // smem leading dim (elements): 96B rows (32B-aligned, %8==0)

__global__ __launch_bounds__(256)
void gemm_wmma(const __nv_bfloat16* __restrict__ A, const __nv_bfloat16* __restrict__ B,
               float* __restrict__ C, int M, int N, int K3, int ldc)
{
    __shared__ __nv_bfloat16 As[128 * WPAD];
    __shared__ __nv_bfloat16 Bs[128 * WPAD];

    int tid  = threadIdx.x;
    int warp = tid >> 5;
    int wm = warp >> 2;          // 0..1 : 64-row slab
    int wn = warp & 3;           // 0..3 : 32-col slab
    int bm = blockIdx.y * 128;
    int bn = blockIdx.x * 128;

    wmma::fragment<wmma::accumulator, 16, 16, 16, float> acc[4][2];
    #pragma unroll
    for (int i = 0; i < 4; i++)
        #pragma unroll
        for (int j = 0; j < 2; j++) wmma::fill_fragment(acc[i][j], 0.0f);

    for (int k0 = 0; k0 < K3; k0 += WBK) {
        #pragma unroll
        for (int i = tid; i < 128 * (WBK/8); i += 256) {
            int r = i >> 2, c = i & 3;
            *(uint4*)&As[r * WPAD + c * 8] = *(const uint4*)(A + (size_t)(bm + r) * K3 + k0 + c * 8);
        }
        #pragma unroll
        for (int i = tid; i < 128 * (WBK/8); i += 256) {
            int r = i >> 2, c = i & 3;
            *(uint4*)&Bs[r * WPAD + c * 8] = *(const uint4*)(B + (size_t)(bn + r) * K3 + k0 + c * 8);
        }
        __syncthreads();

        #pragma unroll
        for (int kk = 0; kk < WBK; kk += 16) {
            wmma::fragment<wmma::matrix_a, 16, 16, 16, __nv_bfloat16, wmma::row_major> fa[4];
            wmma::fragment<wmma::matrix_b, 16, 16, 16, __nv_bfloat16, wmma::col_major> fb[2];
            #pragma unroll
            for (int i = 0; i < 4; i++)
                wmma::load_matrix_sync(fa[i], &As[(wm * 64 + i * 16) * WPAD + kk], WPAD);
            #pragma unroll
            for (int j = 0; j < 2; j++)
                wmma::load_matrix_sync(fb[j], &Bs[(wn * 32 + j * 16) * WPAD + kk], WPAD);
            #pragma unroll
            for (int i = 0; i < 4; i++)
                #pragma unroll
                for (int j = 0; j < 2; j++)
                    wmma::mma_sync(acc[i][j], fa[i], fb[j], acc[i][j]);
        }
        __syncthreads();
    }

    #pragma unroll
    for (int i = 0; i < 4; i++)
        #pragma unroll
        for (int j = 0; j < 2; j++) {
            int m0 = bm + wm * 64 + i * 16;
            int n0 = bn + wn * 32 + j * 16;
            wmma::store_matrix_sync(C + (size_t)m0 * ldc + n0, acc[i][j], ldc, wmma::mem_row_major);
        }
}

// ================= split-bf16 conversion =================
// orderB=0: [hi|lo|hi] (A-side) ; orderB=1: [hi|hi|lo] (B-side)
__global__ void split_bf16_kernel(const float* __restrict__ X, __nv_bfloat16* __restrict__ Y,
                                  int n, int Kd, int orderB)
{
    int idx = blockIdx.x * blockDim.x + threadIdx.x;
    if (idx >= n) return;
    float x = X[idx];
    __nv_bfloat16 h = __float2bfloat16(x);
    __nv_bfloat16 l = __float2bfloat16(x - __bfloat162float(h));
    int r = idx / Kd, k = idx - r * Kd;
    size_t bse = (size_t)r * 3 * Kd;
    if (orderB) { Y[bse + k] = h; Y[bse + Kd + k] = h; Y[bse + 2*Kd + k] = l; }
    else        { Y[bse + k] = h; Y[bse + Kd + k] = l; Y[bse + 2*Kd + k] = h; }
}

// ---------------- scalar-FFMA SGEMM (small tail GEMMs) ----------------
template<int BM, int BN, int BK, int TM, int TN>
__global__ void sgemm_nt(const float* __restrict__ A, const float* __restrict__ B,
                         const float* __restrict__ bias, float* __restrict__ C,
                         int M, int N, int K, int lda, int ldb, int ldc,
                         long long sA, long long sB, long long sC, int act)
{
    constexpr int THREADS = (BM/TM) * (BN/TN);
    __shared__ float As[BK][BM];
    __shared__ float Bs[BK][BN];

    A += (size_t)blockIdx.z * sA;
    B += (size_t)blockIdx.z * sB;
    C += (size_t)blockIdx.z * sC;

    int bm = blockIdx.y * BM;
    int bn = blockIdx.x * BN;
    int tid = threadIdx.x;
    int tx = tid % (BN/TN);
    int ty = tid / (BN/TN);

    float acc[TM][TN];
    #pragma unroll
    for (int i = 0; i < TM; i++)
        #pragma unroll
        for (int j = 0; j < TN; j++) acc[i][j] = 0.f;

    for (int k0 = 0; k0 < K; k0 += BK) {
        #pragma unroll
        for (int i = tid; i < BM*BK/4; i += THREADS) {
            int r = i / (BK/4), c4 = i % (BK/4);
            float4 v = *(const float4*)&A[(size_t)(bm+r)*lda + k0 + c4*4];
            As[c4*4+0][r] = v.x; As[c4*4+1][r] = v.y;
            As[c4*4+2][r] = v.z; As[c4*4+3][r] = v.w;
        }
        #pragma unroll
        for (int i = tid; i < BN*BK/4; i += THREADS) {
            int r = i / (BK/4), c4 = i % (BK/4);
            float4 v = *(const float4*)&B[(size_t)(bn+r)*ldb + k0 + c4*4];
            Bs[c4*4+0][r] = v.x; Bs[c4*4+1][r] = v.y;
            Bs[c4*4+2][r] = v.z; Bs[c4*4+3][r] = v.w;
        }
        __syncthreads();
        #pragma unroll
        for (int kk = 0; kk < BK; kk++) {
            float a[TM], b[TN];
            #pragma unroll
            for (int i = 0; i < TM; i++) a[i] = As[kk][ty*TM + i];
            #pragma unroll
            for (int j = 0; j < TN; j++) b[j] = Bs[kk][tx*TN + j];
            #pragma unroll
            for (int i = 0; i < TM; i++)
                #pragma unroll
                for (int j = 0; j < TN; j++) acc[i][j] += a[i]*b[j];
        }
        __syncthreads();
    }

    #pragma unroll
    for (int i = 0; i < TM; i++) {
        int m = bm + ty*TM + i;
        #pragma unroll
        for (int j = 0; j < TN; j++) {
            int n = bn + tx*TN + j;
            float v = acc[i][j];
            if (bias) v += bias[n];
            if (act == 1) v = tanhf(v);
            C[(size_t)m*ldc + n] = v;
        }
    }
}

// ---------------- masked mean gather IN PROJECTED SPACE (R7 version) ----------------
__global__ void proj_gather_kernel(const int* __restrict__ col_idx, const int* __restrict__ col_mask,
                                   const int* __restrict__ tab_idx, const int* __restrict__ tab_mask)
{
    int u = blockIdx.x, t = blockIdx.y;
    int h4 = threadIdx.x;               // 192 threads, float4 each -> 768 floats
    const float* Pf = d_Pf + (size_t)t * DB_ * G3_;
    const float* Pb = d_Pb + (size_t)t * DB_ * G3_;
    size_t orow = ((size_t)t*U_ + u) * G3_ + h4*4;

    {
        float4 af = make_float4(0.f,0.f,0.f,0.f);
        float4 ab = make_float4(0.f,0.f,0.f,0.f);
        float cnt = 0.f;
        #pragma unroll
        for (int m = 0; m < MT_; m++) {
            if (tab_mask[u*MT_+m]) {
                int id = tab_idx[u*MT_+m];
                float4 vf = *(const float4*)&Pf[(size_t)id*G3_ + h4*4];
                float4 vb = *(const float4*)&Pb[(size_t)id*G3_ + h4*4];
                af.x += vf.x; af.y += vf.y; af.z += vf.z; af.w += vf.w;
                ab.x += vb.x; ab.y += vb.y; ab.z += vb.z; ab.w += vb.w;
                cnt += 1.f;
            }
        }
        float inv = 1.f / fmaxf(cnt, 1.f);
        af.x *= inv; af.y *= inv; af.z *= inv; af.w *= inv;
        ab.x *= inv; ab.y *= inv; ab.z *= inv; ab.w *= inv;
        *(float4*)&d_g_f1[orow] = af;
        *(float4*)&d_g_b2[orow] = ab;
    }
    {
        float4 af = make_float4(0.f,0.f,0.f,0.f);
        float4 ab = make_float4(0.f,0.f,0.f,0.f);
        float cnt = 0.f;
        #pragma unroll
        for (int m = 0; m < MC_; m++) {
            if (col_mask[u*MC_+m]) {
                int id = col_idx[u*MC_+m];
                float4 vf = *(const float4*)&Pf[(size_t)id*G3_ + h4*4];
                float4 vb = *(const float4*)&Pb[(size_t)id*G3_ + h4*4];
                af.x += vf.x; af.y += vf.y; af.z += vf.z; af.w += vf.w;
                ab.x += vb.x; ab.y += vb.y; ab.z += vb.z; ab.w += vb.w;
                cnt += 1.f;
            }
        }
        float inv = 1.f / fmaxf(cnt, 1.f);
        af.x *= inv; af.y *= inv; af.z *= inv; af.w *= inv;
        ab.x *= inv; ab.y *= inv; ab.z *= inv; ab.w *= inv;
        *(float4*)&d_g_f2[orow] = af;
        *(float4*)&d_g_b1[orow] = ab;
    }
}

// ---------------- GRU elementwise ----------------
__device__ __forceinline__ float sigm(float x) { return 1.f / (1.f + expf(-x)); }

// first steps (h=0). Also emits f1/b1 in split-bf16 [hi|lo|hi].  (R7 version)
__global__ void gru_first_kernel(const float* __restrict__ bih_f, const float* __restrict__ bhh_f,
                                 const float* __restrict__ bih_b, const float* __restrict__ bhh_b)
{
    int idx = blockIdx.x * blockDim.x + threadIdx.x;   // TU_*Hh_
    int row = idx >> 8, j = idx & 255;
    size_t sb = (size_t)row * G3_;
    {
        const float* g = d_g_f1 + sb;
        float r = sigm(g[j]       + bih_f[j]       + bhh_f[j]);
        float z = sigm(g[Hh_+j]   + bih_f[Hh_+j]   + bhh_f[Hh_+j]);
        float n = tanhf(g[2*Hh_+j] + bih_f[2*Hh_+j] + r * bhh_f[2*Hh_+j]);
        float v = (1.f - z) * n;
        d_f1[idx] = v;
        __nv_bfloat16 h = __float2bfloat16(v);
        __nv_bfloat16 l = __float2bfloat16(v - __bfloat162float(h));
        d_f1S[sb + j] = h; d_f1S[sb + Hh_ + j] = l; d_f1S[sb + 2*Hh_ + j] = h;
    }
    {
        const float* g = d_g_b1 + sb;
        float r = sigm(g[j]       + bih_b[j]       + bhh_b[j]);
        float z = sigm(g[Hh_+j]   + bih_b[Hh_+j]   + bhh_b[Hh_+j]);
        float n = tanhf(g[2*Hh_+j] + bih_b[2*Hh_+j] + r * bhh_b[2*Hh_+j]);
        float v = (1.f - z) * n;
        d_b1[idx] = v;
        __nv_bfloat16 h = __float2bfloat16(v);
        __nv_bfloat16 l = __float2bfloat16(v - __bfloat162float(h));
        d_b1S[sb + j] = h; d_b1S[sb + Hh_ + j] = l; d_b1S[sb + 2*Hh_ + j] = h;
    }
}

// second steps + db_emb + FUSED masked logit (key . db_row).
// One block per (t,u) row: 256 threads, thread j owns (j, j+256).
__global__ __launch_bounds__(256)
void gru_second_kernel(const float* __restrict__ bih_f, const float* __restrict__ bhh_f,
                       const float* __restrict__ bih_b, const float* __restrict__ bhh_b,
                       const float* __restrict__ key, const int* __restrict__ attn_mask)
{
    int row = blockIdx.x;                 // 0..TU_-1
    int j   = threadIdx.x;                // 0..255
    int idx = row * Hh_ + j;
    int t   = row >> 10;                  // row / U_
    float db0, db1;
    {
        const float* gi = d_g_f2 + (size_t)row * G3_;
        const float* gh = d_gh_f + (size_t)row * G3_;
        float h  = d_f1[idx];
        float r = sigm(gi[j]       + bih_f[j]       + gh[j]       + bhh_f[j]);
        float z = sigm(gi[Hh_+j]   + bih_f[Hh_+j]   + gh[Hh_+j]   + bhh_f[Hh_+j]);
        float n = tanhf(gi[2*Hh_+j] + bih_f[2*Hh_+j] + r * (gh[2*Hh_+j] + bhh_f[2*Hh_+j]));
        float f2 = (1.f - z) * n + z * h;
        db0 = 0.5f * (h + f2);
        d_db[(size_t)row*H_ + j] = db0;
    }
    {
        const float* gi = d_g_b2 + (size_t)row * G3_;
        const float* gh = d_gh_b + (size_t)row * G3_;
        float h  = d_b1[idx];
        float r = sigm(gi[j]       + bih_b[j]       + gh[j]       + bhh_b[j]);
        float z = sigm(gi[Hh_+j]   + bih_b[Hh_+j]   + gh[Hh_+j]   + bhh_b[Hh_+j]);
        float n = tanhf(gi[2*Hh_+j] + bih_b[2*Hh_+j] + r * (gh[2*Hh_+j] + bhh_b[2*Hh_+j]));
        float b2 = (1.f - z) * n + z * h;
        db1 = 0.5f * (h + b2);
        d_db[(size_t)row*H_ + Hh_ + j] = db1;
    }
    // fused logit: sum_j key[t][j]*db0 + key[t][Hh+j]*db1
    float part = key[(size_t)t*H_ + j] * db0 + key[(size_t)t*H_ + Hh_ + j] * db1;
    #pragma unroll
    for (int s = 16; s > 0; s >>= 1) part += __shfl_xor_sync(0xFFFFFFFFu, part, s);
    __shared__ float wsum[8];
    if ((j & 31) == 0) wsum[j >> 5] = part;
    __syncthreads();
    if (j == 0) {
        float acc = 0.f;
        #pragma unroll
        for (int w = 0; w < 8; w++) acc += wsum[w];
        d_logits[row] = attn_mask[row] ? acc : -1e9f;
    }
}

// ---------------- attention ----------------
__global__ void softmax_kernel()
{
    int t = blockIdx.x;
    __shared__ float red[256];
    int tid = threadIdx.x;
    float mx = -INFINITY;
    for (int u = tid; u < U_; u += 256) mx = fmaxf(mx, d_logits[t*U_+u]);
    red[tid] = mx; __syncthreads();
    for (int s = 128; s > 0; s >>= 1) { if (tid < s) red[tid] = fmaxf(red[tid], red[tid+s]); __syncthreads(); }
    mx = red[0]; __syncthreads();
    float sum = 0.f;
    for (int u = tid; u < U_; u += 256) sum += expf(d_logits[t*U_+u] - mx);
    red[tid] = sum; __syncthreads();
    for (int s = 128; s > 0; s >>= 1) { if (tid < s) red[tid] += red[tid+s]; __syncthreads(); }
    sum = red[0];
    float inv = 1.f / sum;
    for (int u = tid; u < U_; u += 256) d_wsm[t*U_+u] = expf(d_logits[t*U_+u] - mx) * inv;
}

// attention value: split U into 8 chunks of 128 (128 blocks) + reduce
__global__ void attn_part_kernel()
{
    int chunk = blockIdx.x, t = blockIdx.y;
    int h = threadIdx.x;                 // 512 threads
    __shared__ float ws[128];
    if (h < 128) ws[h] = d_wsm[t*U_ + chunk*128 + h];
    __syncthreads();
    float acc = 0.f;
    const float* d = d_db + ((size_t)t*U_ + chunk*128) * H_ + h;
    #pragma unroll 4
    for (int u = 0; u < 128; u++) acc += ws[u] * d[(size_t)u*H_];
    d_attnp[((size_t)t*8 + chunk)*H_ + h] = acc;
}

__global__ void attn_reduce_kernel()
{
    int t = blockIdx.x;
    int h = threadIdx.x;                 // 512
    float acc = 0.f;
    #pragma unroll
    for (int c = 0; c < 8; c++) acc += d_attnp[((size_t)t*8 + c)*H_ + h];
    d_attnv[t*H_ + h] = acc;
}

__global__ void add_attn_kernel(const float* __restrict__ final_feature)
{
    int idx = blockIdx.x * blockDim.x + threadIdx.x;   // T_*L_*H_
    int h = idx & (H_-1);
    int t = idx >> 15;
    d_ffin[idx] = final_feature[idx] + d_attnv[t*H_ + h];
}

// ---------------- final log-softmax ----------------
__global__ void logsoftmax_kernel(float* __restrict__ out)
{
    int r = blockIdx.x;
    int tid = threadIdx.x;
    __shared__ float red[256];
    const float* x = d_probs + (size_t)r * OUTC_;
    float mx = -INFINITY;
    for (int c = tid; c < OUTC_; c += 256) mx = fmaxf(mx, x[c]);
    red[tid] = mx; __syncthreads();
    for (int s = 128; s > 0; s >>= 1) { if (tid < s) red[tid] = fmaxf(red[tid], red[tid+s]); __syncthreads(); }
    mx = red[0]; __syncthreads();
    float sum = 0.f;
    for (int c = tid; c < OUTC_; c += 256) sum += expf(x[c] - mx);
    red[tid] = sum; __syncthreads();
    for (int s = 128; s > 0; s >>= 1) { if (tid < s) red[tid] += red[tid+s]; __syncthreads(); }
    float lse = mx + logf(red[0]);
    for (int c = tid; c < OUTC_; c += 256) out[(size_t)r*OUTC_ + c] = x[c] - lse;
}

// ---------------- host launcher ----------------
#define SYM(p, t, s) do { void* _t; cudaGetSymbolAddress(&_t, s); (p) = (t*)_t; } while (0)

extern "C" void kernel_launch(void* const* d_in, const int* in_sizes, int n_in,
                              void* d_out, int out_size)
{
    const float* feat          = (const float*)d_in[0];
    const float* key           = (const float*)d_in[1];
    const float* final_feature = (const float*)d_in[2];
    const float* Wih_f         = (const float*)d_in[3];
    const float* Whh_f         = (const float*)d_in[4];
    const float* bih_f         = (const float*)d_in[5];
    const float* bhh_f         = (const float*)d_in[6];
    const float* Wih_b         = (const float*)d_in[7];
    const float* Whh_b         = (const float*)d_in[8];
    const float* bih_b         = (const float*)d_in[9];
    const float* bhh_b         = (const float*)d_in[10];
    const float* Wb            = (const float*)d_in[11];
    const float* bb            = (const float*)d_in[12];
    const float* Kemb          = (const float*)d_in[13];
    const int*   col_idx       = (const int*)d_in[14];
    const int*   col_mask      = (const int*)d_in[15];
    const int*   tab_idx       = (const int*)d_in[16];
    const int*   tab_mask      = (const int*)d_in[17];
    const int*   attn_mask     = (const int*)d_in[18];
    float* out = (float*)d_out;

    float *Pf, *Pb, *gh_f, *gh_b, *db, *ffin, *ff, *probs;
    __nv_bfloat16 *featS, *WihfS, *WihbS, *WhhfS, *WhhbS, *f1S, *b1S;
    SYM(Pf, float, d_Pf);   SYM(Pb, float, d_Pb);
    SYM(gh_f, float, d_gh_f); SYM(gh_b, float, d_gh_b);
    SYM(db, float, d_db);   SYM(ffin, float, d_ffin); SYM(ff, float, d_ff); SYM(probs, float, d_probs);
    SYM(featS, __nv_bfloat16, d_featS);
    SYM(WihfS, __nv_bfloat16, d_WihfS); SYM(WihbS, __nv_bfloat16, d_WihbS);
    SYM(WhhfS, __nv_bfloat16, d_WhhfS); SYM(WhhbS, __nv_bfloat16, d_WhhbS);
    SYM(f1S, __nv_bfloat16, d_f1S);     SYM(b1S, __nv_bfloat16, d_b1S);

    // 0) split-bf16 conversions
    split_bf16_kernel<<<(TDB_*H_+255)/256, 256>>>(feat,  featS, TDB_*H_, H_, 0);
    split_bf16_kernel<<<(G3_*H_+255)/256, 256>>>(Wih_f, WihfS, G3_*H_, H_, 1);
    split_bf16_kernel<<<(G3_*H_+255)/256, 256>>>(Wih_b, WihbS, G3_*H_, H_, 1);
    split_bf16_kernel<<<(G3_*Hh_+255)/256, 256>>>(Whh_f, WhhfS, G3_*Hh_, Hh_, 1);
    split_bf16_kernel<<<(G3_*Hh_+255)/256, 256>>>(Whh_b, WhhbS, G3_*Hh_, Hh_, 1);

    // 1) projection GEMMs (HMMA): P = feat @ Wih^T  (8192 x 768, K'=1536)
    {
        dim3 grid(G3_/128, TDB_/128);
        gemm_wmma<<<grid, 256>>>(featS, WihfS, Pf, TDB_, G3_, 3*H_, G3_);
        gemm_wmma<<<grid, 256>>>(featS, WihbS, Pb, TDB_, G3_, 3*H_, G3_);
    }

    // 2) masked means in projected space -> gi buffers
    proj_gather_kernel<<<dim3(U_, T_), 192>>>(col_idx, col_mask, tab_idx, tab_mask);

    // 3) first GRU steps (h = 0), emits f1/b1 fp32 + split-bf16
    gru_first_kernel<<<TU_*Hh_/256, 256>>>(bih_f, bhh_f, bih_b, bhh_b);

    // 4) hidden-projection GEMMs (HMMA): (16384 x 768, K'=768) — raw, bhh added later
    {
        dim3 grid(G3_/128, TU_/128);
        gemm_wmma<<<grid, 256>>>(f1S, WhhfS, gh_f, TU_, G3_, 3*Hh_, G3_);
        gemm_wmma<<<grid, 256>>>(b1S, WhhbS, gh_b, TU_, G3_, 3*Hh_, G3_);
    }

    // 5) second GRU steps + db_emb + fused logits
    gru_second_kernel<<<TU_, 256>>>(bih_f, bhh_f, bih_b, bhh_b, key, attn_mask);

    // 6) attention
    softmax_kernel<<<T_, 256>>>();
    attn_part_kernel<<<dim3(8, T_), 512>>>();
    attn_reduce_kernel<<<T_, 512>>>();

    // 7) feature + attn, then ff = tanh(ffin @ Wb^T + bb)
    add_attn_kernel<<<T_*L_*H_/256, 256>>>(final_feature);
    {
        dim3 grid(H_/128, T_*L_/128, 1);
        sgemm_nt<128,128,16,8,8><<<grid, 256>>>(ffin, Wb, bb, ff, T_*L_, H_, H_, H_, H_, H_, 0,0,0, 1);
    }

    // 8) db_prob: per-t (64 x 1024) = ff[t] (64x512) @ db_emb[t] (1024x512)^T
    {
        dim3 grid(U_/128, L_/64, T_);
        sgemm_nt<64,128,16,4,8><<<grid, 256>>>(ff, db, nullptr, probs,
            L_, U_, H_, H_, H_, OUTC_,
            (long long)L_*H_, (long long)U_*H_, (long long)L_*OUTC_, 0);
    }
    // 9) kw_prob: (1024 x 64) = ff @ Kemb^T, at column offset U_
    {
        dim3 grid(K_/64, T_*L_/64, 1);
        sgemm_nt<64,64,16,4,4><<<grid, 256>>>(ff, Kemb, nullptr, probs + U_,
            T_*L_, K_, H_, H_, H_, OUTC_, 0,0,0, 0);
    }

    // 10) log-softmax over last dim (1088) -> output
    logsoftmax_kernel<<<T_*L_, 256>>>(out);
}

// round 12
// speedup vs baseline: 1.3663x; 1.1109x over previous
#include <cuda_runtime.h>
#include <cuda_bf16.h>
#include <mma.h>
#include <math.h>
#include <stdint.h>

using namespace nvcuda;

// Problem constants
#define T_  16
#define DB_ 512
#define H_  512
#define U_  1024
#define MC_ 8
#define MT_ 4
#define L_  64
#define K_  64
#define Hh_ 256
#define G3_ (3*Hh_)     // 768
#define TU_ (T_*U_)     // 16384
#define TDB_ (T_*DB_)   // 8192
#define OUTC_ (U_+K_)   // 1088

// ---------------- scratch (device globals; no allocs allowed) ----------------
__device__ float d_Pf[TDB_*G3_];      // feat @ Wih_f^T   (8192 x 768)
__device__ float d_Pb[TDB_*G3_];      // feat @ Wih_b^T
__device__ float d_g_f1[TU_*G3_];
__device__ float d_g_b2[TU_*G3_];
__device__ float d_g_f2[TU_*G3_];
__device__ float d_g_b1[TU_*G3_];
__device__ float d_f1[TU_*Hh_];
__device__ float d_b1[TU_*Hh_];
__device__ float d_gh_f[TU_*G3_];     // f1@Whh_f^T (raw, bhh added in gru_second)
__device__ float d_gh_b[TU_*G3_];
__device__ float d_db[TU_*H_];        // db_emb
__device__ float d_logits[T_*U_];
__device__ float d_wsm[T_*U_];
__device__ float d_attnp[T_*8*H_];    // attention partials (8 U-chunks)
__device__ float d_attnv[T_*H_];
__device__ float d_ffin[T_*L_*H_];
__device__ float d_ff[T_*L_*H_];
__device__ float d_probs[T_*L_*OUTC_];

// split-bf16 operand buffers ([hi|lo|hi] A-side, [hi|hi|lo] B-side)
__device__ __nv_bfloat16 d_featS[TDB_*3*H_];   // 8192 x 1536
__device__ __nv_bfloat16 d_WihfS[G3_*3*H_];
__device__ __nv_bfloat16 d_WihbS[G3_*3*H_];
__device__ __nv_bfloat16 d_WhhfS[G3_*3*Hh_];
__device__ __nv_bfloat16 d_WhhbS[G3_*3*Hh_];
__device__ __nv_bfloat16 d_f1S[TU_*3*Hh_];
__device__ __nv_bfloat16 d_b1S[TU_*3*Hh_];

// ================= cp.async helpers =================
__device__ __forceinline__ void cp_async16(void* smem_ptr, const void* gptr) {
    uint32_t s = (uint32_t)__cvta_generic_to_shared(smem_ptr);
    asm volatile("cp.async.cg.shared.global [%0], [%1], 16;" :: "r"(s), "l"(gptr));
}
__device__ __forceinline__ void cp_commit() { asm volatile("cp.async.commit_group;" ::: "memory"); }
__device__ __forceinline__ void cp_wait1()  { asm volatile("cp.async.wait_group 1;" ::: "memory"); }
__device__ __forceinline__ void cp_wait0()  { asm volatile("cp.async.wait_group 0;" ::: "memory"); }

// ================= WMMA bf16 GEMM — double-buffered cp.async, WPAD=48 =================
// C(MxN) = A(M x K3) @ B(N x K3)^T ; bf16 operands, fp32 accumulate.
// Tile: BM=128, BN=128, BK=32; 256 threads = 8 warps (2x4), warp tile 64x32.
// ONLY change vs the 944us kernel: 2-stage pipeline; smem layout (WPAD=48) unchanged.
#define WBK 32
#define WPAD 48   // smem leading dim (elements): 96B rows (32B-aligned, %8==0)

__global__ __launch_bounds__(256)
void gemm_wmma(const __nv_bfloat16* __restrict__ A, const __nv_bfloat16* __restrict__ B,
               float* __restrict__ C, int M, int N, int K3, int ldc)
{
    __shared__ __nv_bfloat16 As[2][128 * WPAD];   // 24 KB
    __shared__ __nv_bfloat16 Bs[2][128 * WPAD];   // 24 KB

    int tid  = threadIdx.x;
    int warp = tid >> 5;
    int wm = warp >> 2;          // 0..1 : 64-row slab
    int wn = warp & 3;           // 0..3 : 32-col slab
    int bm = blockIdx.y * 128;
    int bn = blockIdx.x * 128;

    wmma::fragment<wmma::accumulator, 16, 16, 16, float> acc[4][2];
    #pragma unroll
    for (int i = 0; i < 4; i++)
        #pragma unroll
        for (int j = 0; j < 2; j++) wmma::fill_fragment(acc[i][j], 0.0f);

    const int nch = K3 / WBK;

    // stage loader: 128 rows x 32 cols per operand, one 16B cp.async per (thread,slot)
    auto load_stage = [&](int s, int k0) {
        #pragma unroll
        for (int i = tid; i < 512; i += 256) {
            int r = i >> 2, c = i & 3;
            cp_async16(&As[s][r * WPAD + c * 8], A + (size_t)(bm + r) * K3 + k0 + c * 8);
        }
        #pragma unroll
        for (int i = tid; i < 512; i += 256) {
            int r = i >> 2, c = i & 3;
            cp_async16(&Bs[s][r * WPAD + c * 8], B + (size_t)(bn + r) * K3 + k0 + c * 8);
        }
        cp_commit();
    };

    load_stage(0, 0);

    for (int c = 0; c < nch; c++) {
        if (c + 1 < nch) { load_stage((c + 1) & 1, (c + 1) * WBK); cp_wait1(); }
        else             { cp_wait0(); }
        __syncthreads();

        int s = c & 1;
        #pragma unroll
        for (int kk = 0; kk < WBK; kk += 16) {
            wmma::fragment<wmma::matrix_a, 16, 16, 16, __nv_bfloat16, wmma::row_major> fa[4];
            wmma::fragment<wmma::matrix_b, 16, 16, 16, __nv_bfloat16, wmma::col_major> fb[2];
            #pragma unroll
            for (int i = 0; i < 4; i++)
                wmma::load_matrix_sync(fa[i], &As[s][(wm * 64 + i * 16) * WPAD + kk], WPAD);
            #pragma unroll
            for (int j = 0; j < 2; j++)
                wmma::load_matrix_sync(fb[j], &Bs[s][(wn * 32 + j * 16) * WPAD + kk], WPAD);
            #pragma unroll
            for (int i = 0; i < 4; i++)
                #pragma unroll
                for (int j = 0; j < 2; j++)
                    wmma::mma_sync(acc[i][j], fa[i], fb[j], acc[i][j]);
        }
        __syncthreads();
    }

    #pragma unroll
    for (int i = 0; i < 4; i++)
        #pragma unroll
        for (int j = 0; j < 2; j++) {
            int m0 = bm + wm * 64 + i * 16;
            int n0 = bn + wn * 32 + j * 16;
            wmma::store_matrix_sync(C + (size_t)m0 * ldc + n0, acc[i][j], ldc, wmma::mem_row_major);
        }
}

// ================= split-bf16 conversion =================
// orderB=0: [hi|lo|hi] (A-side) ; orderB=1: [hi|hi|lo] (B-side)
__global__ void split_bf16_kernel(const float* __restrict__ X, __nv_bfloat16* __restrict__ Y,
                                  int n, int Kd, int orderB)
{
    int idx = blockIdx.x * blockDim.x + threadIdx.x;
    if (idx >= n) return;
    float x = X[idx];
    __nv_bfloat16 h = __float2bfloat16(x);
    __nv_bfloat16 l = __float2bfloat16(x - __bfloat162float(h));
    int r = idx / Kd, k = idx - r * Kd;
    size_t bse = (size_t)r * 3 * Kd;
    if (orderB) { Y[bse + k] = h; Y[bse + Kd + k] = h; Y[bse + 2*Kd + k] = l; }
    else        { Y[bse + k] = h; Y[bse + Kd + k] = l; Y[bse + 2*Kd + k] = h; }
}

// ---------------- scalar-FFMA SGEMM (small tail GEMMs) ----------------
template<int BM, int BN, int BK, int TM, int TN>
__global__ void sgemm_nt(const float* __restrict__ A, const float* __restrict__ B,
                         const float* __restrict__ bias, float* __restrict__ C,
                         int M, int N, int K, int lda, int ldb, int ldc,
                         long long sA, long long sB, long long sC, int act)
{
    constexpr int THREADS = (BM/TM) * (BN/TN);
    __shared__ float As[BK][BM];
    __shared__ float Bs[BK][BN];

    A += (size_t)blockIdx.z * sA;
    B += (size_t)blockIdx.z * sB;
    C += (size_t)blockIdx.z * sC;

    int bm = blockIdx.y * BM;
    int bn = blockIdx.x * BN;
    int tid = threadIdx.x;
    int tx = tid % (BN/TN);
    int ty = tid / (BN/TN);

    float acc[TM][TN];
    #pragma unroll
    for (int i = 0; i < TM; i++)
        #pragma unroll
        for (int j = 0; j < TN; j++) acc[i][j] = 0.f;

    for (int k0 = 0; k0 < K; k0 += BK) {
        #pragma unroll
        for (int i = tid; i < BM*BK/4; i += THREADS) {
            int r = i / (BK/4), c4 = i % (BK/4);
            float4 v = *(const float4*)&A[(size_t)(bm+r)*lda + k0 + c4*4];
            As[c4*4+0][r] = v.x; As[c4*4+1][r] = v.y;
            As[c4*4+2][r] = v.z; As[c4*4+3][r] = v.w;
        }
        #pragma unroll
        for (int i = tid; i < BN*BK/4; i += THREADS) {
            int r = i / (BK/4), c4 = i % (BK/4);
            float4 v = *(const float4*)&B[(size_t)(bn+r)*ldb + k0 + c4*4];
            Bs[c4*4+0][r] = v.x; Bs[c4*4+1][r] = v.y;
            Bs[c4*4+2][r] = v.z; Bs[c4*4+3][r] = v.w;
        }
        __syncthreads();
        #pragma unroll
        for (int kk = 0; kk < BK; kk++) {
            float a[TM], b[TN];
            #pragma unroll
            for (int i = 0; i < TM; i++) a[i] = As[kk][ty*TM + i];
            #pragma unroll
            for (int j = 0; j < TN; j++) b[j] = Bs[kk][tx*TN + j];
            #pragma unroll
            for (int i = 0; i < TM; i++)
                #pragma unroll
                for (int j = 0; j < TN; j++) acc[i][j] += a[i]*b[j];
        }
        __syncthreads();
    }

    #pragma unroll
    for (int i = 0; i < TM; i++) {
        int m = bm + ty*TM + i;
        #pragma unroll
        for (int j = 0; j < TN; j++) {
            int n = bn + tx*TN + j;
            float v = acc[i][j];
            if (bias) v += bias[n];
            if (act == 1) v = tanhf(v);
            C[(size_t)m*ldc + n] = v;
        }
    }
}

// ---------------- masked mean gather IN PROJECTED SPACE ----------------
__global__ void proj_gather_kernel(const int* __restrict__ col_idx, const int* __restrict__ col_mask,
                                   const int* __restrict__ tab_idx, const int* __restrict__ tab_mask)
{
    int u = blockIdx.x, t = blockIdx.y;
    int h4 = threadIdx.x;               // 192 threads, float4 each -> 768 floats
    const float* Pf = d_Pf + (size_t)t * DB_ * G3_;
    const float* Pb = d_Pb + (size_t)t * DB_ * G3_;
    size_t orow = ((size_t)t*U_ + u) * G3_ + h4*4;

    {
        float4 af = make_float4(0.f,0.f,0.f,0.f);
        float4 ab = make_float4(0.f,0.f,0.f,0.f);
        float cnt = 0.f;
        #pragma unroll
        for (int m = 0; m < MT_; m++) {
            if (tab_mask[u*MT_+m]) {
                int id = tab_idx[u*MT_+m];
                float4 vf = *(const float4*)&Pf[(size_t)id*G3_ + h4*4];
                float4 vb = *(const float4*)&Pb[(size_t)id*G3_ + h4*4];
                af.x += vf.x; af.y += vf.y; af.z += vf.z; af.w += vf.w;
                ab.x += vb.x; ab.y += vb.y; ab.z += vb.z; ab.w += vb.w;
                cnt += 1.f;
            }
        }
        float inv = 1.f / fmaxf(cnt, 1.f);
        af.x *= inv; af.y *= inv; af.z *= inv; af.w *= inv;
        ab.x *= inv; ab.y *= inv; ab.z *= inv; ab.w *= inv;
        *(float4*)&d_g_f1[orow] = af;
        *(float4*)&d_g_b2[orow] = ab;
    }
    {
        float4 af = make_float4(0.f,0.f,0.f,0.f);
        float4 ab = make_float4(0.f,0.f,0.f,0.f);
        float cnt = 0.f;
        #pragma unroll
        for (int m = 0; m < MC_; m++) {
            if (col_mask[u*MC_+m]) {
                int id = col_idx[u*MC_+m];
                float4 vf = *(const float4*)&Pf[(size_t)id*G3_ + h4*4];
                float4 vb = *(const float4*)&Pb[(size_t)id*G3_ + h4*4];
                af.x += vf.x; af.y += vf.y; af.z += vf.z; af.w += vf.w;
                ab.x += vb.x; ab.y += vb.y; ab.z += vb.z; ab.w += vb.w;
                cnt += 1.f;
            }
        }
        float inv = 1.f / fmaxf(cnt, 1.f);
        af.x *= inv; af.y *= inv; af.z *= inv; af.w *= inv;
        ab.x *= inv; ab.y *= inv; ab.z *= inv; ab.w *= inv;
        *(float4*)&d_g_f2[orow] = af;
        *(float4*)&d_g_b1[orow] = ab;
    }
}

// ---------------- GRU elementwise ----------------
__device__ __forceinline__ float sigm(float x) { return 1.f / (1.f + expf(-x)); }

// first steps (h=0). Also emits f1/b1 in split-bf16 [hi|lo|hi].
__global__ void gru_first_kernel(const float* __restrict__ bih_f, const float* __restrict__ bhh_f,
                                 const float* __restrict__ bih_b, const float* __restrict__ bhh_b)
{
    int idx = blockIdx.x * blockDim.x + threadIdx.x;   // TU_*Hh_
    int row = idx >> 8, j = idx & 255;
    size_t sb = (size_t)row * G3_;
    {
        const float* g = d_g_f1 + sb;
        float r = sigm(g[j]       + bih_f[j]       + bhh_f[j]);
        float z = sigm(g[Hh_+j]   + bih_f[Hh_+j]   + bhh_f[Hh_+j]);
        float n = tanhf(g[2*Hh_+j] + bih_f[2*Hh_+j] + r * bhh_f[2*Hh_+j]);
        float v = (1.f - z) * n;
        d_f1[idx] = v;
        __nv_bfloat16 h = __float2bfloat16(v);
        __nv_bfloat16 l = __float2bfloat16(v - __bfloat162float(h));
        d_f1S[sb + j] = h; d_f1S[sb + Hh_ + j] = l; d_f1S[sb + 2*Hh_ + j] = h;
    }
    {
        const float* g = d_g_b1 + sb;
        float r = sigm(g[j]       + bih_b[j]       + bhh_b[j]);
        float z = sigm(g[Hh_+j]   + bih_b[Hh_+j]   + bhh_b[Hh_+j]);
        float n = tanhf(g[2*Hh_+j] + bih_b[2*Hh_+j] + r * bhh_b[2*Hh_+j]);
        float v = (1.f - z) * n;
        d_b1[idx] = v;
        __nv_bfloat16 h = __float2bfloat16(v);
        __nv_bfloat16 l = __float2bfloat16(v - __bfloat162float(h));
        d_b1S[sb + j] = h; d_b1S[sb + Hh_ + j] = l; d_b1S[sb + 2*Hh_ + j] = h;
    }
}

// second steps + db_emb + FUSED masked logit (key . db_row).
__global__ __launch_bounds__(256)
void gru_second_kernel(const float* __restrict__ bih_f, const float* __restrict__ bhh_f,
                       const float* __restrict__ bih_b, const float* __restrict__ bhh_b,
                       const float* __restrict__ key, const int* __restrict__ attn_mask)
{
    int row = blockIdx.x;                 // 0..TU_-1
    int j   = threadIdx.x;                // 0..255
    int idx = row * Hh_ + j;
    int t   = row >> 10;                  // row / U_
    float db0, db1;
    {
        const float* gi = d_g_f2 + (size_t)row * G3_;
        const float* gh = d_gh_f + (size_t)row * G3_;
        float h  = d_f1[idx];
        float r = sigm(gi[j]       + bih_f[j]       + gh[j]       + bhh_f[j]);
        float z = sigm(gi[Hh_+j]   + bih_f[Hh_+j]   + gh[Hh_+j]   + bhh_f[Hh_+j]);
        float n = tanhf(gi[2*Hh_+j] + bih_f[2*Hh_+j] + r * (gh[2*Hh_+j] + bhh_f[2*Hh_+j]));
        float f2 = (1.f - z) * n + z * h;
        db0 = 0.5f * (h + f2);
        d_db[(size_t)row*H_ + j] = db0;
    }
    {
        const float* gi = d_g_b2 + (size_t)row * G3_;
        const float* gh = d_gh_b + (size_t)row * G3_;
        float h  = d_b1[idx];
        float r = sigm(gi[j]       + bih_b[j]       + gh[j]       + bhh_b[j]);
        float z = sigm(gi[Hh_+j]   + bih_b[Hh_+j]   + gh[Hh_+j]   + bhh_b[Hh_+j]);
        float n = tanhf(gi[2*Hh_+j] + bih_b[2*Hh_+j] + r * (gh[2*Hh_+j] + bhh_b[2*Hh_+j]));
        float b2 = (1.f - z) * n + z * h;
        db1 = 0.5f * (h + b2);
        d_db[(size_t)row*H_ + Hh_ + j] = db1;
    }
    // fused logit: sum_j key[t][j]*db0 + key[t][Hh+j]*db1
    float part = key[(size_t)t*H_ + j] * db0 + key[(size_t)t*H_ + Hh_ + j] * db1;
    #pragma unroll
    for (int s = 16; s > 0; s >>= 1) part += __shfl_xor_sync(0xFFFFFFFFu, part, s);
    __shared__ float wsum[8];
    if ((j & 31) == 0) wsum[j >> 5] = part;
    __syncthreads();
    if (j == 0) {
        float acc = 0.f;
        #pragma unroll
        for (int w = 0; w < 8; w++) acc += wsum[w];
        d_logits[row] = attn_mask[row] ? acc : -1e9f;
    }
}

// ---------------- attention ----------------
__global__ void softmax_kernel()
{
    int t = blockIdx.x;
    __shared__ float red[256];
    int tid = threadIdx.x;
    float mx = -INFINITY;
    for (int u = tid; u < U_; u += 256) mx = fmaxf(mx, d_logits[t*U_+u]);
    red[tid] = mx; __syncthreads();
    for (int s = 128; s > 0; s >>= 1) { if (tid < s) red[tid] = fmaxf(red[tid], red[tid+s]); __syncthreads(); }
    mx = red[0]; __syncthreads();
    float sum = 0.f;
    for (int u = tid; u < U_; u += 256) sum += expf(d_logits[t*U_+u] - mx);
    red[tid] = sum; __syncthreads();
    for (int s = 128; s > 0; s >>= 1) { if (tid < s) red[tid] += red[tid+s]; __syncthreads(); }
    sum = red[0];
    float inv = 1.f / sum;
    for (int u = tid; u < U_; u += 256) d_wsm[t*U_+u] = expf(d_logits[t*U_+u] - mx) * inv;
}

// attention value: split U into 8 chunks of 128 (128 blocks) + reduce
__global__ void attn_part_kernel()
{
    int chunk = blockIdx.x, t = blockIdx.y;
    int h = threadIdx.x;                 // 512 threads
    __shared__ float ws[128];
    if (h < 128) ws[h] = d_wsm[t*U_ + chunk*128 + h];
    __syncthreads();
    float acc = 0.f;
    const float* d = d_db + ((size_t)t*U_ + chunk*128) * H_ + h;
    #pragma unroll 4
    for (int u = 0; u < 128; u++) acc += ws[u] * d[(size_t)u*H_];
    d_attnp[((size_t)t*8 + chunk)*H_ + h] = acc;
}

__global__ void attn_reduce_kernel()
{
    int t = blockIdx.x;
    int h = threadIdx.x;                 // 512
    float acc = 0.f;
    #pragma unroll
    for (int c = 0; c < 8; c++) acc += d_attnp[((size_t)t*8 + c)*H_ + h];
    d_attnv[t*H_ + h] = acc;
}

__global__ void add_attn_kernel(const float* __restrict__ final_feature)
{
    int idx = blockIdx.x * blockDim.x + threadIdx.x;   // T_*L_*H_
    int h = idx & (H_-1);
    int t = idx >> 15;
    d_ffin[idx] = final_feature[idx] + d_attnv[t*H_ + h];
}

// ---------------- final log-softmax ----------------
__global__ void logsoftmax_kernel(float* __restrict__ out)
{
    int r = blockIdx.x;
    int tid = threadIdx.x;
    __shared__ float red[256];
    const float* x = d_probs + (size_t)r * OUTC_;
    float mx = -INFINITY;
    for (int c = tid; c < OUTC_; c += 256) mx = fmaxf(mx, x[c]);
    red[tid] = mx; __syncthreads();
    for (int s = 128; s > 0; s >>= 1) { if (tid < s) red[tid] = fmaxf(red[tid], red[tid+s]); __syncthreads(); }
    mx = red[0]; __syncthreads();
    float sum = 0.f;
    for (int c = tid; c < OUTC_; c += 256) sum += expf(x[c] - mx);
    red[tid] = sum; __syncthreads();
    for (int s = 128; s > 0; s >>= 1) { if (tid < s) red[tid] += red[tid+s]; __syncthreads(); }
    float lse = mx + logf(red[0]);
    for (int c = tid; c < OUTC_; c += 256) out[(size_t)r*OUTC_ + c] = x[c] - lse;
}

// ---------------- host launcher ----------------
#define SYM(p, t, s) do { void* _t; cudaGetSymbolAddress(&_t, s); (p) = (t*)_t; } while (0)

extern "C" void kernel_launch(void* const* d_in, const int* in_sizes, int n_in,
                              void* d_out, int out_size)
{
    const float* feat          = (const float*)d_in[0];
    const float* key           = (const float*)d_in[1];
    const float* final_feature = (const float*)d_in[2];
    const float* Wih_f         = (const float*)d_in[3];
    const float* Whh_f         = (const float*)d_in[4];
    const float* bih_f         = (const float*)d_in[5];
    const float* bhh_f         = (const float*)d_in[6];
    const float* Wih_b         = (const float*)d_in[7];
    const float* Whh_b         = (const float*)d_in[8];
    const float* bih_b         = (const float*)d_in[9];
    const float* bhh_b         = (const float*)d_in[10];
    const float* Wb            = (const float*)d_in[11];
    const float* bb            = (const float*)d_in[12];
    const float* Kemb          = (const float*)d_in[13];
    const int*   col_idx       = (const int*)d_in[14];
    const int*   col_mask      = (const int*)d_in[15];
    const int*   tab_idx       = (const int*)d_in[16];
    const int*   tab_mask      = (const int*)d_in[17];
    const int*   attn_mask     = (const int*)d_in[18];
    float* out = (float*)d_out;

    float *Pf, *Pb, *gh_f, *gh_b, *db, *ffin, *ff, *probs;
    __nv_bfloat16 *featS, *WihfS, *WihbS, *WhhfS, *WhhbS, *f1S, *b1S;
    SYM(Pf, float, d_Pf);   SYM(Pb, float, d_Pb);
    SYM(gh_f, float, d_gh_f); SYM(gh_b, float, d_gh_b);
    SYM(db, float, d_db);   SYM(ffin, float, d_ffin); SYM(ff, float, d_ff); SYM(probs, float, d_probs);
    SYM(featS, __nv_bfloat16, d_featS);
    SYM(WihfS, __nv_bfloat16, d_WihfS); SYM(WihbS, __nv_bfloat16, d_WihbS);
    SYM(WhhfS, __nv_bfloat16, d_WhhfS); SYM(WhhbS, __nv_bfloat16, d_WhhbS);
    SYM(f1S, __nv_bfloat16, d_f1S);     SYM(b1S, __nv_bfloat16, d_b1S);

    // 0) split-bf16 conversions
    split_bf16_kernel<<<(TDB_*H_+255)/256, 256>>>(feat,  featS, TDB_*H_, H_, 0);
    split_bf16_kernel<<<(G3_*H_+255)/256, 256>>>(Wih_f, WihfS, G3_*H_, H_, 1);
    split_bf16_kernel<<<(G3_*H_+255)/256, 256>>>(Wih_b, WihbS, G3_*H_, H_, 1);
    split_bf16_kernel<<<(G3_*Hh_+255)/256, 256>>>(Whh_f, WhhfS, G3_*Hh_, Hh_, 1);
    split_bf16_kernel<<<(G3_*Hh_+255)/256, 256>>>(Whh_b, WhhbS, G3_*Hh_, Hh_, 1);

    // 1) projection GEMMs (HMMA, pipelined): P = feat @ Wih^T  (8192 x 768, K'=1536)
    {
        dim3 grid(G3_/128, TDB_/128);
        gemm_wmma<<<grid, 256>>>(featS, WihfS, Pf, TDB_, G3_, 3*H_, G3_);
        gemm_wmma<<<grid, 256>>>(featS, WihbS, Pb, TDB_, G3_, 3*H_, G3_);
    }

    // 2) masked means in projected space -> gi buffers
    proj_gather_kernel<<<dim3(U_, T_), 192>>>(col_idx, col_mask, tab_idx, tab_mask);

    // 3) first GRU steps (h = 0), emits f1/b1 fp32 + split-bf16
    gru_first_kernel<<<TU_*Hh_/256, 256>>>(bih_f, bhh_f, bih_b, bhh_b);

    // 4) hidden-projection GEMMs (HMMA, pipelined): (16384 x 768, K'=768)
    {
        dim3 grid(G3_/128, TU_/128);
        gemm_wmma<<<grid, 256>>>(f1S, WhhfS, gh_f, TU_, G3_, 3*Hh_, G3_);
        gemm_wmma<<<grid, 256>>>(b1S, WhhbS, gh_b, TU_, G3_, 3*Hh_, G3_);
    }

    // 5) second GRU steps + db_emb + fused logits
    gru_second_kernel<<<TU_, 256>>>(bih_f, bhh_f, bih_b, bhh_b, key, attn_mask);

    // 6) attention
    softmax_kernel<<<T_, 256>>>();
    attn_part_kernel<<<dim3(8, T_), 512>>>();
    attn_reduce_kernel<<<T_, 512>>>();

    // 7) feature + attn, then ff = tanh(ffin @ Wb^T + bb)
    add_attn_kernel<<<T_*L_*H_/256, 256>>>(final_feature);
    {
        dim3 grid(H_/128, T_*L_/128, 1);
        sgemm_nt<128,128,16,8,8><<<grid, 256>>>(ffin, Wb, bb, ff, T_*L_, H_, H_, H_, H_, H_, 0,0,0, 1);
    }

    // 8) db_prob: per-t (64 x 1024) = ff[t] (64x512) @ db_emb[t] (1024x512)^T
    {
        dim3 grid(U_/128, L_/64, T_);
        sgemm_nt<64,128,16,4,8><<<grid, 256>>>(ff, db, nullptr, probs,
            L_, U_, H_, H_, H_, OUTC_,
            (long long)L_*H_, (long long)U_*H_, (long long)L_*OUTC_, 0);
    }
    // 9) kw_prob: (1024 x 64) = ff @ Kemb^T, at column offset U_
    {
        dim3 grid(K_/64, T_*L_/64, 1);
        sgemm_nt<64,64,16,4,4><<<grid, 256>>>(ff, Kemb, nullptr, probs + U_,
            T_*L_, K_, H_, H_, H_, OUTC_, 0,0,0, 0);
    }

    // 10) log-softmax over last dim (1088) -> output
    logsoftmax_kernel<<<T_*L_, 256>>>(out);
}

// round 14
// speedup vs baseline: 1.4070x; 1.0298x over previous
#include <cuda_runtime.h>
#include <cuda_bf16.h>
#include <mma.h>
#include <math.h>
#include <stdint.h>

using namespace nvcuda;

// Problem constants
#define T_  16
#define DB_ 512
#define H_  512
#define U_  1024
#define MC_ 8
#define MT_ 4
#define L_  64
#define K_  64
#define Hh_ 256
#define G3_ (3*Hh_)     // 768
#define TU_ (T_*U_)     // 16384
#define TDB_ (T_*DB_)   // 8192
#define OUTC_ (U_+K_)   // 1088

// ---------------- scratch (device globals; no allocs allowed) ----------------
__device__ float d_Pf[TDB_*G3_];      // feat @ Wih_f^T   (8192 x 768)
__device__ float d_Pb[TDB_*G3_];      // feat @ Wih_b^T
__device__ float d_g_f2[TU_*G3_];     // col-mean of Pf  (gi for f2)
__device__ float d_g_b2[TU_*G3_];     // tab-mean of Pb  (gi for b2)
__device__ float d_f1[TU_*Hh_];
__device__ float d_b1[TU_*Hh_];
__device__ float d_gh_f[TU_*G3_];     // f1@Whh_f^T (raw, bhh added in gru_second)
__device__ float d_gh_b[TU_*G3_];
__device__ float d_db[TU_*H_];        // db_emb
__device__ float d_logits[T_*U_];
__device__ float d_wsm[T_*U_];
__device__ float d_attnp[T_*8*H_];    // attention partials (8 U-chunks)
__device__ float d_attnv[T_*H_];
__device__ float d_ffin[T_*L_*H_];
__device__ float d_ff[T_*L_*H_];
__device__ float d_probs[T_*L_*OUTC_];

// split-bf16 operand buffers ([hi|lo|hi] A-side, [hi|hi|lo] B-side)
__device__ __nv_bfloat16 d_featS[TDB_*3*H_];   // 8192 x 1536
__device__ __nv_bfloat16 d_WihfS[G3_*3*H_];
__device__ __nv_bfloat16 d_WihbS[G3_*3*H_];
__device__ __nv_bfloat16 d_WhhfS[G3_*3*Hh_];
__device__ __nv_bfloat16 d_WhhbS[G3_*3*Hh_];
__device__ __nv_bfloat16 d_f1S[TU_*3*Hh_];
__device__ __nv_bfloat16 d_b1S[TU_*3*Hh_];

// ================= cp.async helpers =================
__device__ __forceinline__ void cp_async16(void* smem_ptr, const void* gptr) {
    uint32_t s = (uint32_t)__cvta_generic_to_shared(smem_ptr);
    asm volatile("cp.async.cg.shared.global [%0], [%1], 16;" :: "r"(s), "l"(gptr));
}
__device__ __forceinline__ void cp_commit() { asm volatile("cp.async.commit_group;" ::: "memory"); }
__device__ __forceinline__ void cp_wait1()  { asm volatile("cp.async.wait_group 1;" ::: "memory"); }
__device__ __forceinline__ void cp_wait0()  { asm volatile("cp.async.wait_group 0;" ::: "memory"); }

// ================= WMMA bf16 GEMM — double-buffered cp.async, WPAD=48 (R12, 850us) =================
#define WBK 32
#define WPAD 48   // smem leading dim (elements): 96B rows (32B-aligned, %8==0)

__global__ __launch_bounds__(256)
void gemm_wmma(const __nv_bfloat16* __restrict__ A, const __nv_bfloat16* __restrict__ B,
               float* __restrict__ C, int M, int N, int K3, int ldc)
{
    __shared__ __nv_bfloat16 As[2][128 * WPAD];   // 24 KB
    __shared__ __nv_bfloat16 Bs[2][128 * WPAD];   // 24 KB

    int tid  = threadIdx.x;
    int warp = tid >> 5;
    int wm = warp >> 2;          // 0..1 : 64-row slab
    int wn = warp & 3;           // 0..3 : 32-col slab
    int bm = blockIdx.y * 128;
    int bn = blockIdx.x * 128;

    wmma::fragment<wmma::accumulator, 16, 16, 16, float> acc[4][2];
    #pragma unroll
    for (int i = 0; i < 4; i++)
        #pragma unroll
        for (int j = 0; j < 2; j++) wmma::fill_fragment(acc[i][j], 0.0f);

    const int nch = K3 / WBK;

    auto load_stage = [&](int s, int k0) {
        #pragma unroll
        for (int i = tid; i < 512; i += 256) {
            int r = i >> 2, c = i & 3;
            cp_async16(&As[s][r * WPAD + c * 8], A + (size_t)(bm + r) * K3 + k0 + c * 8);
        }
        #pragma unroll
        for (int i = tid; i < 512; i += 256) {
            int r = i >> 2, c = i & 3;
            cp_async16(&Bs[s][r * WPAD + c * 8], B + (size_t)(bn + r) * K3 + k0 + c * 8);
        }
        cp_commit();
    };

    load_stage(0, 0);

    for (int c = 0; c < nch; c++) {
        if (c + 1 < nch) { load_stage((c + 1) & 1, (c + 1) * WBK); cp_wait1(); }
        else             { cp_wait0(); }
        __syncthreads();

        int s = c & 1;
        #pragma unroll
        for (int kk = 0; kk < WBK; kk += 16) {
            wmma::fragment<wmma::matrix_a, 16, 16, 16, __nv_bfloat16, wmma::row_major> fa[4];
            wmma::fragment<wmma::matrix_b, 16, 16, 16, __nv_bfloat16, wmma::col_major> fb[2];
            #pragma unroll
            for (int i = 0; i < 4; i++)
                wmma::load_matrix_sync(fa[i], &As[s][(wm * 64 + i * 16) * WPAD + kk], WPAD);
            #pragma unroll
            for (int j = 0; j < 2; j++)
                wmma::load_matrix_sync(fb[j], &Bs[s][(wn * 32 + j * 16) * WPAD + kk], WPAD);
            #pragma unroll
            for (int i = 0; i < 4; i++)
                #pragma unroll
                for (int j = 0; j < 2; j++)
                    wmma::mma_sync(acc[i][j], fa[i], fb[j], acc[i][j]);
        }
        __syncthreads();
    }

    #pragma unroll
    for (int i = 0; i < 4; i++)
        #pragma unroll
        for (int j = 0; j < 2; j++) {
            int m0 = bm + wm * 64 + i * 16;
            int n0 = bn + wn * 32 + j * 16;
            wmma::store_matrix_sync(C + (size_t)m0 * ldc + n0, acc[i][j], ldc, wmma::mem_row_major);
        }
}

// ================= split-bf16 conversion =================
// orderB=0: [hi|lo|hi] (A-side) ; orderB=1: [hi|hi|lo] (B-side)
__global__ void split_bf16_kernel(const float* __restrict__ X, __nv_bfloat16* __restrict__ Y,
                                  int n, int Kd, int orderB)
{
    int idx = blockIdx.x * blockDim.x + threadIdx.x;
    if (idx >= n) return;
    float x = X[idx];
    __nv_bfloat16 h = __float2bfloat16(x);
    __nv_bfloat16 l = __float2bfloat16(x - __bfloat162float(h));
    int r = idx / Kd, k = idx - r * Kd;
    size_t bse = (size_t)r * 3 * Kd;
    if (orderB) { Y[bse + k] = h; Y[bse + Kd + k] = h; Y[bse + 2*Kd + k] = l; }
    else        { Y[bse + k] = h; Y[bse + Kd + k] = l; Y[bse + 2*Kd + k] = h; }
}

// ---------------- scalar-FFMA SGEMM (small tail GEMMs) ----------------
template<int BM, int BN, int BK, int TM, int TN>
__global__ void sgemm_nt(const float* __restrict__ A, const float* __restrict__ B,
                         const float* __restrict__ bias, float* __restrict__ C,
                         int M, int N, int K, int lda, int ldb, int ldc,
                         long long sA, long long sB, long long sC, int act)
{
    constexpr int THREADS = (BM/TM) * (BN/TN);
    __shared__ float As[BK][BM];
    __shared__ float Bs[BK][BN];

    A += (size_t)blockIdx.z * sA;
    B += (size_t)blockIdx.z * sB;
    C += (size_t)blockIdx.z * sC;

    int bm = blockIdx.y * BM;
    int bn = blockIdx.x * BN;
    int tid = threadIdx.x;
    int tx = tid % (BN/TN);
    int ty = tid / (BN/TN);

    float acc[TM][TN];
    #pragma unroll
    for (int i = 0; i < TM; i++)
        #pragma unroll
        for (int j = 0; j < TN; j++) acc[i][j] = 0.f;

    for (int k0 = 0; k0 < K; k0 += BK) {
        #pragma unroll
        for (int i = tid; i < BM*BK/4; i += THREADS) {
            int r = i / (BK/4), c4 = i % (BK/4);
            float4 v = *(const float4*)&A[(size_t)(bm+r)*lda + k0 + c4*4];
            As[c4*4+0][r] = v.x; As[c4*4+1][r] = v.y;
            As[c4*4+2][r] = v.z; As[c4*4+3][r] = v.w;
        }
        #pragma unroll
        for (int i = tid; i < BN*BK/4; i += THREADS) {
            int r = i / (BK/4), c4 = i % (BK/4);
            float4 v = *(const float4*)&B[(size_t)(bn+r)*ldb + k0 + c4*4];
            Bs[c4*4+0][r] = v.x; Bs[c4*4+1][r] = v.y;
            Bs[c4*4+2][r] = v.z; Bs[c4*4+3][r] = v.w;
        }
        __syncthreads();
        #pragma unroll
        for (int kk = 0; kk < BK; kk++) {
            float a[TM], b[TN];
            #pragma unroll
            for (int i = 0; i < TM; i++) a[i] = As[kk][ty*TM + i];
            #pragma unroll
            for (int j = 0; j < TN; j++) b[j] = Bs[kk][tx*TN + j];
            #pragma unroll
            for (int i = 0; i < TM; i++)
                #pragma unroll
                for (int j = 0; j < TN; j++) acc[i][j] += a[i]*b[j];
        }
        __syncthreads();
    }

    #pragma unroll
    for (int i = 0; i < TM; i++) {
        int m = bm + ty*TM + i;
        #pragma unroll
        for (int j = 0; j < TN; j++) {
            int n = bn + tx*TN + j;
            float v = acc[i][j];
            if (bias) v += bias[n];
            if (act == 1) v = tanhf(v);
            C[(size_t)m*ldc + n] = v;
        }
    }
}

// ---------------- GRU math ----------------
__device__ __forceinline__ float sigm(float x) { return 1.f / (1.f + expf(-x)); }

// ============ FUSED: masked-mean gather (projected space) + GRU step 1 ============
// Block = (u, t), 256 threads; thread j owns gate triple (j, j+256, j+512).
// Eliminates the g_f1/g_b1 round-trip (write+read of 2x 50MB) and one launch.
__global__ __launch_bounds__(256)
void gather_gru1_kernel(const int* __restrict__ col_idx, const int* __restrict__ col_mask,
                        const int* __restrict__ tab_idx, const int* __restrict__ tab_mask,
                        const float* __restrict__ bih_f, const float* __restrict__ bhh_f,
                        const float* __restrict__ bih_b, const float* __restrict__ bhh_b)
{
    int u = blockIdx.x, t = blockIdx.y;
    int j = threadIdx.x;
    const float* Pf = d_Pf + (size_t)t * DB_ * G3_;
    const float* Pb = d_Pb + (size_t)t * DB_ * G3_;

    // tab means: (Pf -> gi for f1), (Pb -> gi for b2)
    float tf_r=0.f, tf_z=0.f, tf_n=0.f, tb_r=0.f, tb_z=0.f, tb_n=0.f, cnt_t=0.f;
    #pragma unroll
    for (int m = 0; m < MT_; m++) {
        if (tab_mask[u*MT_+m]) {
            int id = tab_idx[u*MT_+m];
            const float* pf = Pf + (size_t)id * G3_;
            const float* pb = Pb + (size_t)id * G3_;
            tf_r += pf[j]; tf_z += pf[Hh_+j]; tf_n += pf[2*Hh_+j];
            tb_r += pb[j]; tb_z += pb[Hh_+j]; tb_n += pb[2*Hh_+j];
            cnt_t += 1.f;
        }
    }
    // col means: (Pf -> gi for f2), (Pb -> gi for b1)
    float cf_r=0.f, cf_z=0.f, cf_n=0.f, cb_r=0.f, cb_z=0.f, cb_n=0.f, cnt_c=0.f;
    #pragma unroll
    for (int m = 0; m < MC_; m++) {
        if (col_mask[u*MC_+m]) {
            int id = col_idx[u*MC_+m];
            const float* pf = Pf + (size_t)id * G3_;
            const float* pb = Pb + (size_t)id * G3_;
            cf_r += pf[j]; cf_z += pf[Hh_+j]; cf_n += pf[2*Hh_+j];
            cb_r += pb[j]; cb_z += pb[Hh_+j]; cb_n += pb[2*Hh_+j];
            cnt_c += 1.f;
        }
    }
    float it = 1.f / fmaxf(cnt_t, 1.f);
    float ic = 1.f / fmaxf(cnt_c, 1.f);
    size_t row = (size_t)t * U_ + u;

    // store gi's needed by GRU step 2
    d_g_f2[row*G3_ + j]         = cf_r * ic;
    d_g_f2[row*G3_ + Hh_ + j]   = cf_z * ic;
    d_g_f2[row*G3_ + 2*Hh_ + j] = cf_n * ic;
    d_g_b2[row*G3_ + j]         = tb_r * it;
    d_g_b2[row*G3_ + Hh_ + j]   = tb_z * it;
    d_g_b2[row*G3_ + 2*Hh_ + j] = tb_n * it;

    // f1 = GRUCell_f(x1 = tab-mean, h = 0)
    {
        float r = sigm(tf_r*it + bih_f[j]       + bhh_f[j]);
        float z = sigm(tf_z*it + bih_f[Hh_+j]   + bhh_f[Hh_+j]);
        float n = tanhf(tf_n*it + bih_f[2*Hh_+j] + r * bhh_f[2*Hh_+j]);
        float v = (1.f - z) * n;
        d_f1[row*Hh_ + j] = v;
        __nv_bfloat16 h = __float2bfloat16(v);
        __nv_bfloat16 l = __float2bfloat16(v - __bfloat162float(h));
        d_f1S[row*G3_ + j] = h; d_f1S[row*G3_ + Hh_ + j] = l; d_f1S[row*G3_ + 2*Hh_ + j] = h;
    }
    // b1 = GRUCell_b(x2 = col-mean, h = 0)
    {
        float r = sigm(cb_r*ic + bih_b[j]       + bhh_b[j]);
        float z = sigm(cb_z*ic + bih_b[Hh_+j]   + bhh_b[Hh_+j]);
        float n = tanhf(cb_n*ic + bih_b[2*Hh_+j] + r * bhh_b[2*Hh_+j]);
        float v = (1.f - z) * n;
        d_b1[row*Hh_ + j] = v;
        __nv_bfloat16 h = __float2bfloat16(v);
        __nv_bfloat16 l = __float2bfloat16(v - __bfloat162float(h));
        d_b1S[row*G3_ + j] = h; d_b1S[row*G3_ + Hh_ + j] = l; d_b1S[row*G3_ + 2*Hh_ + j] = h;
    }
}

// second steps + db_emb + FUSED masked logit (key . db_row).
__global__ __launch_bounds__(256)
void gru_second_kernel(const float* __restrict__ bih_f, const float* __restrict__ bhh_f,
                       const float* __restrict__ bih_b, const float* __restrict__ bhh_b,
                       const float* __restrict__ key, const int* __restrict__ attn_mask)
{
    int row = blockIdx.x;                 // 0..TU_-1
    int j   = threadIdx.x;                // 0..255
    int idx = row * Hh_ + j;
    int t   = row >> 10;                  // row / U_
    float db0, db1;
    {
        const float* gi = d_g_f2 + (size_t)row * G3_;
        const float* gh = d_gh_f + (size_t)row * G3_;
        float h  = d_f1[idx];
        float r = sigm(gi[j]       + bih_f[j]       + gh[j]       + bhh_f[j]);
        float z = sigm(gi[Hh_+j]   + bih_f[Hh_+j]   + gh[Hh_+j]   + bhh_f[Hh_+j]);
        float n = tanhf(gi[2*Hh_+j] + bih_f[2*Hh_+j] + r * (gh[2*Hh_+j] + bhh_f[2*Hh_+j]));
        float f2 = (1.f - z) * n + z * h;
        db0 = 0.5f * (h + f2);
        d_db[(size_t)row*H_ + j] = db0;
    }
    {
        const float* gi = d_g_b2 + (size_t)row * G3_;
        const float* gh = d_gh_b + (size_t)row * G3_;
        float h  = d_b1[idx];
        float r = sigm(gi[j]       + bih_b[j]       + gh[j]       + bhh_b[j]);
        float z = sigm(gi[Hh_+j]   + bih_b[Hh_+j]   + gh[Hh_+j]   + bhh_b[Hh_+j]);
        float n = tanhf(gi[2*Hh_+j] + bih_b[2*Hh_+j] + r * (gh[2*Hh_+j] + bhh_b[2*Hh_+j]));
        float b2 = (1.f - z) * n + z * h;
        db1 = 0.5f * (h + b2);
        d_db[(size_t)row*H_ + Hh_ + j] = db1;
    }
    // fused logit: sum_j key[t][j]*db0 + key[t][Hh+j]*db1
    float part = key[(size_t)t*H_ + j] * db0 + key[(size_t)t*H_ + Hh_ + j] * db1;
    #pragma unroll
    for (int s = 16; s > 0; s >>= 1) part += __shfl_xor_sync(0xFFFFFFFFu, part, s);
    __shared__ float wsum[8];
    if ((j & 31) == 0) wsum[j >> 5] = part;
    __syncthreads();
    if (j == 0) {
        float acc = 0.f;
        #pragma unroll
        for (int w = 0; w < 8; w++) acc += wsum[w];
        d_logits[row] = attn_mask[row] ? acc : -1e9f;
    }
}

// ---------------- attention ----------------
__global__ void softmax_kernel()
{
    int t = blockIdx.x;
    __shared__ float red[256];
    int tid = threadIdx.x;
    float mx = -INFINITY;
    for (int u = tid; u < U_; u += 256) mx = fmaxf(mx, d_logits[t*U_+u]);
    red[tid] = mx; __syncthreads();
    for (int s = 128; s > 0; s >>= 1) { if (tid < s) red[tid] = fmaxf(red[tid], red[tid+s]); __syncthreads(); }
    mx = red[0]; __syncthreads();
    float sum = 0.f;
    for (int u = tid; u < U_; u += 256) sum += expf(d_logits[t*U_+u] - mx);
    red[tid] = sum; __syncthreads();
    for (int s = 128; s > 0; s >>= 1) { if (tid < s) red[tid] += red[tid+s]; __syncthreads(); }
    sum = red[0];
    float inv = 1.f / sum;
    for (int u = tid; u < U_; u += 256) d_wsm[t*U_+u] = expf(d_logits[t*U_+u] - mx) * inv;
}

// attention value: split U into 8 chunks of 128 (128 blocks) + reduce
__global__ void attn_part_kernel()
{
    int chunk = blockIdx.x, t = blockIdx.y;
    int h = threadIdx.x;                 // 512 threads
    __shared__ float ws[128];
    if (h < 128) ws[h] = d_wsm[t*U_ + chunk*128 + h];
    __syncthreads();
    float acc = 0.f;
    const float* d = d_db + ((size_t)t*U_ + chunk*128) * H_ + h;
    #pragma unroll 4
    for (int u = 0; u < 128; u++) acc += ws[u] * d[(size_t)u*H_];
    d_attnp[((size_t)t*8 + chunk)*H_ + h] = acc;
}

__global__ void attn_reduce_kernel()
{
    int t = blockIdx.x;
    int h = threadIdx.x;                 // 512
    float acc = 0.f;
    #pragma unroll
    for (int c = 0; c < 8; c++) acc += d_attnp[((size_t)t*8 + c)*H_ + h];
    d_attnv[t*H_ + h] = acc;
}

__global__ void add_attn_kernel(const float* __restrict__ final_feature)
{
    int idx = blockIdx.x * blockDim.x + threadIdx.x;   // T_*L_*H_
    int h = idx & (H_-1);
    int t = idx >> 15;
    d_ffin[idx] = final_feature[idx] + d_attnv[t*H_ + h];
}

// ---------------- final log-softmax ----------------
__global__ void logsoftmax_kernel(float* __restrict__ out)
{
    int r = blockIdx.x;
    int tid = threadIdx.x;
    __shared__ float red[256];
    const float* x = d_probs + (size_t)r * OUTC_;
    float mx = -INFINITY;
    for (int c = tid; c < OUTC_; c += 256) mx = fmaxf(mx, x[c]);
    red[tid] = mx; __syncthreads();
    for (int s = 128; s > 0; s >>= 1) { if (tid < s) red[tid] = fmaxf(red[tid], red[tid+s]); __syncthreads(); }
    mx = red[0]; __syncthreads();
    float sum = 0.f;
    for (int c = tid; c < OUTC_; c += 256) sum += expf(x[c] - mx);
    red[tid] = sum; __syncthreads();
    for (int s = 128; s > 0; s >>= 1) { if (tid < s) red[tid] += red[tid+s]; __syncthreads(); }
    float lse = mx + logf(red[0]);
    for (int c = tid; c < OUTC_; c += 256) out[(size_t)r*OUTC_ + c] = x[c] - lse;
}

// ---------------- host launcher ----------------
#define SYM(p, t, s) do { void* _t; cudaGetSymbolAddress(&_t, s); (p) = (t*)_t; } while (0)

extern "C" void kernel_launch(void* const* d_in, const int* in_sizes, int n_in,
                              void* d_out, int out_size)
{
    const float* feat          = (const float*)d_in[0];
    const float* key           = (const float*)d_in[1];
    const float* final_feature = (const float*)d_in[2];
    const float* Wih_f         = (const float*)d_in[3];
    const float* Whh_f         = (const float*)d_in[4];
    const float* bih_f         = (const float*)d_in[5];
    const float* bhh_f         = (const float*)d_in[6];
    const float* Wih_b         = (const float*)d_in[7];
    const float* Whh_b         = (const float*)d_in[8];
    const float* bih_b         = (const float*)d_in[9];
    const float* bhh_b         = (const float*)d_in[10];
    const float* Wb            = (const float*)d_in[11];
    const float* bb            = (const float*)d_in[12];
    const float* Kemb          = (const float*)d_in[13];
    const int*   col_idx       = (const int*)d_in[14];
    const int*   col_mask      = (const int*)d_in[15];
    const int*   tab_idx       = (const int*)d_in[16];
    const int*   tab_mask      = (const int*)d_in[17];
    const int*   attn_mask     = (const int*)d_in[18];
    float* out = (float*)d_out;

    float *Pf, *Pb, *gh_f, *gh_b, *db, *ffin, *ff, *probs;
    __nv_bfloat16 *featS, *WihfS, *WihbS, *WhhfS, *WhhbS, *f1S, *b1S;
    SYM(Pf, float, d_Pf);   SYM(Pb, float, d_Pb);
    SYM(gh_f, float, d_gh_f); SYM(gh_b, float, d_gh_b);
    SYM(db, float, d_db);   SYM(ffin, float, d_ffin); SYM(ff, float, d_ff); SYM(probs, float, d_probs);
    SYM(featS, __nv_bfloat16, d_featS);
    SYM(WihfS, __nv_bfloat16, d_WihfS); SYM(WihbS, __nv_bfloat16, d_WihbS);
    SYM(WhhfS, __nv_bfloat16, d_WhhfS); SYM(WhhbS, __nv_bfloat16, d_WhhbS);
    SYM(f1S, __nv_bfloat16, d_f1S);     SYM(b1S, __nv_bfloat16, d_b1S);

    // 0) split-bf16 conversions
    split_bf16_kernel<<<(TDB_*H_+255)/256, 256>>>(feat,  featS, TDB_*H_, H_, 0);
    split_bf16_kernel<<<(G3_*H_+255)/256, 256>>>(Wih_f, WihfS, G3_*H_, H_, 1);
    split_bf16_kernel<<<(G3_*H_+255)/256, 256>>>(Wih_b, WihbS, G3_*H_, H_, 1);
    split_bf16_kernel<<<(G3_*Hh_+255)/256, 256>>>(Whh_f, WhhfS, G3_*Hh_, Hh_, 1);
    split_bf16_kernel<<<(G3_*Hh_+255)/256, 256>>>(Whh_b, WhhbS, G3_*Hh_, Hh_, 1);

    // 1) projection GEMMs (HMMA, pipelined): P = feat @ Wih^T  (8192 x 768, K'=1536)
    {
        dim3 grid(G3_/128, TDB_/128);
        gemm_wmma<<<grid, 256>>>(featS, WihfS, Pf, TDB_, G3_, 3*H_, G3_);
        gemm_wmma<<<grid, 256>>>(featS, WihbS, Pb, TDB_, G3_, 3*H_, G3_);
    }

    // 2+3) FUSED masked-mean gather + GRU step 1
    gather_gru1_kernel<<<dim3(U_, T_), 256>>>(col_idx, col_mask, tab_idx, tab_mask,
                                              bih_f, bhh_f, bih_b, bhh_b);

    // 4) hidden-projection GEMMs (HMMA, pipelined): (16384 x 768, K'=768)
    {
        dim3 grid(G3_/128, TU_/128);
        gemm_wmma<<<grid, 256>>>(f1S, WhhfS, gh_f, TU_, G3_, 3*Hh_, G3_);
        gemm_wmma<<<grid, 256>>>(b1S, WhhbS, gh_b, TU_, G3_, 3*Hh_, G3_);
    }

    // 5) second GRU steps + db_emb + fused logits
    gru_second_kernel<<<TU_, 256>>>(bih_f, bhh_f, bih_b, bhh_b, key, attn_mask);

    // 6) attention
    softmax_kernel<<<T_, 256>>>();
    attn_part_kernel<<<dim3(8, T_), 512>>>();
    attn_reduce_kernel<<<T_, 512>>>();

    // 7) feature + attn, then ff = tanh(ffin @ Wb^T + bb)
    add_attn_kernel<<<T_*L_*H_/256, 256>>>(final_feature);
    {
        dim3 grid(H_/128, T_*L_/128, 1);
        sgemm_nt<128,128,16,8,8><<<grid, 256>>>(ffin, Wb, bb, ff, T_*L_, H_, H_, H_, H_, H_, 0,0,0, 1);
    }

    // 8) db_prob: per-t (64 x 1024) = ff[t] (64x512) @ db_emb[t] (1024x512)^T
    {
        dim3 grid(U_/128, L_/64, T_);
        sgemm_nt<64,128,16,4,8><<<grid, 256>>>(ff, db, nullptr, probs,
            L_, U_, H_, H_, H_, OUTC_,
            (long long)L_*H_, (long long)U_*H_, (long long)L_*OUTC_, 0);
    }
    // 9) kw_prob: (1024 x 64) = ff @ Kemb^T, at column offset U_
    {
        dim3 grid(K_/64, T_*L_/64, 1);
        sgemm_nt<64,64,16,4,4><<<grid, 256>>>(ff, Kemb, nullptr, probs + U_,
            T_*L_, K_, H_, H_, H_, OUTC_, 0,0,0, 0);
    }

    // 10) log-softmax over last dim (1088) -> output
    logsoftmax_kernel<<<T_*L_, 256>>>(out);
}

// round 15
// speedup vs baseline: 1.4520x; 1.0320x over previous
#include <cuda_runtime.h>
#include <cuda_bf16.h>
#include <mma.h>
#include <math.h>
#include <stdint.h>

using namespace nvcuda;

// Problem constants
#define T_  16
#define DB_ 512
#define H_  512
#define U_  1024
#define MC_ 8
#define MT_ 4
#define L_  64
#define K_  64
#define Hh_ 256
#define G3_ (3*Hh_)     // 768
#define TU_ (T_*U_)     // 16384
#define TDB_ (T_*DB_)   // 8192
#define OUTC_ (U_+K_)   // 1088

// ---------------- scratch (device globals; no allocs allowed) ----------------
__device__ float d_Pf[TDB_*G3_];      // feat @ Wih_f^T   (8192 x 768)
__device__ float d_Pb[TDB_*G3_];      // feat @ Wih_b^T
__device__ float d_g_f2[TU_*G3_];     // col-mean of Pf  (gi for f2)
__device__ float d_g_b2[TU_*G3_];     // tab-mean of Pb  (gi for b2)
__device__ float d_f1[TU_*Hh_];
__device__ float d_b1[TU_*Hh_];
__device__ float d_gh_f[TU_*G3_];     // f1@Whh_f^T (raw, bhh added in gru_second)
__device__ float d_gh_b[TU_*G3_];
__device__ float d_db[TU_*H_];        // db_emb
__device__ float d_logits[T_*U_];
__device__ float d_wsm[T_*U_];
__device__ float d_attnp[T_*8*H_];    // attention partials (8 U-chunks)
__device__ float d_attnv[T_*H_];
__device__ float d_ffin[T_*L_*H_];
__device__ float d_ff[T_*L_*H_];
__device__ float d_probs[T_*L_*OUTC_];

// split-bf16 operand buffers ([hi|lo|hi] A-side, [hi|hi|lo] B-side)
__device__ __nv_bfloat16 d_featS[TDB_*3*H_];   // 8192 x 1536
__device__ __nv_bfloat16 d_WihfS[G3_*3*H_];
__device__ __nv_bfloat16 d_WihbS[G3_*3*H_];
__device__ __nv_bfloat16 d_WhhfS[G3_*3*Hh_];
__device__ __nv_bfloat16 d_WhhbS[G3_*3*Hh_];
__device__ __nv_bfloat16 d_f1S[TU_*3*Hh_];
__device__ __nv_bfloat16 d_b1S[TU_*3*Hh_];

// ================= cp.async helpers =================
__device__ __forceinline__ void cp_async16(void* smem_ptr, const void* gptr) {
    uint32_t s = (uint32_t)__cvta_generic_to_shared(smem_ptr);
    asm volatile("cp.async.cg.shared.global [%0], [%1], 16;" :: "r"(s), "l"(gptr));
}
__device__ __forceinline__ void cp_commit() { asm volatile("cp.async.commit_group;" ::: "memory"); }
__device__ __forceinline__ void cp_wait1()  { asm volatile("cp.async.wait_group 1;" ::: "memory"); }
__device__ __forceinline__ void cp_wait0()  { asm volatile("cp.async.wait_group 0;" ::: "memory"); }

// ================= WMMA bf16 GEMM — double-buffered cp.async, WPAD=48 =================
// BATCHED over blockIdx.z: z=0 -> (A0,B0,C0), z=1 -> (A1,B1,C1). Body identical to R12.
#define WBK 32
#define WPAD 48   // smem leading dim (elements): 96B rows (32B-aligned, %8==0)

__global__ __launch_bounds__(256)
void gemm_wmma2(const __nv_bfloat16* __restrict__ A0, const __nv_bfloat16* __restrict__ B0,
                float* __restrict__ C0,
                const __nv_bfloat16* __restrict__ A1, const __nv_bfloat16* __restrict__ B1,
                float* __restrict__ C1,
                int M, int N, int K3, int ldc)
{
    __shared__ __nv_bfloat16 As[2][128 * WPAD];   // 24 KB
    __shared__ __nv_bfloat16 Bs[2][128 * WPAD];   // 24 KB

    const __nv_bfloat16* A = blockIdx.z ? A1 : A0;
    const __nv_bfloat16* B = blockIdx.z ? B1 : B0;
    float*               C = blockIdx.z ? C1 : C0;

    int tid  = threadIdx.x;
    int warp = tid >> 5;
    int wm = warp >> 2;          // 0..1 : 64-row slab
    int wn = warp & 3;           // 0..3 : 32-col slab
    int bm = blockIdx.y * 128;
    int bn = blockIdx.x * 128;

    wmma::fragment<wmma::accumulator, 16, 16, 16, float> acc[4][2];
    #pragma unroll
    for (int i = 0; i < 4; i++)
        #pragma unroll
        for (int j = 0; j < 2; j++) wmma::fill_fragment(acc[i][j], 0.0f);

    const int nch = K3 / WBK;

    auto load_stage = [&](int s, int k0) {
        #pragma unroll
        for (int i = tid; i < 512; i += 256) {
            int r = i >> 2, c = i & 3;
            cp_async16(&As[s][r * WPAD + c * 8], A + (size_t)(bm + r) * K3 + k0 + c * 8);
        }
        #pragma unroll
        for (int i = tid; i < 512; i += 256) {
            int r = i >> 2, c = i & 3;
            cp_async16(&Bs[s][r * WPAD + c * 8], B + (size_t)(bn + r) * K3 + k0 + c * 8);
        }
        cp_commit();
    };

    load_stage(0, 0);

    for (int c = 0; c < nch; c++) {
        if (c + 1 < nch) { load_stage((c + 1) & 1, (c + 1) * WBK); cp_wait1(); }
        else             { cp_wait0(); }
        __syncthreads();

        int s = c & 1;
        #pragma unroll
        for (int kk = 0; kk < WBK; kk += 16) {
            wmma::fragment<wmma::matrix_a, 16, 16, 16, __nv_bfloat16, wmma::row_major> fa[4];
            wmma::fragment<wmma::matrix_b, 16, 16, 16, __nv_bfloat16, wmma::col_major> fb[2];
            #pragma unroll
            for (int i = 0; i < 4; i++)
                wmma::load_matrix_sync(fa[i], &As[s][(wm * 64 + i * 16) * WPAD + kk], WPAD);
            #pragma unroll
            for (int j = 0; j < 2; j++)
                wmma::load_matrix_sync(fb[j], &Bs[s][(wn * 32 + j * 16) * WPAD + kk], WPAD);
            #pragma unroll
            for (int i = 0; i < 4; i++)
                #pragma unroll
                for (int j = 0; j < 2; j++)
                    wmma::mma_sync(acc[i][j], fa[i], fb[j], acc[i][j]);
        }
        __syncthreads();
    }

    #pragma unroll
    for (int i = 0; i < 4; i++)
        #pragma unroll
        for (int j = 0; j < 2; j++) {
            int m0 = bm + wm * 64 + i * 16;
            int n0 = bn + wn * 32 + j * 16;
            wmma::store_matrix_sync(C + (size_t)m0 * ldc + n0, acc[i][j], ldc, wmma::mem_row_major);
        }
}

// ================= split-bf16 conversion =================
// orderB=0: [hi|lo|hi] (A-side) ; orderB=1: [hi|hi|lo] (B-side)
__global__ void split_bf16_kernel(const float* __restrict__ X, __nv_bfloat16* __restrict__ Y,
                                  int n, int Kd, int orderB)
{
    int idx = blockIdx.x * blockDim.x + threadIdx.x;
    if (idx >= n) return;
    float x = X[idx];
    __nv_bfloat16 h = __float2bfloat16(x);
    __nv_bfloat16 l = __float2bfloat16(x - __bfloat162float(h));
    int r = idx / Kd, k = idx - r * Kd;
    size_t bse = (size_t)r * 3 * Kd;
    if (orderB) { Y[bse + k] = h; Y[bse + Kd + k] = h; Y[bse + 2*Kd + k] = l; }
    else        { Y[bse + k] = h; Y[bse + Kd + k] = l; Y[bse + 2*Kd + k] = h; }
}

// ---------------- scalar-FFMA SGEMM (small tail GEMMs) ----------------
template<int BM, int BN, int BK, int TM, int TN>
__global__ void sgemm_nt(const float* __restrict__ A, const float* __restrict__ B,
                         const float* __restrict__ bias, float* __restrict__ C,
                         int M, int N, int K, int lda, int ldb, int ldc,
                         long long sA, long long sB, long long sC, int act)
{
    constexpr int THREADS = (BM/TM) * (BN/TN);
    __shared__ float As[BK][BM];
    __shared__ float Bs[BK][BN];

    A += (size_t)blockIdx.z * sA;
    B += (size_t)blockIdx.z * sB;
    C += (size_t)blockIdx.z * sC;

    int bm = blockIdx.y * BM;
    int bn = blockIdx.x * BN;
    int tid = threadIdx.x;
    int tx = tid % (BN/TN);
    int ty = tid / (BN/TN);

    float acc[TM][TN];
    #pragma unroll
    for (int i = 0; i < TM; i++)
        #pragma unroll
        for (int j = 0; j < TN; j++) acc[i][j] = 0.f;

    for (int k0 = 0; k0 < K; k0 += BK) {
        #pragma unroll
        for (int i = tid; i < BM*BK/4; i += THREADS) {
            int r = i / (BK/4), c4 = i % (BK/4);
            float4 v = *(const float4*)&A[(size_t)(bm+r)*lda + k0 + c4*4];
            As[c4*4+0][r] = v.x; As[c4*4+1][r] = v.y;
            As[c4*4+2][r] = v.z; As[c4*4+3][r] = v.w;
        }
        #pragma unroll
        for (int i = tid; i < BN*BK/4; i += THREADS) {
            int r = i / (BK/4), c4 = i % (BK/4);
            float4 v = *(const float4*)&B[(size_t)(bn+r)*ldb + k0 + c4*4];
            Bs[c4*4+0][r] = v.x; Bs[c4*4+1][r] = v.y;
            Bs[c4*4+2][r] = v.z; Bs[c4*4+3][r] = v.w;
        }
        __syncthreads();
        #pragma unroll
        for (int kk = 0; kk < BK; kk++) {
            float a[TM], b[TN];
            #pragma unroll
            for (int i = 0; i < TM; i++) a[i] = As[kk][ty*TM + i];
            #pragma unroll
            for (int j = 0; j < TN; j++) b[j] = Bs[kk][tx*TN + j];
            #pragma unroll
            for (int i = 0; i < TM; i++)
                #pragma unroll
                for (int j = 0; j < TN; j++) acc[i][j] += a[i]*b[j];
        }
        __syncthreads();
    }

    #pragma unroll
    for (int i = 0; i < TM; i++) {
        int m = bm + ty*TM + i;
        #pragma unroll
        for (int j = 0; j < TN; j++) {
            int n = bn + tx*TN + j;
            float v = acc[i][j];
            if (bias) v += bias[n];
            if (act == 1) v = tanhf(v);
            C[(size_t)m*ldc + n] = v;
        }
    }
}

// ---------------- GRU math ----------------
__device__ __forceinline__ float sigm(float x) { return 1.f / (1.f + expf(-x)); }

// ============ FUSED: masked-mean gather (projected space) + GRU step 1 ============
__global__ __launch_bounds__(256)
void gather_gru1_kernel(const int* __restrict__ col_idx, const int* __restrict__ col_mask,
                        const int* __restrict__ tab_idx, const int* __restrict__ tab_mask,
                        const float* __restrict__ bih_f, const float* __restrict__ bhh_f,
                        const float* __restrict__ bih_b, const float* __restrict__ bhh_b)
{
    int u = blockIdx.x, t = blockIdx.y;
    int j = threadIdx.x;
    const float* Pf = d_Pf + (size_t)t * DB_ * G3_;
    const float* Pb = d_Pb + (size_t)t * DB_ * G3_;

    // tab means: (Pf -> gi for f1), (Pb -> gi for b2)
    float tf_r=0.f, tf_z=0.f, tf_n=0.f, tb_r=0.f, tb_z=0.f, tb_n=0.f, cnt_t=0.f;
    #pragma unroll
    for (int m = 0; m < MT_; m++) {
        if (tab_mask[u*MT_+m]) {
            int id = tab_idx[u*MT_+m];
            const float* pf = Pf + (size_t)id * G3_;
            const float* pb = Pb + (size_t)id * G3_;
            tf_r += pf[j]; tf_z += pf[Hh_+j]; tf_n += pf[2*Hh_+j];
            tb_r += pb[j]; tb_z += pb[Hh_+j]; tb_n += pb[2*Hh_+j];
            cnt_t += 1.f;
        }
    }
    // col means: (Pf -> gi for f2), (Pb -> gi for b1)
    float cf_r=0.f, cf_z=0.f, cf_n=0.f, cb_r=0.f, cb_z=0.f, cb_n=0.f, cnt_c=0.f;
    #pragma unroll
    for (int m = 0; m < MC_; m++) {
        if (col_mask[u*MC_+m]) {
            int id = col_idx[u*MC_+m];
            const float* pf = Pf + (size_t)id * G3_;
            const float* pb = Pb + (size_t)id * G3_;
            cf_r += pf[j]; cf_z += pf[Hh_+j]; cf_n += pf[2*Hh_+j];
            cb_r += pb[j]; cb_z += pb[Hh_+j]; cb_n += pb[2*Hh_+j];
            cnt_c += 1.f;
        }
    }
    float it = 1.f / fmaxf(cnt_t, 1.f);
    float ic = 1.f / fmaxf(cnt_c, 1.f);
    size_t row = (size_t)t * U_ + u;

    // store gi's needed by GRU step 2
    d_g_f2[row*G3_ + j]         = cf_r * ic;
    d_g_f2[row*G3_ + Hh_ + j]   = cf_z * ic;
    d_g_f2[row*G3_ + 2*Hh_ + j] = cf_n * ic;
    d_g_b2[row*G3_ + j]         = tb_r * it;
    d_g_b2[row*G3_ + Hh_ + j]   = tb_z * it;
    d_g_b2[row*G3_ + 2*Hh_ + j] = tb_n * it;

    // f1 = GRUCell_f(x1 = tab-mean, h = 0)
    {
        float r = sigm(tf_r*it + bih_f[j]       + bhh_f[j]);
        float z = sigm(tf_z*it + bih_f[Hh_+j]   + bhh_f[Hh_+j]);
        float n = tanhf(tf_n*it + bih_f[2*Hh_+j] + r * bhh_f[2*Hh_+j]);
        float v = (1.f - z) * n;
        d_f1[row*Hh_ + j] = v;
        __nv_bfloat16 h = __float2bfloat16(v);
        __nv_bfloat16 l = __float2bfloat16(v - __bfloat162float(h));
        d_f1S[row*G3_ + j] = h; d_f1S[row*G3_ + Hh_ + j] = l; d_f1S[row*G3_ + 2*Hh_ + j] = h;
    }
    // b1 = GRUCell_b(x2 = col-mean, h = 0)
    {
        float r = sigm(cb_r*ic + bih_b[j]       + bhh_b[j]);
        float z = sigm(cb_z*ic + bih_b[Hh_+j]   + bhh_b[Hh_+j]);
        float n = tanhf(cb_n*ic + bih_b[2*Hh_+j] + r * bhh_b[2*Hh_+j]);
        float v = (1.f - z) * n;
        d_b1[row*Hh_ + j] = v;
        __nv_bfloat16 h = __float2bfloat16(v);
        __nv_bfloat16 l = __float2bfloat16(v - __bfloat162float(h));
        d_b1S[row*G3_ + j] = h; d_b1S[row*G3_ + Hh_ + j] = l; d_b1S[row*G3_ + 2*Hh_ + j] = h;
    }
}

// second steps + db_emb + FUSED masked logit (key . db_row).
__global__ __launch_bounds__(256)
void gru_second_kernel(const float* __restrict__ bih_f, const float* __restrict__ bhh_f,
                       const float* __restrict__ bih_b, const float* __restrict__ bhh_b,
                       const float* __restrict__ key, const int* __restrict__ attn_mask)
{
    int row = blockIdx.x;                 // 0..TU_-1
    int j   = threadIdx.x;                // 0..255
    int idx = row * Hh_ + j;
    int t   = row >> 10;                  // row / U_
    float db0, db1;
    {
        const float* gi = d_g_f2 + (size_t)row * G3_;
        const float* gh = d_gh_f + (size_t)row * G3_;
        float h  = d_f1[idx];
        float r = sigm(gi[j]       + bih_f[j]       + gh[j]       + bhh_f[j]);
        float z = sigm(gi[Hh_+j]   + bih_f[Hh_+j]   + gh[Hh_+j]   + bhh_f[Hh_+j]);
        float n = tanhf(gi[2*Hh_+j] + bih_f[2*Hh_+j] + r * (gh[2*Hh_+j] + bhh_f[2*Hh_+j]));
        float f2 = (1.f - z) * n + z * h;
        db0 = 0.5f * (h + f2);
        d_db[(size_t)row*H_ + j] = db0;
    }
    {
        const float* gi = d_g_b2 + (size_t)row * G3_;
        const float* gh = d_gh_b + (size_t)row * G3_;
        float h  = d_b1[idx];
        float r = sigm(gi[j]       + bih_b[j]       + gh[j]       + bhh_b[j]);
        float z = sigm(gi[Hh_+j]   + bih_b[Hh_+j]   + gh[Hh_+j]   + bhh_b[Hh_+j]);
        float n = tanhf(gi[2*Hh_+j] + bih_b[2*Hh_+j] + r * (gh[2*Hh_+j] + bhh_b[2*Hh_+j]));
        float b2 = (1.f - z) * n + z * h;
        db1 = 0.5f * (h + b2);
        d_db[(size_t)row*H_ + Hh_ + j] = db1;
    }
    // fused logit: sum_j key[t][j]*db0 + key[t][Hh+j]*db1
    float part = key[(size_t)t*H_ + j] * db0 + key[(size_t)t*H_ + Hh_ + j] * db1;
    #pragma unroll
    for (int s = 16; s > 0; s >>= 1) part += __shfl_xor_sync(0xFFFFFFFFu, part, s);
    __shared__ float wsum[8];
    if ((j & 31) == 0) wsum[j >> 5] = part;
    __syncthreads();
    if (j == 0) {
        float acc = 0.f;
        #pragma unroll
        for (int w = 0; w < 8; w++) acc += wsum[w];
        d_logits[row] = attn_mask[row] ? acc : -1e9f;
    }
}

// ---------------- attention ----------------
__global__ void softmax_kernel()
{
    int t = blockIdx.x;
    __shared__ float red[256];
    int tid = threadIdx.x;
    float mx = -INFINITY;
    for (int u = tid; u < U_; u += 256) mx = fmaxf(mx, d_logits[t*U_+u]);
    red[tid] = mx; __syncthreads();
    for (int s = 128; s > 0; s >>= 1) { if (tid < s) red[tid] = fmaxf(red[tid], red[tid+s]); __syncthreads(); }
    mx = red[0]; __syncthreads();
    float sum = 0.f;
    for (int u = tid; u < U_; u += 256) sum += expf(d_logits[t*U_+u] - mx);
    red[tid] = sum; __syncthreads();
    for (int s = 128; s > 0; s >>= 1) { if (tid < s) red[tid] += red[tid+s]; __syncthreads(); }
    sum = red[0];
    float inv = 1.f / sum;
    for (int u = tid; u < U_; u += 256) d_wsm[t*U_+u] = expf(d_logits[t*U_+u] - mx) * inv;
}

// attention value: split U into 8 chunks of 128 (128 blocks) + reduce
__global__ void attn_part_kernel()
{
    int chunk = blockIdx.x, t = blockIdx.y;
    int h = threadIdx.x;                 // 512 threads
    __shared__ float ws[128];
    if (h < 128) ws[h] = d_wsm[t*U_ + chunk*128 + h];
    __syncthreads();
    float acc = 0.f;
    const float* d = d_db + ((size_t)t*U_ + chunk*128) * H_ + h;
    #pragma unroll 4
    for (int u = 0; u < 128; u++) acc += ws[u] * d[(size_t)u*H_];
    d_attnp[((size_t)t*8 + chunk)*H_ + h] = acc;
}

__global__ void attn_reduce_kernel()
{
    int t = blockIdx.x;
    int h = threadIdx.x;                 // 512
    float acc = 0.f;
    #pragma unroll
    for (int c = 0; c < 8; c++) acc += d_attnp[((size_t)t*8 + c)*H_ + h];
    d_attnv[t*H_ + h] = acc;
}

__global__ void add_attn_kernel(const float* __restrict__ final_feature)
{
    int idx = blockIdx.x * blockDim.x + threadIdx.x;   // T_*L_*H_
    int h = idx & (H_-1);
    int t = idx >> 15;
    d_ffin[idx] = final_feature[idx] + d_attnv[t*H_ + h];
}

// ---------------- final log-softmax ----------------
__global__ void logsoftmax_kernel(float* __restrict__ out)
{
    int r = blockIdx.x;
    int tid = threadIdx.x;
    __shared__ float red[256];
    const float* x = d_probs + (size_t)r * OUTC_;
    float mx = -INFINITY;
    for (int c = tid; c < OUTC_; c += 256) mx = fmaxf(mx, x[c]);
    red[tid] = mx; __syncthreads();
    for (int s = 128; s > 0; s >>= 1) { if (tid < s) red[tid] = fmaxf(red[tid], red[tid+s]); __syncthreads(); }
    mx = red[0]; __syncthreads();
    float sum = 0.f;
    for (int c = tid; c < OUTC_; c += 256) sum += expf(x[c] - mx);
    red[tid] = sum; __syncthreads();
    for (int s = 128; s > 0; s >>= 1) { if (tid < s) red[tid] += red[tid+s]; __syncthreads(); }
    float lse = mx + logf(red[0]);
    for (int c = tid; c < OUTC_; c += 256) out[(size_t)r*OUTC_ + c] = x[c] - lse;
}

// ---------------- host launcher ----------------
#define SYM(p, t, s) do { void* _t; cudaGetSymbolAddress(&_t, s); (p) = (t*)_t; } while (0)

extern "C" void kernel_launch(void* const* d_in, const int* in_sizes, int n_in,
                              void* d_out, int out_size)
{
    const float* feat          = (const float*)d_in[0];
    const float* key           = (const float*)d_in[1];
    const float* final_feature = (const float*)d_in[2];
    const float* Wih_f         = (const float*)d_in[3];
    const float* Whh_f         = (const float*)d_in[4];
    const float* bih_f         = (const float*)d_in[5];
    const float* bhh_f         = (const float*)d_in[6];
    const float* Wih_b         = (const float*)d_in[7];
    const float* Whh_b         = (const float*)d_in[8];
    const float* bih_b         = (const float*)d_in[9];
    const float* bhh_b         = (const float*)d_in[10];
    const float* Wb            = (const float*)d_in[11];
    const float* bb            = (const float*)d_in[12];
    const float* Kemb          = (const float*)d_in[13];
    const int*   col_idx       = (const int*)d_in[14];
    const int*   col_mask      = (const int*)d_in[15];
    const int*   tab_idx       = (const int*)d_in[16];
    const int*   tab_mask      = (const int*)d_in[17];
    const int*   attn_mask     = (const int*)d_in[18];
    float* out = (float*)d_out;

    float *Pf, *Pb, *gh_f, *gh_b, *db, *ffin, *ff, *probs;
    __nv_bfloat16 *featS, *WihfS, *WihbS, *WhhfS, *WhhbS, *f1S, *b1S;
    SYM(Pf, float, d_Pf);   SYM(Pb, float, d_Pb);
    SYM(gh_f, float, d_gh_f); SYM(gh_b, float, d_gh_b);
    SYM(db, float, d_db);   SYM(ffin, float, d_ffin); SYM(ff, float, d_ff); SYM(probs, float, d_probs);
    SYM(featS, __nv_bfloat16, d_featS);
    SYM(WihfS, __nv_bfloat16, d_WihfS); SYM(WihbS, __nv_bfloat16, d_WihbS);
    SYM(WhhfS, __nv_bfloat16, d_WhhfS); SYM(WhhbS, __nv_bfloat16, d_WhhbS);
    SYM(f1S, __nv_bfloat16, d_f1S);     SYM(b1S, __nv_bfloat16, d_b1S);

    // 0) split-bf16 conversions
    split_bf16_kernel<<<(TDB_*H_+255)/256, 256>>>(feat,  featS, TDB_*H_, H_, 0);
    split_bf16_kernel<<<(G3_*H_+255)/256, 256>>>(Wih_f, WihfS, G3_*H_, H_, 1);
    split_bf16_kernel<<<(G3_*H_+255)/256, 256>>>(Wih_b, WihbS, G3_*H_, H_, 1);
    split_bf16_kernel<<<(G3_*Hh_+255)/256, 256>>>(Whh_f, WhhfS, G3_*Hh_, Hh_, 1);
    split_bf16_kernel<<<(G3_*Hh_+255)/256, 256>>>(Whh_b, WhhbS, G3_*Hh_, Hh_, 1);

    // 1) projection GEMMs, BATCHED in one launch (z=0: Wih_f, z=1: Wih_b)
    {
        dim3 grid(G3_/128, TDB_/128, 2);
        gemm_wmma2<<<grid, 256>>>(featS, WihfS, Pf, featS, WihbS, Pb, TDB_, G3_, 3*H_, G3_);
    }

    // 2+3) FUSED masked-mean gather + GRU step 1
    gather_gru1_kernel<<<dim3(U_, T_), 256>>>(col_idx, col_mask, tab_idx, tab_mask,
                                              bih_f, bhh_f, bih_b, bhh_b);

    // 4) hidden-projection GEMMs, BATCHED in one launch (z=0: f, z=1: b)
    {
        dim3 grid(G3_/128, TU_/128, 2);
        gemm_wmma2<<<grid, 256>>>(f1S, WhhfS, gh_f, b1S, WhhbS, gh_b, TU_, G3_, 3*Hh_, G3_);
    }

    // 5) second GRU steps + db_emb + fused logits
    gru_second_kernel<<<TU_, 256>>>(bih_f, bhh_f, bih_b, bhh_b, key, attn_mask);

    // 6) attention
    softmax_kernel<<<T_, 256>>>();
    attn_part_kernel<<<dim3(8, T_), 512>>>();
    attn_reduce_kernel<<<T_, 512>>>();

    // 7) feature + attn, then ff = tanh(ffin @ Wb^T + bb)
    add_attn_kernel<<<T_*L_*H_/256, 256>>>(final_feature);
    {
        dim3 grid(H_/128, T_*L_/128, 1);
        sgemm_nt<128,128,16,8,8><<<grid, 256>>>(ffin, Wb, bb, ff, T_*L_, H_, H_, H_, H_, H_, 0,0,0, 1);
    }

    // 8) db_prob: per-t (64 x 1024) = ff[t] (64x512) @ db_emb[t] (1024x512)^T
    {
        dim3 grid(U_/128, L_/64, T_);
        sgemm_nt<64,128,16,4,8><<<grid, 256>>>(ff, db, nullptr, probs,
            L_, U_, H_, H_, H_, OUTC_,
            (long long)L_*H_, (long long)U_*H_, (long long)L_*OUTC_, 0);
    }
    // 9) kw_prob: (1024 x 64) = ff @ Kemb^T, at column offset U_
    {
        dim3 grid(K_/64, T_*L_/64, 1);
        sgemm_nt<64,64,16,4,4><<<grid, 256>>>(ff, Kemb, nullptr, probs + U_,
            T_*L_, K_, H_, H_, H_, OUTC_, 0,0,0, 0);
    }

    // 10) log-softmax over last dim (1088) -> output
    logsoftmax_kernel<<<T_*L_, 256>>>(out);
}

// round 16
// speedup vs baseline: 1.4792x; 1.0188x over previous
#include <cuda_runtime.h>
#include <cuda_bf16.h>
#include <mma.h>
#include <math.h>
#include <stdint.h>

using namespace nvcuda;

// Problem constants
#define T_  16
#define DB_ 512
#define H_  512
#define U_  1024
#define MC_ 8
#define MT_ 4
#define L_  64
#define K_  64
#define Hh_ 256
#define G3_ (3*Hh_)     // 768
#define TU_ (T_*U_)     // 16384
#define TDB_ (T_*DB_)   // 8192
#define OUTC_ (U_+K_)   // 1088
#define K3H_ (3*H_)     // 1536

// ---------------- scratch (device globals; no allocs allowed) ----------------
__device__ float d_Pf[TDB_*G3_];      // feat @ Wih_f^T   (8192 x 768)
__device__ float d_Pb[TDB_*G3_];      // feat @ Wih_b^T
__device__ float d_g_f2[TU_*G3_];     // col-mean of Pf  (gi for f2)
__device__ float d_g_b2[TU_*G3_];     // tab-mean of Pb  (gi for b2)
__device__ float d_f1[TU_*Hh_];
__device__ float d_b1[TU_*Hh_];
__device__ float d_gh_f[TU_*G3_];     // f1@Whh_f^T (raw, bhh added in gru_second)
__device__ float d_gh_b[TU_*G3_];
__device__ float d_db[TU_*H_];        // db_emb (fp32, for attention)
__device__ float d_logits[T_*U_];
__device__ float d_wsm[T_*U_];
__device__ float d_attnp[T_*8*H_];    // attention partials (8 U-chunks)
__device__ float d_attnv[T_*H_];
__device__ float d_ffin[T_*L_*H_];
__device__ float d_ff[T_*L_*H_];
__device__ float d_probs[T_*L_*OUTC_];

// split-bf16 operand buffers ([hi|lo|hi] A-side, [hi|hi|lo] B-side)
__device__ __nv_bfloat16 d_featS[TDB_*K3H_];   // 8192 x 1536
__device__ __nv_bfloat16 d_WihfS[G3_*K3H_];
__device__ __nv_bfloat16 d_WihbS[G3_*K3H_];
__device__ __nv_bfloat16 d_WhhfS[G3_*3*Hh_];
__device__ __nv_bfloat16 d_WhhbS[G3_*3*Hh_];
__device__ __nv_bfloat16 d_f1S[TU_*3*Hh_];
__device__ __nv_bfloat16 d_b1S[TU_*3*Hh_];
__device__ __nv_bfloat16 d_dbS[TU_*K3H_];      // db_emb split, B-side [hi|hi|lo] (50 MB)
__device__ __nv_bfloat16 d_ffS[T_*L_*K3H_];    // ff split, A-side [hi|lo|hi] (3 MB)

// ================= cp.async helpers =================
__device__ __forceinline__ void cp_async16(void* smem_ptr, const void* gptr) {
    uint32_t s = (uint32_t)__cvta_generic_to_shared(smem_ptr);
    asm volatile("cp.async.cg.shared.global [%0], [%1], 16;" :: "r"(s), "l"(gptr));
}
__device__ __forceinline__ void cp_commit() { asm volatile("cp.async.commit_group;" ::: "memory"); }
__device__ __forceinline__ void cp_wait1()  { asm volatile("cp.async.wait_group 1;" ::: "memory"); }
__device__ __forceinline__ void cp_wait0()  { asm volatile("cp.async.wait_group 0;" ::: "memory"); }

// ================= WMMA bf16 GEMM — double-buffered cp.async, WPAD=48 =================
// BATCHED over blockIdx.z: z=0 -> (A0,B0,C0), z=1 -> (A1,B1,C1).
#define WBK 32
#define WPAD 48   // smem leading dim (elements): 96B rows

__global__ __launch_bounds__(256)
void gemm_wmma2(const __nv_bfloat16* __restrict__ A0, const __nv_bfloat16* __restrict__ B0,
                float* __restrict__ C0,
                const __nv_bfloat16* __restrict__ A1, const __nv_bfloat16* __restrict__ B1,
                float* __restrict__ C1,
                int M, int N, int K3, int ldc)
{
    __shared__ __nv_bfloat16 As[2][128 * WPAD];   // 24 KB
    __shared__ __nv_bfloat16 Bs[2][128 * WPAD];   // 24 KB

    const __nv_bfloat16* A = blockIdx.z ? A1 : A0;
    const __nv_bfloat16* B = blockIdx.z ? B1 : B0;
    float*               C = blockIdx.z ? C1 : C0;

    int tid  = threadIdx.x;
    int warp = tid >> 5;
    int wm = warp >> 2;
    int wn = warp & 3;
    int bm = blockIdx.y * 128;
    int bn = blockIdx.x * 128;

    wmma::fragment<wmma::accumulator, 16, 16, 16, float> acc[4][2];
    #pragma unroll
    for (int i = 0; i < 4; i++)
        #pragma unroll
        for (int j = 0; j < 2; j++) wmma::fill_fragment(acc[i][j], 0.0f);

    const int nch = K3 / WBK;

    auto load_stage = [&](int s, int k0) {
        #pragma unroll
        for (int i = tid; i < 512; i += 256) {
            int r = i >> 2, c = i & 3;
            cp_async16(&As[s][r * WPAD + c * 8], A + (size_t)(bm + r) * K3 + k0 + c * 8);
        }
        #pragma unroll
        for (int i = tid; i < 512; i += 256) {
            int r = i >> 2, c = i & 3;
            cp_async16(&Bs[s][r * WPAD + c * 8], B + (size_t)(bn + r) * K3 + k0 + c * 8);
        }
        cp_commit();
    };

    load_stage(0, 0);

    for (int c = 0; c < nch; c++) {
        if (c + 1 < nch) { load_stage((c + 1) & 1, (c + 1) * WBK); cp_wait1(); }
        else             { cp_wait0(); }
        __syncthreads();

        int s = c & 1;
        #pragma unroll
        for (int kk = 0; kk < WBK; kk += 16) {
            wmma::fragment<wmma::matrix_a, 16, 16, 16, __nv_bfloat16, wmma::row_major> fa[4];
            wmma::fragment<wmma::matrix_b, 16, 16, 16, __nv_bfloat16, wmma::col_major> fb[2];
            #pragma unroll
            for (int i = 0; i < 4; i++)
                wmma::load_matrix_sync(fa[i], &As[s][(wm * 64 + i * 16) * WPAD + kk], WPAD);
            #pragma unroll
            for (int j = 0; j < 2; j++)
                wmma::load_matrix_sync(fb[j], &Bs[s][(wn * 32 + j * 16) * WPAD + kk], WPAD);
            #pragma unroll
            for (int i = 0; i < 4; i++)
                #pragma unroll
                for (int j = 0; j < 2; j++)
                    wmma::mma_sync(acc[i][j], fa[i], fb[j], acc[i][j]);
        }
        __syncthreads();
    }

    #pragma unroll
    for (int i = 0; i < 4; i++)
        #pragma unroll
        for (int j = 0; j < 2; j++) {
            int m0 = bm + wm * 64 + i * 16;
            int n0 = bn + wn * 32 + j * 16;
            wmma::store_matrix_sync(C + (size_t)m0 * ldc + n0, acc[i][j], ldc, wmma::mem_row_major);
        }
}

// ================= WMMA bf16 GEMM, BM=64 — for db_prob (batched over z=t) =================
// C[z](64 x N) = A[z](64 x K3) @ B[z](N x K3)^T ; C has leading dim ldc (OUTC_).
__global__ __launch_bounds__(256)
void gemm_wmma64(const __nv_bfloat16* __restrict__ Ab, const __nv_bfloat16* __restrict__ Bb,
                 float* __restrict__ Cb,
                 long long sA, long long sB, long long sC,
                 int K3, int ldc)
{
    __shared__ __nv_bfloat16 As[2][64 * WPAD];    // 12 KB
    __shared__ __nv_bfloat16 Bs[2][128 * WPAD];   // 24 KB

    const __nv_bfloat16* A = Ab + (size_t)blockIdx.z * sA;
    const __nv_bfloat16* B = Bb + (size_t)blockIdx.z * sB;
    float*               C = Cb + (size_t)blockIdx.z * sC;

    int tid  = threadIdx.x;
    int warp = tid >> 5;
    int wm = warp >> 2;          // 0..1 : 32-row slab
    int wn = warp & 3;           // 0..3 : 32-col slab
    int bn = blockIdx.x * 128;

    wmma::fragment<wmma::accumulator, 16, 16, 16, float> acc[2][2];
    #pragma unroll
    for (int i = 0; i < 2; i++)
        #pragma unroll
        for (int j = 0; j < 2; j++) wmma::fill_fragment(acc[i][j], 0.0f);

    const int nch = K3 / WBK;

    auto load_stage = [&](int s, int k0) {
        // A: 64 rows x 32 cols = 256 16B-slots (one per thread)
        {
            int r = tid >> 2, c = tid & 3;
            cp_async16(&As[s][r * WPAD + c * 8], A + (size_t)r * K3 + k0 + c * 8);
        }
        // B: 128 rows x 32 cols = 512 slots
        #pragma unroll
        for (int i = tid; i < 512; i += 256) {
            int r = i >> 2, c = i & 3;
            cp_async16(&Bs[s][r * WPAD + c * 8], B + (size_t)(bn + r) * K3 + k0 + c * 8);
        }
        cp_commit();
    };

    load_stage(0, 0);

    for (int c = 0; c < nch; c++) {
        if (c + 1 < nch) { load_stage((c + 1) & 1, (c + 1) * WBK); cp_wait1(); }
        else             { cp_wait0(); }
        __syncthreads();

        int s = c & 1;
        #pragma unroll
        for (int kk = 0; kk < WBK; kk += 16) {
            wmma::fragment<wmma::matrix_a, 16, 16, 16, __nv_bfloat16, wmma::row_major> fa[2];
            wmma::fragment<wmma::matrix_b, 16, 16, 16, __nv_bfloat16, wmma::col_major> fb[2];
            #pragma unroll
            for (int i = 0; i < 2; i++)
                wmma::load_matrix_sync(fa[i], &As[s][(wm * 32 + i * 16) * WPAD + kk], WPAD);
            #pragma unroll
            for (int j = 0; j < 2; j++)
                wmma::load_matrix_sync(fb[j], &Bs[s][(wn * 32 + j * 16) * WPAD + kk], WPAD);
            #pragma unroll
            for (int i = 0; i < 2; i++)
                #pragma unroll
                for (int j = 0; j < 2; j++)
                    wmma::mma_sync(acc[i][j], fa[i], fb[j], acc[i][j]);
        }
        __syncthreads();
    }

    #pragma unroll
    for (int i = 0; i < 2; i++)
        #pragma unroll
        for (int j = 0; j < 2; j++) {
            int m0 = wm * 32 + i * 16;
            int n0 = bn + wn * 32 + j * 16;
            wmma::store_matrix_sync(C + (size_t)m0 * ldc + n0, acc[i][j], ldc, wmma::mem_row_major);
        }
}

// ================= split-bf16 conversion =================
// orderB=0: [hi|lo|hi] (A-side) ; orderB=1: [hi|hi|lo] (B-side)
__global__ void split_bf16_kernel(const float* __restrict__ X, __nv_bfloat16* __restrict__ Y,
                                  int n, int Kd, int orderB)
{
    int idx = blockIdx.x * blockDim.x + threadIdx.x;
    if (idx >= n) return;
    float x = X[idx];
    __nv_bfloat16 h = __float2bfloat16(x);
    __nv_bfloat16 l = __float2bfloat16(x - __bfloat162float(h));
    int r = idx / Kd, k = idx - r * Kd;
    size_t bse = (size_t)r * 3 * Kd;
    if (orderB) { Y[bse + k] = h; Y[bse + Kd + k] = h; Y[bse + 2*Kd + k] = l; }
    else        { Y[bse + k] = h; Y[bse + Kd + k] = l; Y[bse + 2*Kd + k] = h; }
}

// ---------------- scalar-FFMA SGEMM (small tail GEMMs) ----------------
template<int BM, int BN, int BK, int TM, int TN>
__global__ void sgemm_nt(const float* __restrict__ A, const float* __restrict__ B,
                         const float* __restrict__ bias, float* __restrict__ C,
                         int M, int N, int K, int lda, int ldb, int ldc,
                         long long sA, long long sB, long long sC, int act)
{
    constexpr int THREADS = (BM/TM) * (BN/TN);
    __shared__ float As[BK][BM];
    __shared__ float Bs[BK][BN];

    A += (size_t)blockIdx.z * sA;
    B += (size_t)blockIdx.z * sB;
    C += (size_t)blockIdx.z * sC;

    int bm = blockIdx.y * BM;
    int bn = blockIdx.x * BN;
    int tid = threadIdx.x;
    int tx = tid % (BN/TN);
    int ty = tid / (BN/TN);

    float acc[TM][TN];
    #pragma unroll
    for (int i = 0; i < TM; i++)
        #pragma unroll
        for (int j = 0; j < TN; j++) acc[i][j] = 0.f;

    for (int k0 = 0; k0 < K; k0 += BK) {
        #pragma unroll
        for (int i = tid; i < BM*BK/4; i += THREADS) {
            int r = i / (BK/4), c4 = i % (BK/4);
            float4 v = *(const float4*)&A[(size_t)(bm+r)*lda + k0 + c4*4];
            As[c4*4+0][r] = v.x; As[c4*4+1][r] = v.y;
            As[c4*4+2][r] = v.z; As[c4*4+3][r] = v.w;
        }
        #pragma unroll
        for (int i = tid; i < BN*BK/4; i += THREADS) {
            int r = i / (BK/4), c4 = i % (BK/4);
            float4 v = *(const float4*)&B[(size_t)(bn+r)*ldb + k0 + c4*4];
            Bs[c4*4+0][r] = v.x; Bs[c4*4+1][r] = v.y;
            Bs[c4*4+2][r] = v.z; Bs[c4*4+3][r] = v.w;
        }
        __syncthreads();
        #pragma unroll
        for (int kk = 0; kk < BK; kk++) {
            float a[TM], b[TN];
            #pragma unroll
            for (int i = 0; i < TM; i++) a[i] = As[kk][ty*TM + i];
            #pragma unroll
            for (int j = 0; j < TN; j++) b[j] = Bs[kk][tx*TN + j];
            #pragma unroll
            for (int i = 0; i < TM; i++)
                #pragma unroll
                for (int j = 0; j < TN; j++) acc[i][j] += a[i]*b[j];
        }
        __syncthreads();
    }

    #pragma unroll
    for (int i = 0; i < TM; i++) {
        int m = bm + ty*TM + i;
        #pragma unroll
        for (int j = 0; j < TN; j++) {
            int n = bn + tx*TN + j;
            float v = acc[i][j];
            if (bias) v += bias[n];
            if (act == 1) v = tanhf(v);
            C[(size_t)m*ldc + n] = v;
        }
    }
}

// ---------------- GRU math ----------------
__device__ __forceinline__ float sigm(float x) { return 1.f / (1.f + expf(-x)); }

// ============ FUSED: masked-mean gather (projected space) + GRU step 1 ============
__global__ __launch_bounds__(256)
void gather_gru1_kernel(const int* __restrict__ col_idx, const int* __restrict__ col_mask,
                        const int* __restrict__ tab_idx, const int* __restrict__ tab_mask,
                        const float* __restrict__ bih_f, const float* __restrict__ bhh_f,
                        const float* __restrict__ bih_b, const float* __restrict__ bhh_b)
{
    int u = blockIdx.x, t = blockIdx.y;
    int j = threadIdx.x;
    const float* Pf = d_Pf + (size_t)t * DB_ * G3_;
    const float* Pb = d_Pb + (size_t)t * DB_ * G3_;

    float tf_r=0.f, tf_z=0.f, tf_n=0.f, tb_r=0.f, tb_z=0.f, tb_n=0.f, cnt_t=0.f;
    #pragma unroll
    for (int m = 0; m < MT_; m++) {
        if (tab_mask[u*MT_+m]) {
            int id = tab_idx[u*MT_+m];
            const float* pf = Pf + (size_t)id * G3_;
            const float* pb = Pb + (size_t)id * G3_;
            tf_r += pf[j]; tf_z += pf[Hh_+j]; tf_n += pf[2*Hh_+j];
            tb_r += pb[j]; tb_z += pb[Hh_+j]; tb_n += pb[2*Hh_+j];
            cnt_t += 1.f;
        }
    }
    float cf_r=0.f, cf_z=0.f, cf_n=0.f, cb_r=0.f, cb_z=0.f, cb_n=0.f, cnt_c=0.f;
    #pragma unroll
    for (int m = 0; m < MC_; m++) {
        if (col_mask[u*MC_+m]) {
            int id = col_idx[u*MC_+m];
            const float* pf = Pf + (size_t)id * G3_;
            const float* pb = Pb + (size_t)id * G3_;
            cf_r += pf[j]; cf_z += pf[Hh_+j]; cf_n += pf[2*Hh_+j];
            cb_r += pb[j]; cb_z += pb[Hh_+j]; cb_n += pb[2*Hh_+j];
            cnt_c += 1.f;
        }
    }
    float it = 1.f / fmaxf(cnt_t, 1.f);
    float ic = 1.f / fmaxf(cnt_c, 1.f);
    size_t row = (size_t)t * U_ + u;

    d_g_f2[row*G3_ + j]         = cf_r * ic;
    d_g_f2[row*G3_ + Hh_ + j]   = cf_z * ic;
    d_g_f2[row*G3_ + 2*Hh_ + j] = cf_n * ic;
    d_g_b2[row*G3_ + j]         = tb_r * it;
    d_g_b2[row*G3_ + Hh_ + j]   = tb_z * it;
    d_g_b2[row*G3_ + 2*Hh_ + j] = tb_n * it;

    {
        float r = sigm(tf_r*it + bih_f[j]       + bhh_f[j]);
        float z = sigm(tf_z*it + bih_f[Hh_+j]   + bhh_f[Hh_+j]);
        float n = tanhf(tf_n*it + bih_f[2*Hh_+j] + r * bhh_f[2*Hh_+j]);
        float v = (1.f - z) * n;
        d_f1[row*Hh_ + j] = v;
        __nv_bfloat16 h = __float2bfloat16(v);
        __nv_bfloat16 l = __float2bfloat16(v - __bfloat162float(h));
        d_f1S[row*G3_ + j] = h; d_f1S[row*G3_ + Hh_ + j] = l; d_f1S[row*G3_ + 2*Hh_ + j] = h;
    }
    {
        float r = sigm(cb_r*ic + bih_b[j]       + bhh_b[j]);
        float z = sigm(cb_z*ic + bih_b[Hh_+j]   + bhh_b[Hh_+j]);
        float n = tanhf(cb_n*ic + bih_b[2*Hh_+j] + r * bhh_b[2*Hh_+j]);
        float v = (1.f - z) * n;
        d_b1[row*Hh_ + j] = v;
        __nv_bfloat16 h = __float2bfloat16(v);
        __nv_bfloat16 l = __float2bfloat16(v - __bfloat162float(h));
        d_b1S[row*G3_ + j] = h; d_b1S[row*G3_ + Hh_ + j] = l; d_b1S[row*G3_ + 2*Hh_ + j] = h;
    }
}

// second steps + db_emb (fp32 + B-side split-bf16) + FUSED masked logit.
__global__ __launch_bounds__(256)
void gru_second_kernel(const float* __restrict__ bih_f, const float* __restrict__ bhh_f,
                       const float* __restrict__ bih_b, const float* __restrict__ bhh_b,
                       const float* __restrict__ key, const int* __restrict__ attn_mask)
{
    int row = blockIdx.x;                 // 0..TU_-1
    int j   = threadIdx.x;                // 0..255
    int idx = row * Hh_ + j;
    int t   = row >> 10;                  // row / U_
    float db0, db1;
    {
        const float* gi = d_g_f2 + (size_t)row * G3_;
        const float* gh = d_gh_f + (size_t)row * G3_;
        float h  = d_f1[idx];
        float r = sigm(gi[j]       + bih_f[j]       + gh[j]       + bhh_f[j]);
        float z = sigm(gi[Hh_+j]   + bih_f[Hh_+j]   + gh[Hh_+j]   + bhh_f[Hh_+j]);
        float n = tanhf(gi[2*Hh_+j] + bih_f[2*Hh_+j] + r * (gh[2*Hh_+j] + bhh_f[2*Hh_+j]));
        float f2 = (1.f - z) * n + z * h;
        db0 = 0.5f * (h + f2);
        d_db[(size_t)row*H_ + j] = db0;
    }
    {
        const float* gi = d_g_b2 + (size_t)row * G3_;
        const float* gh = d_gh_b + (size_t)row * G3_;
        float h  = d_b1[idx];
        float r = sigm(gi[j]       + bih_b[j]       + gh[j]       + bhh_b[j]);
        float z = sigm(gi[Hh_+j]   + bih_b[Hh_+j]   + gh[Hh_+j]   + bhh_b[Hh_+j]);
        float n = tanhf(gi[2*Hh_+j] + bih_b[2*Hh_+j] + r * (gh[2*Hh_+j] + bhh_b[2*Hh_+j]));
        float b2 = (1.f - z) * n + z * h;
        db1 = 0.5f * (h + b2);
        d_db[(size_t)row*H_ + Hh_ + j] = db1;
    }
    // emit B-side split-bf16 ([hi|hi|lo] over K=512): elems j (db0) and j+256 (db1)
    {
        size_t sb = (size_t)row * K3H_;
        __nv_bfloat16 h0 = __float2bfloat16(db0);
        __nv_bfloat16 l0 = __float2bfloat16(db0 - __bfloat162float(h0));
        d_dbS[sb + j] = h0; d_dbS[sb + H_ + j] = h0; d_dbS[sb + 2*H_ + j] = l0;
        __nv_bfloat16 h1 = __float2bfloat16(db1);
        __nv_bfloat16 l1 = __float2bfloat16(db1 - __bfloat162float(h1));
        d_dbS[sb + Hh_ + j] = h1; d_dbS[sb + H_ + Hh_ + j] = h1; d_dbS[sb + 2*H_ + Hh_ + j] = l1;
    }
    // fused logit: sum_j key[t][j]*db0 + key[t][Hh+j]*db1
    float part = key[(size_t)t*H_ + j] * db0 + key[(size_t)t*H_ + Hh_ + j] * db1;
    #pragma unroll
    for (int s = 16; s > 0; s >>= 1) part += __shfl_xor_sync(0xFFFFFFFFu, part, s);
    __shared__ float wsum[8];
    if ((j & 31) == 0) wsum[j >> 5] = part;
    __syncthreads();
    if (j == 0) {
        float acc = 0.f;
        #pragma unroll
        for (int w = 0; w < 8; w++) acc += wsum[w];
        d_logits[row] = attn_mask[row] ? acc : -1e9f;
    }
}

// ---------------- attention ----------------
__global__ void softmax_kernel()
{
    int t = blockIdx.x;
    __shared__ float red[256];
    int tid = threadIdx.x;
    float mx = -INFINITY;
    for (int u = tid; u < U_; u += 256) mx = fmaxf(mx, d_logits[t*U_+u]);
    red[tid] = mx; __syncthreads();
    for (int s = 128; s > 0; s >>= 1) { if (tid < s) red[tid] = fmaxf(red[tid], red[tid+s]); __syncthreads(); }
    mx = red[0]; __syncthreads();
    float sum = 0.f;
    for (int u = tid; u < U_; u += 256) sum += expf(d_logits[t*U_+u] - mx);
    red[tid] = sum; __syncthreads();
    for (int s = 128; s > 0; s >>= 1) { if (tid < s) red[tid] += red[tid+s]; __syncthreads(); }
    sum = red[0];
    float inv = 1.f / sum;
    for (int u = tid; u < U_; u += 256) d_wsm[t*U_+u] = expf(d_logits[t*U_+u] - mx) * inv;
}

// attention value: split U into 8 chunks of 128 (128 blocks) + reduce
__global__ void attn_part_kernel()
{
    int chunk = blockIdx.x, t = blockIdx.y;
    int h = threadIdx.x;                 // 512 threads
    __shared__ float ws[128];
    if (h < 128) ws[h] = d_wsm[t*U_ + chunk*128 + h];
    __syncthreads();
    float acc = 0.f;
    const float* d = d_db + ((size_t)t*U_ + chunk*128) * H_ + h;
    #pragma unroll 4
    for (int u = 0; u < 128; u++) acc += ws[u] * d[(size_t)u*H_];
    d_attnp[((size_t)t*8 + chunk)*H_ + h] = acc;
}

__global__ void attn_reduce_kernel()
{
    int t = blockIdx.x;
    int h = threadIdx.x;                 // 512
    float acc = 0.f;
    #pragma unroll
    for (int c = 0; c < 8; c++) acc += d_attnp[((size_t)t*8 + c)*H_ + h];
    d_attnv[t*H_ + h] = acc;
}

__global__ void add_attn_kernel(const float* __restrict__ final_feature)
{
    int idx = blockIdx.x * blockDim.x + threadIdx.x;   // T_*L_*H_
    int h = idx & (H_-1);
    int t = idx >> 15;
    d_ffin[idx] = final_feature[idx] + d_attnv[t*H_ + h];
}

// ---------------- final log-softmax ----------------
__global__ void logsoftmax_kernel(float* __restrict__ out)
{
    int r = blockIdx.x;
    int tid = threadIdx.x;
    __shared__ float red[256];
    const float* x = d_probs + (size_t)r * OUTC_;
    float mx = -INFINITY;
    for (int c = tid; c < OUTC_; c += 256) mx = fmaxf(mx, x[c]);
    red[tid] = mx; __syncthreads();
    for (int s = 128; s > 0; s >>= 1) { if (tid < s) red[tid] = fmaxf(red[tid], red[tid+s]); __syncthreads(); }
    mx = red[0]; __syncthreads();
    float sum = 0.f;
    for (int c = tid; c < OUTC_; c += 256) sum += expf(x[c] - mx);
    red[tid] = sum; __syncthreads();
    for (int s = 128; s > 0; s >>= 1) { if (tid < s) red[tid] += red[tid+s]; __syncthreads(); }
    float lse = mx + logf(red[0]);
    for (int c = tid; c < OUTC_; c += 256) out[(size_t)r*OUTC_ + c] = x[c] - lse;
}

// ---------------- host launcher ----------------
#define SYM(p, t, s) do { void* _t; cudaGetSymbolAddress(&_t, s); (p) = (t*)_t; } while (0)

extern "C" void kernel_launch(void* const* d_in, const int* in_sizes, int n_in,
                              void* d_out, int out_size)
{
    const float* feat          = (const float*)d_in[0];
    const float* key           = (const float*)d_in[1];
    const float* final_feature = (const float*)d_in[2];
    const float* Wih_f         = (const float*)d_in[3];
    const float* Whh_f         = (const float*)d_in[4];
    const float* bih_f         = (const float*)d_in[5];
    const float* bhh_f         = (const float*)d_in[6];
    const float* Wih_b         = (const float*)d_in[7];
    const float* Whh_b         = (const float*)d_in[8];
    const float* bih_b         = (const float*)d_in[9];
    const float* bhh_b         = (const float*)d_in[10];
    const float* Wb            = (const float*)d_in[11];
    const float* bb            = (const float*)d_in[12];
    const float* Kemb          = (const float*)d_in[13];
    const int*   col_idx       = (const int*)d_in[14];
    const int*   col_mask      = (const int*)d_in[15];
    const int*   tab_idx       = (const int*)d_in[16];
    const int*   tab_mask      = (const int*)d_in[17];
    const int*   attn_mask     = (const int*)d_in[18];
    float* out = (float*)d_out;

    float *Pf, *Pb, *gh_f, *gh_b, *db, *ffin, *ff, *probs;
    __nv_bfloat16 *featS, *WihfS, *WihbS, *WhhfS, *WhhbS, *f1S, *b1S, *dbS, *ffS;
    SYM(Pf, float, d_Pf);   SYM(Pb, float, d_Pb);
    SYM(gh_f, float, d_gh_f); SYM(gh_b, float, d_gh_b);
    SYM(db, float, d_db);   SYM(ffin, float, d_ffin); SYM(ff, float, d_ff); SYM(probs, float, d_probs);
    SYM(featS, __nv_bfloat16, d_featS);
    SYM(WihfS, __nv_bfloat16, d_WihfS); SYM(WihbS, __nv_bfloat16, d_WihbS);
    SYM(WhhfS, __nv_bfloat16, d_WhhfS); SYM(WhhbS, __nv_bfloat16, d_WhhbS);
    SYM(f1S, __nv_bfloat16, d_f1S);     SYM(b1S, __nv_bfloat16, d_b1S);
    SYM(dbS, __nv_bfloat16, d_dbS);     SYM(ffS, __nv_bfloat16, d_ffS);

    // 0) split-bf16 conversions
    split_bf16_kernel<<<(TDB_*H_+255)/256, 256>>>(feat,  featS, TDB_*H_, H_, 0);
    split_bf16_kernel<<<(G3_*H_+255)/256, 256>>>(Wih_f, WihfS, G3_*H_, H_, 1);
    split_bf16_kernel<<<(G3_*H_+255)/256, 256>>>(Wih_b, WihbS, G3_*H_, H_, 1);
    split_bf16_kernel<<<(G3_*Hh_+255)/256, 256>>>(Whh_f, WhhfS, G3_*Hh_, Hh_, 1);
    split_bf16_kernel<<<(G3_*Hh_+255)/256, 256>>>(Whh_b, WhhbS, G3_*Hh_, Hh_, 1);

    // 1) projection GEMMs, BATCHED in one launch (z=0: Wih_f, z=1: Wih_b)
    {
        dim3 grid(G3_/128, TDB_/128, 2);
        gemm_wmma2<<<grid, 256>>>(featS, WihfS, Pf, featS, WihbS, Pb, TDB_, G3_, K3H_, G3_);
    }

    // 2+3) FUSED masked-mean gather + GRU step 1
    gather_gru1_kernel<<<dim3(U_, T_), 256>>>(col_idx, col_mask, tab_idx, tab_mask,
                                              bih_f, bhh_f, bih_b, bhh_b);

    // 4) hidden-projection GEMMs, BATCHED in one launch (z=0: f, z=1: b)
    {
        dim3 grid(G3_/128, TU_/128, 2);
        gemm_wmma2<<<grid, 256>>>(f1S, WhhfS, gh_f, b1S, WhhbS, gh_b, TU_, G3_, 3*Hh_, G3_);
    }

    // 5) second GRU steps + db_emb (fp32 + split) + fused logits
    gru_second_kernel<<<TU_, 256>>>(bih_f, bhh_f, bih_b, bhh_b, key, attn_mask);

    // 6) attention
    softmax_kernel<<<T_, 256>>>();
    attn_part_kernel<<<dim3(8, T_), 512>>>();
    attn_reduce_kernel<<<T_, 512>>>();

    // 7) feature + attn, then ff = tanh(ffin @ Wb^T + bb)
    add_attn_kernel<<<T_*L_*H_/256, 256>>>(final_feature);
    {
        dim3 grid(H_/128, T_*L_/128, 1);
        sgemm_nt<128,128,16,8,8><<<grid, 256>>>(ffin, Wb, bb, ff, T_*L_, H_, H_, H_, H_, H_, 0,0,0, 1);
    }
    // split ff for the tensor db_prob GEMM (A-side [hi|lo|hi])
    split_bf16_kernel<<<(T_*L_*H_+255)/256, 256>>>(ff, ffS, T_*L_*H_, H_, 0);

    // 8) db_prob on tensor cores: per-t (64 x 1024, K'=1536), batched over z=t
    {
        dim3 grid(U_/128, 1, T_);
        gemm_wmma64<<<grid, 256>>>(ffS, dbS, probs,
            (long long)L_*K3H_, (long long)U_*K3H_, (long long)L_*OUTC_,
            K3H_, OUTC_);
    }
    // 9) kw_prob: (1024 x 64) = ff @ Kemb^T, at column offset U_ (fp32)
    {
        dim3 grid(K_/64, T_*L_/64, 1);
        sgemm_nt<64,64,16,4,4><<<grid, 256>>>(ff, Kemb, nullptr, probs + U_,
            T_*L_, K_, H_, H_, H_, OUTC_, 0,0,0, 0);
    }

    // 10) log-softmax over last dim (1088) -> output
    logsoftmax_kernel<<<T_*L_, 256>>>(out);
}

// round 17
// speedup vs baseline: 1.6377x; 1.1071x over previous
#include <cuda_runtime.h>
#include <cuda_bf16.h>
#include <mma.h>
#include <math.h>
#include <stdint.h>

using namespace nvcuda;

// Problem constants
#define T_  16
#define DB_ 512
#define H_  512
#define U_  1024
#define MC_ 8
#define MT_ 4
#define L_  64
#define K_  64
#define Hh_ 256
#define G3_ (3*Hh_)     // 768
#define TU_ (T_*U_)     // 16384
#define TDB_ (T_*DB_)   // 8192
#define OUTC_ (U_+K_)   // 1088
#define K3H_ (3*H_)     // 1536
#define TL_ (T_*L_)     // 1024

// ---------------- scratch (device globals; no allocs allowed) ----------------
__device__ float d_Pf[TDB_*G3_];
__device__ float d_Pb[TDB_*G3_];
__device__ float d_g_f2[TU_*G3_];
__device__ float d_g_b2[TU_*G3_];
__device__ float d_f1[TU_*Hh_];
__device__ float d_b1[TU_*Hh_];
__device__ float d_gh_f[TU_*G3_];
__device__ float d_gh_b[TU_*G3_];
__device__ float d_db[TU_*H_];        // db_emb (fp32, for attention)
__device__ float d_logits[T_*U_];
__device__ float d_wsm[T_*U_];
__device__ float d_attnp[T_*8*H_];
__device__ float d_attnv[T_*H_];
__device__ float d_ff[TL_*H_];        // ff fp32 (for kw_prob)
__device__ float d_probs[TL_*OUTC_];

// split-bf16 operand buffers ([hi|lo|hi] A-side, [hi|hi|lo] B-side)
__device__ __nv_bfloat16 d_featS[TDB_*K3H_];
__device__ __nv_bfloat16 d_WihfS[G3_*K3H_];
__device__ __nv_bfloat16 d_WihbS[G3_*K3H_];
__device__ __nv_bfloat16 d_WhhfS[G3_*3*Hh_];
__device__ __nv_bfloat16 d_WhhbS[G3_*3*Hh_];
__device__ __nv_bfloat16 d_WbS[H_*K3H_];       // Wb split (B-side)
__device__ __nv_bfloat16 d_f1S[TU_*3*Hh_];
__device__ __nv_bfloat16 d_b1S[TU_*3*Hh_];
__device__ __nv_bfloat16 d_dbS[TU_*K3H_];      // db_emb split, B-side
__device__ __nv_bfloat16 d_ffinS[TL_*K3H_];    // ffin split, A-side
__device__ __nv_bfloat16 d_ffS[TL_*K3H_];      // ff split, A-side

// ================= cp.async helpers =================
__device__ __forceinline__ void cp_async16(void* smem_ptr, const void* gptr) {
    uint32_t s = (uint32_t)__cvta_generic_to_shared(smem_ptr);
    asm volatile("cp.async.cg.shared.global [%0], [%1], 16;" :: "r"(s), "l"(gptr));
}
__device__ __forceinline__ void cp_commit() { asm volatile("cp.async.commit_group;" ::: "memory"); }
__device__ __forceinline__ void cp_wait1()  { asm volatile("cp.async.wait_group 1;" ::: "memory"); }
__device__ __forceinline__ void cp_wait0()  { asm volatile("cp.async.wait_group 0;" ::: "memory"); }

#define WBK 32
#define WPAD 48

// ================= WMMA bf16 GEMM 128x128, batched-by-z over two problem sets =================
__global__ __launch_bounds__(256)
void gemm_wmma2(const __nv_bfloat16* __restrict__ A0, const __nv_bfloat16* __restrict__ B0,
                float* __restrict__ C0,
                const __nv_bfloat16* __restrict__ A1, const __nv_bfloat16* __restrict__ B1,
                float* __restrict__ C1,
                int M, int N, int K3, int ldc)
{
    __shared__ __nv_bfloat16 As[2][128 * WPAD];
    __shared__ __nv_bfloat16 Bs[2][128 * WPAD];

    const __nv_bfloat16* A = blockIdx.z ? A1 : A0;
    const __nv_bfloat16* B = blockIdx.z ? B1 : B0;
    float*               C = blockIdx.z ? C1 : C0;

    int tid  = threadIdx.x;
    int warp = tid >> 5;
    int wm = warp >> 2;
    int wn = warp & 3;
    int bm = blockIdx.y * 128;
    int bn = blockIdx.x * 128;

    wmma::fragment<wmma::accumulator, 16, 16, 16, float> acc[4][2];
    #pragma unroll
    for (int i = 0; i < 4; i++)
        #pragma unroll
        for (int j = 0; j < 2; j++) wmma::fill_fragment(acc[i][j], 0.0f);

    const int nch = K3 / WBK;

    auto load_stage = [&](int s, int k0) {
        #pragma unroll
        for (int i = tid; i < 512; i += 256) {
            int r = i >> 2, c = i & 3;
            cp_async16(&As[s][r * WPAD + c * 8], A + (size_t)(bm + r) * K3 + k0 + c * 8);
        }
        #pragma unroll
        for (int i = tid; i < 512; i += 256) {
            int r = i >> 2, c = i & 3;
            cp_async16(&Bs[s][r * WPAD + c * 8], B + (size_t)(bn + r) * K3 + k0 + c * 8);
        }
        cp_commit();
    };

    load_stage(0, 0);

    for (int c = 0; c < nch; c++) {
        if (c + 1 < nch) { load_stage((c + 1) & 1, (c + 1) * WBK); cp_wait1(); }
        else             { cp_wait0(); }
        __syncthreads();

        int s = c & 1;
        #pragma unroll
        for (int kk = 0; kk < WBK; kk += 16) {
            wmma::fragment<wmma::matrix_a, 16, 16, 16, __nv_bfloat16, wmma::row_major> fa[4];
            wmma::fragment<wmma::matrix_b, 16, 16, 16, __nv_bfloat16, wmma::col_major> fb[2];
            #pragma unroll
            for (int i = 0; i < 4; i++)
                wmma::load_matrix_sync(fa[i], &As[s][(wm * 64 + i * 16) * WPAD + kk], WPAD);
            #pragma unroll
            for (int j = 0; j < 2; j++)
                wmma::load_matrix_sync(fb[j], &Bs[s][(wn * 32 + j * 16) * WPAD + kk], WPAD);
            #pragma unroll
            for (int i = 0; i < 4; i++)
                #pragma unroll
                for (int j = 0; j < 2; j++)
                    wmma::mma_sync(acc[i][j], fa[i], fb[j], acc[i][j]);
        }
        __syncthreads();
    }

    #pragma unroll
    for (int i = 0; i < 4; i++)
        #pragma unroll
        for (int j = 0; j < 2; j++) {
            int m0 = bm + wm * 64 + i * 16;
            int n0 = bn + wn * 32 + j * 16;
            wmma::store_matrix_sync(C + (size_t)m0 * ldc + n0, acc[i][j], ldc, wmma::mem_row_major);
        }
}

// ================= WMMA bf16 GEMM, BM=64 — db_prob (batched over z=t) =================
__global__ __launch_bounds__(256)
void gemm_wmma64(const __nv_bfloat16* __restrict__ Ab, const __nv_bfloat16* __restrict__ Bb,
                 float* __restrict__ Cb,
                 long long sA, long long sB, long long sC,
                 int K3, int ldc)
{
    __shared__ __nv_bfloat16 As[2][64 * WPAD];
    __shared__ __nv_bfloat16 Bs[2][128 * WPAD];

    const __nv_bfloat16* A = Ab + (size_t)blockIdx.z * sA;
    const __nv_bfloat16* B = Bb + (size_t)blockIdx.z * sB;
    float*               C = Cb + (size_t)blockIdx.z * sC;

    int tid  = threadIdx.x;
    int warp = tid >> 5;
    int wm = warp >> 2;
    int wn = warp & 3;
    int bn = blockIdx.x * 128;

    wmma::fragment<wmma::accumulator, 16, 16, 16, float> acc[2][2];
    #pragma unroll
    for (int i = 0; i < 2; i++)
        #pragma unroll
        for (int j = 0; j < 2; j++) wmma::fill_fragment(acc[i][j], 0.0f);

    const int nch = K3 / WBK;

    auto load_stage = [&](int s, int k0) {
        {
            int r = tid >> 2, c = tid & 3;
            cp_async16(&As[s][r * WPAD + c * 8], A + (size_t)r * K3 + k0 + c * 8);
        }
        #pragma unroll
        for (int i = tid; i < 512; i += 256) {
            int r = i >> 2, c = i & 3;
            cp_async16(&Bs[s][r * WPAD + c * 8], B + (size_t)(bn + r) * K3 + k0 + c * 8);
        }
        cp_commit();
    };

    load_stage(0, 0);

    for (int c = 0; c < nch; c++) {
        if (c + 1 < nch) { load_stage((c + 1) & 1, (c + 1) * WBK); cp_wait1(); }
        else             { cp_wait0(); }
        __syncthreads();

        int s = c & 1;
        #pragma unroll
        for (int kk = 0; kk < WBK; kk += 16) {
            wmma::fragment<wmma::matrix_a, 16, 16, 16, __nv_bfloat16, wmma::row_major> fa[2];
            wmma::fragment<wmma::matrix_b, 16, 16, 16, __nv_bfloat16, wmma::col_major> fb[2];
            #pragma unroll
            for (int i = 0; i < 2; i++)
                wmma::load_matrix_sync(fa[i], &As[s][(wm * 32 + i * 16) * WPAD + kk], WPAD);
            #pragma unroll
            for (int j = 0; j < 2; j++)
                wmma::load_matrix_sync(fb[j], &Bs[s][(wn * 32 + j * 16) * WPAD + kk], WPAD);
            #pragma unroll
            for (int i = 0; i < 2; i++)
                #pragma unroll
                for (int j = 0; j < 2; j++)
                    wmma::mma_sync(acc[i][j], fa[i], fb[j], acc[i][j]);
        }
        __syncthreads();
    }

    #pragma unroll
    for (int i = 0; i < 2; i++)
        #pragma unroll
        for (int j = 0; j < 2; j++) {
            int m0 = wm * 32 + i * 16;
            int n0 = bn + wn * 32 + j * 16;
            wmma::store_matrix_sync(C + (size_t)m0 * ldc + n0, acc[i][j], ldc, wmma::mem_row_major);
        }
}

// ================= WMMA ffn: ff = tanh(ffin @ Wb^T + bb), dual emission =================
// A = ffinS (TL x K3H split), B = WbS (H x K3H split B-side). BM=64, BN=128.
// Epilogue: smem staging -> tanh(+bias) -> d_ff (fp32) AND d_ffS (A-side split).
#define CPAD 132   // fp32 staging leading dim

__global__ __launch_bounds__(256)
void gemm_wmma_ffn(const __nv_bfloat16* __restrict__ A, const __nv_bfloat16* __restrict__ B,
                   const float* __restrict__ bias,
                   float* __restrict__ Cff, __nv_bfloat16* __restrict__ CffS)
{
    // As: 2*64*48*2 = 12288 B ; Bs: 2*128*48*2 = 24576 B ; Cs (reuse): 64*132*4 = 33792 B
    __shared__ __align__(16) char sraw[12288 + 24576];
    __nv_bfloat16* Asp = (__nv_bfloat16*)sraw;            // [2][64*WPAD]
    __nv_bfloat16* Bsp = (__nv_bfloat16*)(sraw + 12288);  // [2][128*WPAD]
    float* Cs = (float*)sraw;                             // staging after mainloop

    const int K3 = K3H_;
    int tid  = threadIdx.x;
    int warp = tid >> 5;
    int wm = warp >> 2;
    int wn = warp & 3;
    int bm = blockIdx.y * 64;
    int bn = blockIdx.x * 128;

    wmma::fragment<wmma::accumulator, 16, 16, 16, float> acc[2][2];
    #pragma unroll
    for (int i = 0; i < 2; i++)
        #pragma unroll
        for (int j = 0; j < 2; j++) wmma::fill_fragment(acc[i][j], 0.0f);

    const int nch = K3 / WBK;   // 48

    auto load_stage = [&](int s, int k0) {
        {
            int r = tid >> 2, c = tid & 3;
            cp_async16(&Asp[s * 64 * WPAD + r * WPAD + c * 8], A + (size_t)(bm + r) * K3 + k0 + c * 8);
        }
        #pragma unroll
        for (int i = tid; i < 512; i += 256) {
            int r = i >> 2, c = i & 3;
            cp_async16(&Bsp[s * 128 * WPAD + r * WPAD + c * 8], B + (size_t)(bn + r) * K3 + k0 + c * 8);
        }
        cp_commit();
    };

    load_stage(0, 0);

    for (int c = 0; c < nch; c++) {
        if (c + 1 < nch) { load_stage((c + 1) & 1, (c + 1) * WBK); cp_wait1(); }
        else             { cp_wait0(); }
        __syncthreads();

        int s = c & 1;
        #pragma unroll
        for (int kk = 0; kk < WBK; kk += 16) {
            wmma::fragment<wmma::matrix_a, 16, 16, 16, __nv_bfloat16, wmma::row_major> fa[2];
            wmma::fragment<wmma::matrix_b, 16, 16, 16, __nv_bfloat16, wmma::col_major> fb[2];
            #pragma unroll
            for (int i = 0; i < 2; i++)
                wmma::load_matrix_sync(fa[i], &Asp[s * 64 * WPAD + (wm * 32 + i * 16) * WPAD + kk], WPAD);
            #pragma unroll
            for (int j = 0; j < 2; j++)
                wmma::load_matrix_sync(fb[j], &Bsp[s * 128 * WPAD + (wn * 32 + j * 16) * WPAD + kk], WPAD);
            #pragma unroll
            for (int i = 0; i < 2; i++)
                #pragma unroll
                for (int j = 0; j < 2; j++)
                    wmma::mma_sync(acc[i][j], fa[i], fb[j], acc[i][j]);
        }
        __syncthreads();
    }

    // epilogue: stage into smem (safe: all stage reads done at last __syncthreads)
    #pragma unroll
    for (int i = 0; i < 2; i++)
        #pragma unroll
        for (int j = 0; j < 2; j++)
            wmma::store_matrix_sync(Cs + (wm * 32 + i * 16) * CPAD + wn * 32 + j * 16,
                                    acc[i][j], CPAD, wmma::mem_row_major);
    __syncthreads();

    #pragma unroll
    for (int i = 0; i < 32; i++) {
        int idx = tid + 256 * i;          // 0 .. 8191
        int r = idx >> 7, n = idx & 127;
        float v = tanhf(Cs[r * CPAD + n] + bias[bn + n]);
        int gr = bm + r, gn = bn + n;
        Cff[(size_t)gr * H_ + gn] = v;
        __nv_bfloat16 h = __float2bfloat16(v);
        __nv_bfloat16 l = __float2bfloat16(v - __bfloat162float(h));
        size_t sb = (size_t)gr * K3H_ + gn;
        CffS[sb] = h; CffS[sb + H_] = l; CffS[sb + 2*H_] = h;
    }
}

// ================= split-bf16 conversion =================
__global__ void split_bf16_kernel(const float* __restrict__ X, __nv_bfloat16* __restrict__ Y,
                                  int n, int Kd, int orderB)
{
    int idx = blockIdx.x * blockDim.x + threadIdx.x;
    if (idx >= n) return;
    float x = X[idx];
    __nv_bfloat16 h = __float2bfloat16(x);
    __nv_bfloat16 l = __float2bfloat16(x - __bfloat162float(h));
    int r = idx / Kd, k = idx - r * Kd;
    size_t bse = (size_t)r * 3 * Kd;
    if (orderB) { Y[bse + k] = h; Y[bse + Kd + k] = h; Y[bse + 2*Kd + k] = l; }
    else        { Y[bse + k] = h; Y[bse + Kd + k] = l; Y[bse + 2*Kd + k] = h; }
}

// ---------------- scalar-FFMA SGEMM (kw_prob only) ----------------
template<int BM, int BN, int BK, int TM, int TN>
__global__ void sgemm_nt(const float* __restrict__ A, const float* __restrict__ B,
                         const float* __restrict__ bias, float* __restrict__ C,
                         int M, int N, int K, int lda, int ldb, int ldc,
                         long long sA, long long sB, long long sC, int act)
{
    constexpr int THREADS = (BM/TM) * (BN/TN);
    __shared__ float As[BK][BM];
    __shared__ float Bs[BK][BN];

    A += (size_t)blockIdx.z * sA;
    B += (size_t)blockIdx.z * sB;
    C += (size_t)blockIdx.z * sC;

    int bm = blockIdx.y * BM;
    int bn = blockIdx.x * BN;
    int tid = threadIdx.x;
    int tx = tid % (BN/TN);
    int ty = tid / (BN/TN);

    float acc[TM][TN];
    #pragma unroll
    for (int i = 0; i < TM; i++)
        #pragma unroll
        for (int j = 0; j < TN; j++) acc[i][j] = 0.f;

    for (int k0 = 0; k0 < K; k0 += BK) {
        #pragma unroll
        for (int i = tid; i < BM*BK/4; i += THREADS) {
            int r = i / (BK/4), c4 = i % (BK/4);
            float4 v = *(const float4*)&A[(size_t)(bm+r)*lda + k0 + c4*4];
            As[c4*4+0][r] = v.x; As[c4*4+1][r] = v.y;
            As[c4*4+2][r] = v.z; As[c4*4+3][r] = v.w;
        }
        #pragma unroll
        for (int i = tid; i < BN*BK/4; i += THREADS) {
            int r = i / (BK/4), c4 = i % (BK/4);
            float4 v = *(const float4*)&B[(size_t)(bn+r)*ldb + k0 + c4*4];
            Bs[c4*4+0][r] = v.x; Bs[c4*4+1][r] = v.y;
            Bs[c4*4+2][r] = v.z; Bs[c4*4+3][r] = v.w;
        }
        __syncthreads();
        #pragma unroll
        for (int kk = 0; kk < BK; kk++) {
            float a[TM], b[TN];
            #pragma unroll
            for (int i = 0; i < TM; i++) a[i] = As[kk][ty*TM + i];
            #pragma unroll
            for (int j = 0; j < TN; j++) b[j] = Bs[kk][tx*TN + j];
            #pragma unroll
            for (int i = 0; i < TM; i++)
                #pragma unroll
                for (int j = 0; j < TN; j++) acc[i][j] += a[i]*b[j];
        }
        __syncthreads();
    }

    #pragma unroll
    for (int i = 0; i < TM; i++) {
        int m = bm + ty*TM + i;
        #pragma unroll
        for (int j = 0; j < TN; j++) {
            int n = bn + tx*TN + j;
            float v = acc[i][j];
            if (bias) v += bias[n];
            if (act == 1) v = tanhf(v);
            C[(size_t)m*ldc + n] = v;
        }
    }
}

// ---------------- GRU math ----------------
__device__ __forceinline__ float sigm(float x) { return 1.f / (1.f + expf(-x)); }

// ============ FUSED: masked-mean gather + GRU step 1 ============
__global__ __launch_bounds__(256)
void gather_gru1_kernel(const int* __restrict__ col_idx, const int* __restrict__ col_mask,
                        const int* __restrict__ tab_idx, const int* __restrict__ tab_mask,
                        const float* __restrict__ bih_f, const float* __restrict__ bhh_f,
                        const float* __restrict__ bih_b, const float* __restrict__ bhh_b)
{
    int u = blockIdx.x, t = blockIdx.y;
    int j = threadIdx.x;
    const float* Pf = d_Pf + (size_t)t * DB_ * G3_;
    const float* Pb = d_Pb + (size_t)t * DB_ * G3_;

    float tf_r=0.f, tf_z=0.f, tf_n=0.f, tb_r=0.f, tb_z=0.f, tb_n=0.f, cnt_t=0.f;
    #pragma unroll
    for (int m = 0; m < MT_; m++) {
        if (tab_mask[u*MT_+m]) {
            int id = tab_idx[u*MT_+m];
            const float* pf = Pf + (size_t)id * G3_;
            const float* pb = Pb + (size_t)id * G3_;
            tf_r += pf[j]; tf_z += pf[Hh_+j]; tf_n += pf[2*Hh_+j];
            tb_r += pb[j]; tb_z += pb[Hh_+j]; tb_n += pb[2*Hh_+j];
            cnt_t += 1.f;
        }
    }
    float cf_r=0.f, cf_z=0.f, cf_n=0.f, cb_r=0.f, cb_z=0.f, cb_n=0.f, cnt_c=0.f;
    #pragma unroll
    for (int m = 0; m < MC_; m++) {
        if (col_mask[u*MC_+m]) {
            int id = col_idx[u*MC_+m];
            const float* pf = Pf + (size_t)id * G3_;
            const float* pb = Pb + (size_t)id * G3_;
            cf_r += pf[j]; cf_z += pf[Hh_+j]; cf_n += pf[2*Hh_+j];
            cb_r += pb[j]; cb_z += pb[Hh_+j]; cb_n += pb[2*Hh_+j];
            cnt_c += 1.f;
        }
    }
    float it = 1.f / fmaxf(cnt_t, 1.f);
    float ic = 1.f / fmaxf(cnt_c, 1.f);
    size_t row = (size_t)t * U_ + u;

    d_g_f2[row*G3_ + j]         = cf_r * ic;
    d_g_f2[row*G3_ + Hh_ + j]   = cf_z * ic;
    d_g_f2[row*G3_ + 2*Hh_ + j] = cf_n * ic;
    d_g_b2[row*G3_ + j]         = tb_r * it;
    d_g_b2[row*G3_ + Hh_ + j]   = tb_z * it;
    d_g_b2[row*G3_ + 2*Hh_ + j] = tb_n * it;

    {
        float r = sigm(tf_r*it + bih_f[j]       + bhh_f[j]);
        float z = sigm(tf_z*it + bih_f[Hh_+j]   + bhh_f[Hh_+j]);
        float n = tanhf(tf_n*it + bih_f[2*Hh_+j] + r * bhh_f[2*Hh_+j]);
        float v = (1.f - z) * n;
        d_f1[row*Hh_ + j] = v;
        __nv_bfloat16 h = __float2bfloat16(v);
        __nv_bfloat16 l = __float2bfloat16(v - __bfloat162float(h));
        d_f1S[row*G3_ + j] = h; d_f1S[row*G3_ + Hh_ + j] = l; d_f1S[row*G3_ + 2*Hh_ + j] = h;
    }
    {
        float r = sigm(cb_r*ic + bih_b[j]       + bhh_b[j]);
        float z = sigm(cb_z*ic + bih_b[Hh_+j]   + bhh_b[Hh_+j]);
        float n = tanhf(cb_n*ic + bih_b[2*Hh_+j] + r * bhh_b[2*Hh_+j]);
        float v = (1.f - z) * n;
        d_b1[row*Hh_ + j] = v;
        __nv_bfloat16 h = __float2bfloat16(v);
        __nv_bfloat16 l = __float2bfloat16(v - __bfloat162float(h));
        d_b1S[row*G3_ + j] = h; d_b1S[row*G3_ + Hh_ + j] = l; d_b1S[row*G3_ + 2*Hh_ + j] = h;
    }
}

// second steps + db_emb (fp32 + B-side split-bf16) + FUSED masked logit.
__global__ __launch_bounds__(256)
void gru_second_kernel(const float* __restrict__ bih_f, const float* __restrict__ bhh_f,
                       const float* __restrict__ bih_b, const float* __restrict__ bhh_b,
                       const float* __restrict__ key, const int* __restrict__ attn_mask)
{
    int row = blockIdx.x;
    int j   = threadIdx.x;
    int idx = row * Hh_ + j;
    int t   = row >> 10;
    float db0, db1;
    {
        const float* gi = d_g_f2 + (size_t)row * G3_;
        const float* gh = d_gh_f + (size_t)row * G3_;
        float h  = d_f1[idx];
        float r = sigm(gi[j]       + bih_f[j]       + gh[j]       + bhh_f[j]);
        float z = sigm(gi[Hh_+j]   + bih_f[Hh_+j]   + gh[Hh_+j]   + bhh_f[Hh_+j]);
        float n = tanhf(gi[2*Hh_+j] + bih_f[2*Hh_+j] + r * (gh[2*Hh_+j] + bhh_f[2*Hh_+j]));
        float f2 = (1.f - z) * n + z * h;
        db0 = 0.5f * (h + f2);
        d_db[(size_t)row*H_ + j] = db0;
    }
    {
        const float* gi = d_g_b2 + (size_t)row * G3_;
        const float* gh = d_gh_b + (size_t)row * G3_;
        float h  = d_b1[idx];
        float r = sigm(gi[j]       + bih_b[j]       + gh[j]       + bhh_b[j]);
        float z = sigm(gi[Hh_+j]   + bih_b[Hh_+j]   + gh[Hh_+j]   + bhh_b[Hh_+j]);
        float n = tanhf(gi[2*Hh_+j] + bih_b[2*Hh_+j] + r * (gh[2*Hh_+j] + bhh_b[2*Hh_+j]));
        float b2 = (1.f - z) * n + z * h;
        db1 = 0.5f * (h + b2);
        d_db[(size_t)row*H_ + Hh_ + j] = db1;
    }
    {
        size_t sb = (size_t)row * K3H_;
        __nv_bfloat16 h0 = __float2bfloat16(db0);
        __nv_bfloat16 l0 = __float2bfloat16(db0 - __bfloat162float(h0));
        d_dbS[sb + j] = h0; d_dbS[sb + H_ + j] = h0; d_dbS[sb + 2*H_ + j] = l0;
        __nv_bfloat16 h1 = __float2bfloat16(db1);
        __nv_bfloat16 l1 = __float2bfloat16(db1 - __bfloat162float(h1));
        d_dbS[sb + Hh_ + j] = h1; d_dbS[sb + H_ + Hh_ + j] = h1; d_dbS[sb + 2*H_ + Hh_ + j] = l1;
    }
    float part = key[(size_t)t*H_ + j] * db0 + key[(size_t)t*H_ + Hh_ + j] * db1;
    #pragma unroll
    for (int s = 16; s > 0; s >>= 1) part += __shfl_xor_sync(0xFFFFFFFFu, part, s);
    __shared__ float wsum[8];
    if ((j & 31) == 0) wsum[j >> 5] = part;
    __syncthreads();
    if (j == 0) {
        float acc = 0.f;
        #pragma unroll
        for (int w = 0; w < 8; w++) acc += wsum[w];
        d_logits[row] = attn_mask[row] ? acc : -1e9f;
    }
}

// ---------------- attention ----------------
__global__ void softmax_kernel()
{
    int t = blockIdx.x;
    __shared__ float red[256];
    int tid = threadIdx.x;
    float mx = -INFINITY;
    for (int u = tid; u < U_; u += 256) mx = fmaxf(mx, d_logits[t*U_+u]);
    red[tid] = mx; __syncthreads();
    for (int s = 128; s > 0; s >>= 1) { if (tid < s) red[tid] = fmaxf(red[tid], red[tid+s]); __syncthreads(); }
    mx = red[0]; __syncthreads();
    float sum = 0.f;
    for (int u = tid; u < U_; u += 256) sum += expf(d_logits[t*U_+u] - mx);
    red[tid] = sum; __syncthreads();
    for (int s = 128; s > 0; s >>= 1) { if (tid < s) red[tid] += red[tid+s]; __syncthreads(); }
    sum = red[0];
    float inv = 1.f / sum;
    for (int u = tid; u < U_; u += 256) d_wsm[t*U_+u] = expf(d_logits[t*U_+u] - mx) * inv;
}

__global__ void attn_part_kernel()
{
    int chunk = blockIdx.x, t = blockIdx.y;
    int h = threadIdx.x;
    __shared__ float ws[128];
    if (h < 128) ws[h] = d_wsm[t*U_ + chunk*128 + h];
    __syncthreads();
    float acc = 0.f;
    const float* d = d_db + ((size_t)t*U_ + chunk*128) * H_ + h;
    #pragma unroll 4
    for (int u = 0; u < 128; u++) acc += ws[u] * d[(size_t)u*H_];
    d_attnp[((size_t)t*8 + chunk)*H_ + h] = acc;
}

__global__ void attn_reduce_kernel()
{
    int t = blockIdx.x;
    int h = threadIdx.x;
    float acc = 0.f;
    #pragma unroll
    for (int c = 0; c < 8; c++) acc += d_attnp[((size_t)t*8 + c)*H_ + h];
    d_attnv[t*H_ + h] = acc;
}

// ffin = final_feature + attn, emitted directly as A-side split-bf16
__global__ void add_attn_kernel(const float* __restrict__ final_feature)
{
    int idx = blockIdx.x * blockDim.x + threadIdx.x;   // TL_*H_
    int h = idx & (H_-1);
    int t = idx >> 15;
    float v = final_feature[idx] + d_attnv[t*H_ + h];
    int r = idx >> 9;                                  // / H_
    __nv_bfloat16 hh = __float2bfloat16(v);
    __nv_bfloat16 ll = __float2bfloat16(v - __bfloat162float(hh));
    size_t sb = (size_t)r * K3H_ + h;
    d_ffinS[sb] = hh; d_ffinS[sb + H_] = ll; d_ffinS[sb + 2*H_] = hh;
}

// ---------------- final log-softmax ----------------
__global__ void logsoftmax_kernel(float* __restrict__ out)
{
    int r = blockIdx.x;
    int tid = threadIdx.x;
    __shared__ float red[256];
    const float* x = d_probs + (size_t)r * OUTC_;
    float mx = -INFINITY;
    for (int c = tid; c < OUTC_; c += 256) mx = fmaxf(mx, x[c]);
    red[tid] = mx; __syncthreads();
    for (int s = 128; s > 0; s >>= 1) { if (tid < s) red[tid] = fmaxf(red[tid], red[tid+s]); __syncthreads(); }
    mx = red[0]; __syncthreads();
    float sum = 0.f;
    for (int c = tid; c < OUTC_; c += 256) sum += expf(x[c] - mx);
    red[tid] = sum; __syncthreads();
    for (int s = 128; s > 0; s >>= 1) { if (tid < s) red[tid] += red[tid+s]; __syncthreads(); }
    float lse = mx + logf(red[0]);
    for (int c = tid; c < OUTC_; c += 256) out[(size_t)r*OUTC_ + c] = x[c] - lse;
}

// ---------------- host launcher ----------------
#define SYM(p, t, s) do { void* _t; cudaGetSymbolAddress(&_t, s); (p) = (t*)_t; } while (0)

extern "C" void kernel_launch(void* const* d_in, const int* in_sizes, int n_in,
                              void* d_out, int out_size)
{
    const float* feat          = (const float*)d_in[0];
    const float* key           = (const float*)d_in[1];
    const float* final_feature = (const float*)d_in[2];
    const float* Wih_f         = (const float*)d_in[3];
    const float* Whh_f         = (const float*)d_in[4];
    const float* bih_f         = (const float*)d_in[5];
    const float* bhh_f         = (const float*)d_in[6];
    const float* Wih_b         = (const float*)d_in[7];
    const float* Whh_b         = (const float*)d_in[8];
    const float* bih_b         = (const float*)d_in[9];
    const float* bhh_b         = (const float*)d_in[10];
    const float* Wb            = (const float*)d_in[11];
    const float* bb            = (const float*)d_in[12];
    const float* Kemb          = (const float*)d_in[13];
    const int*   col_idx       = (const int*)d_in[14];
    const int*   col_mask      = (const int*)d_in[15];
    const int*   tab_idx       = (const int*)d_in[16];
    const int*   tab_mask      = (const int*)d_in[17];
    const int*   attn_mask     = (const int*)d_in[18];
    float* out = (float*)d_out;

    float *Pf, *Pb, *gh_f, *gh_b, *ff, *probs;
    __nv_bfloat16 *featS, *WihfS, *WihbS, *WhhfS, *WhhbS, *WbS, *f1S, *b1S, *dbS, *ffinS, *ffS;
    SYM(Pf, float, d_Pf);   SYM(Pb, float, d_Pb);
    SYM(gh_f, float, d_gh_f); SYM(gh_b, float, d_gh_b);
    SYM(ff, float, d_ff);   SYM(probs, float, d_probs);
    SYM(featS, __nv_bfloat16, d_featS);
    SYM(WihfS, __nv_bfloat16, d_WihfS); SYM(WihbS, __nv_bfloat16, d_WihbS);
    SYM(WhhfS, __nv_bfloat16, d_WhhfS); SYM(WhhbS, __nv_bfloat16, d_WhhbS);
    SYM(WbS, __nv_bfloat16, d_WbS);
    SYM(f1S, __nv_bfloat16, d_f1S);     SYM(b1S, __nv_bfloat16, d_b1S);
    SYM(dbS, __nv_bfloat16, d_dbS);
    SYM(ffinS, __nv_bfloat16, d_ffinS); SYM(ffS, __nv_bfloat16, d_ffS);

    // 0) split-bf16 conversions
    split_bf16_kernel<<<(TDB_*H_+255)/256, 256>>>(feat,  featS, TDB_*H_, H_, 0);
    split_bf16_kernel<<<(G3_*H_+255)/256, 256>>>(Wih_f, WihfS, G3_*H_, H_, 1);
    split_bf16_kernel<<<(G3_*H_+255)/256, 256>>>(Wih_b, WihbS, G3_*H_, H_, 1);
    split_bf16_kernel<<<(G3_*Hh_+255)/256, 256>>>(Whh_f, WhhfS, G3_*Hh_, Hh_, 1);
    split_bf16_kernel<<<(G3_*Hh_+255)/256, 256>>>(Whh_b, WhhbS, G3_*Hh_, Hh_, 1);
    split_bf16_kernel<<<(H_*H_+255)/256, 256>>>(Wb, WbS, H_*H_, H_, 1);

    // 1) projection GEMMs, batched (z=0: Wih_f, z=1: Wih_b)
    {
        dim3 grid(G3_/128, TDB_/128, 2);
        gemm_wmma2<<<grid, 256>>>(featS, WihfS, Pf, featS, WihbS, Pb, TDB_, G3_, K3H_, G3_);
    }

    // 2+3) fused masked-mean gather + GRU step 1
    gather_gru1_kernel<<<dim3(U_, T_), 256>>>(col_idx, col_mask, tab_idx, tab_mask,
                                              bih_f, bhh_f, bih_b, bhh_b);

    // 4) hidden-projection GEMMs, batched (z=0: f, z=1: b)
    {
        dim3 grid(G3_/128, TU_/128, 2);
        gemm_wmma2<<<grid, 256>>>(f1S, WhhfS, gh_f, b1S, WhhbS, gh_b, TU_, G3_, 3*Hh_, G3_);
    }

    // 5) second GRU steps + db_emb (fp32 + split) + fused logits
    gru_second_kernel<<<TU_, 256>>>(bih_f, bhh_f, bih_b, bhh_b, key, attn_mask);

    // 6) attention
    softmax_kernel<<<T_, 256>>>();
    attn_part_kernel<<<dim3(8, T_), 512>>>();
    attn_reduce_kernel<<<T_, 512>>>();

    // 7) ffin = final_feature + attn (split emission), then ff = tanh(ffin@Wb^T+bb) on HMMA
    add_attn_kernel<<<TL_*H_/256, 256>>>(final_feature);
    {
        dim3 grid(H_/128, TL_/64, 1);   // 4 x 16 = 64 blocks
        gemm_wmma_ffn<<<grid, 256>>>(ffinS, WbS, bb, ff, ffS);
    }

    // 8) db_prob on tensor cores: per-t (64 x 1024, K'=1536), batched over z=t
    {
        dim3 grid(U_/128, 1, T_);
        gemm_wmma64<<<grid, 256>>>(ffS, dbS, probs,
            (long long)L_*K3H_, (long long)U_*K3H_, (long long)L_*OUTC_,
            K3H_, OUTC_);
    }
    // 9) kw_prob: (1024 x 64) = ff @ Kemb^T, at column offset U_ (fp32)
    {
        dim3 grid(K_/64, TL_/64, 1);
        sgemm_nt<64,64,16,4,4><<<grid, 256>>>(ff, Kemb, nullptr, probs + U_,
            TL_, K_, H_, H_, H_, OUTC_, 0,0,0, 0);
    }

    // 10) log-softmax over last dim (1088) -> output
    logsoftmax_kernel<<<TL_, 256>>>(out);
}